// round 1
// baseline (speedup 1.0000x reference)
#include <cuda_runtime.h>

// Gene Linear Attention — fp32 SIMT baseline.
// Pipeline: proj(q,k,v) -> q group-softmax(+scale) -> k column-softmax
//        -> attn = q@k^T (output) -> ctx = k^T@v -> out = q@ctx (scattered output)

#define RR   64
#define CC   2048
#define EE   128
#define HH   8
#define HDIM 16
#define DD   1024   // RR*HDIM

// Scratch (device globals: allocation-free rule)
__device__ float g_Q[HH * CC * DD];
__device__ float g_K[HH * CC * DD];
__device__ float g_V[HH * CC * DD];
__device__ float g_CTX[HH * DD * DD];

// GEMM tile config: 64x64 block tile, K-step 16, 256 threads, 4x4 per thread
#define BM 64
#define BN 64
#define BK 16
#define AST 68   // padded stride for transposed tiles (4-float aligned, reduces bank conflicts)
#define BST 64   // stride for direct-layout tiles

// ---------------------------------------------------------------------------
// helpers
// ---------------------------------------------------------------------------

// Load a BM x BK tile from row-major G (leading dim ldg) and store TRANSPOSED
// into S as S[k][m] with stride AST. Each thread loads one float4.
__device__ __forceinline__ void load_tile_T(float* S, const float* __restrict__ G,
                                            int ldg, int row, int seg) {
    float4 v = *(const float4*)(G + (size_t)row * ldg + seg * 4);
    S[(seg * 4 + 0) * AST + row] = v.x;
    S[(seg * 4 + 1) * AST + row] = v.y;
    S[(seg * 4 + 2) * AST + row] = v.z;
    S[(seg * 4 + 3) * AST + row] = v.w;
}

// Load a BK x BN tile from row-major G (rows are the k dimension) directly:
// S[k][n] with stride BST. Each thread loads one float4.
__device__ __forceinline__ void load_tile_D(float* S, const float* __restrict__ G,
                                            int ldg, int kk, int cs) {
    *(float4*)(S + kk * BST + cs * 4) = *(const float4*)(G + (size_t)kk * ldg + cs * 4);
}

template <int ASTR, int BSTR>
__device__ __forceinline__ void microtile(const float* As, const float* Bs,
                                          int ty, int tx, float acc[4][4]) {
#pragma unroll
    for (int kk = 0; kk < BK; kk++) {
        float4 a4 = *(const float4*)(As + kk * ASTR + ty * 4);
        float4 b4 = *(const float4*)(Bs + kk * BSTR + tx * 4);
        float ar[4] = {a4.x, a4.y, a4.z, a4.w};
        float br[4] = {b4.x, b4.y, b4.z, b4.w};
#pragma unroll
        for (int i = 0; i < 4; i++)
#pragma unroll
            for (int j = 0; j < 4; j++)
                acc[i][j] = fmaf(ar[i], br[j], acc[i][j]);
    }
}

// ---------------------------------------------------------------------------
// 1) Projection: Y = X @ W^T + b, scattered into [h][c][r*16+j] layout
//    X: (RR*CC, EE) row-major; W: (EE, EE) row-major (NT GEMM).
//    sel: 0 -> g_Q, 1 -> g_K, 2 -> g_V
// ---------------------------------------------------------------------------
__global__ __launch_bounds__(256) void proj_kernel(const float* __restrict__ X,
                                                   const float* __restrict__ W,
                                                   const float* __restrict__ bias,
                                                   int sel) {
    __shared__ float As[BK * AST];
    __shared__ float Bs[BK * AST];
    float* outp = (sel == 0) ? g_Q : (sel == 1) ? g_K : g_V;

    int tid = threadIdx.x;
    int m0 = blockIdx.y * BM;
    int n0 = blockIdx.x * BN;
    int row = tid >> 2, seg = tid & 3;
    int ty = tid >> 4, tx = tid & 15;

    float acc[4][4] = {};
    for (int k0 = 0; k0 < EE; k0 += BK) {
        load_tile_T(As, X + (size_t)m0 * EE + k0, EE, row, seg);
        load_tile_T(Bs, W + (size_t)n0 * EE + k0, EE, row, seg);
        __syncthreads();
        microtile<AST, AST>(As, Bs, ty, tx, acc);
        __syncthreads();
    }

#pragma unroll
    for (int i = 0; i < 4; i++) {
        int rc = m0 + ty * 4 + i;
        int r = rc >> 11;            // rc / CC
        int c = rc & (CC - 1);       // rc % CC
#pragma unroll
        for (int j = 0; j < 4; j++) {
            int e = n0 + tx * 4 + j;
            int hh = e >> 4;         // e / HDIM
            int jj = e & 15;         // e % HDIM
            outp[((size_t)hh * CC + c) * DD + (r << 4) + jj] = acc[i][j] + bias[e];
        }
    }
}

// ---------------------------------------------------------------------------
// 2a) q softmax over 16-element groups (h,c,r), then scale by dim^-0.5 = 1/32
// ---------------------------------------------------------------------------
__global__ __launch_bounds__(256) void qsoft_kernel() {
    size_t g = (size_t)blockIdx.x * blockDim.x + threadIdx.x;  // group id
    float* p = g_Q + g * 16;
    float v[16];
    *(float4*)&v[0]  = *(const float4*)&p[0];
    *(float4*)&v[4]  = *(const float4*)&p[4];
    *(float4*)&v[8]  = *(const float4*)&p[8];
    *(float4*)&v[12] = *(const float4*)&p[12];
    float mx = v[0];
#pragma unroll
    for (int i = 1; i < 16; i++) mx = fmaxf(mx, v[i]);
    float s = 0.f;
#pragma unroll
    for (int i = 0; i < 16; i++) { v[i] = __expf(v[i] - mx); s += v[i]; }
    float sc = 0.03125f / s;   // softmax * dim^-0.5
#pragma unroll
    for (int i = 0; i < 16; i++) v[i] *= sc;
    *(float4*)&p[0]  = *(const float4*)&v[0];
    *(float4*)&p[4]  = *(const float4*)&v[4];
    *(float4*)&p[8]  = *(const float4*)&v[8];
    *(float4*)&p[12] = *(const float4*)&v[12];
}

// ---------------------------------------------------------------------------
// 2b) k softmax over the sequence axis (n = 0..CC-1) per (h, d) column
//     Input values are ~N(0,1) so exp without max-subtraction is safe.
// ---------------------------------------------------------------------------
__global__ __launch_bounds__(256) void ksoft_kernel() {
    int h = blockIdx.y;
    int d = blockIdx.x * blockDim.x + threadIdx.x;
    float* base = g_K + (size_t)h * CC * DD + d;
    float s = 0.f;
    for (int n = 0; n < CC; n++) s += __expf(base[(size_t)n * DD]);
    float inv = 1.f / s;
    for (int n = 0; n < CC; n++) {
        float v = base[(size_t)n * DD];
        base[(size_t)n * DD] = __expf(v) * inv;
    }
}

// ---------------------------------------------------------------------------
// 3) attn[h][n][m] = sum_d q[h][n][d] * k[h][m][d]   (NT GEMM, K=DD)
//    Written directly into d_out at offset RR*CC*EE.
// ---------------------------------------------------------------------------
__global__ __launch_bounds__(256) void attn_kernel(float* __restrict__ out) {
    __shared__ float As[BK * AST];
    __shared__ float Bs[BK * AST];
    int h = blockIdx.z;
    const float* A = g_Q + (size_t)h * CC * DD;
    const float* B = g_K + (size_t)h * CC * DD;
    float* Cp = out + (size_t)RR * CC * EE + (size_t)h * CC * CC;

    int tid = threadIdx.x;
    int m0 = blockIdx.y * BM;
    int n0 = blockIdx.x * BN;
    int row = tid >> 2, seg = tid & 3;
    int ty = tid >> 4, tx = tid & 15;

    float acc[4][4] = {};
    for (int k0 = 0; k0 < DD; k0 += BK) {
        load_tile_T(As, A + (size_t)m0 * DD + k0, DD, row, seg);
        load_tile_T(Bs, B + (size_t)n0 * DD + k0, DD, row, seg);
        __syncthreads();
        microtile<AST, AST>(As, Bs, ty, tx, acc);
        __syncthreads();
    }

#pragma unroll
    for (int i = 0; i < 4; i++) {
        float4 v = make_float4(acc[i][0], acc[i][1], acc[i][2], acc[i][3]);
        *(float4*)&Cp[(size_t)(m0 + ty * 4 + i) * CC + n0 + tx * 4] = v;
    }
}

// ---------------------------------------------------------------------------
// 4) ctx[h][d][e] = sum_n k[h][n][d] * v[h][n][e]   (TN GEMM, K=CC)
// ---------------------------------------------------------------------------
__global__ __launch_bounds__(256) void ctx_kernel() {
    __shared__ float As[BK * BST];
    __shared__ float Bs[BK * BST];
    int h = blockIdx.z;
    const float* A = g_K + (size_t)h * CC * DD;
    const float* B = g_V + (size_t)h * CC * DD;
    float* Cp = g_CTX + (size_t)h * DD * DD;

    int tid = threadIdx.x;
    int d0 = blockIdx.y * BM;
    int e0 = blockIdx.x * BN;
    int kk = tid >> 4, cs = tid & 15;
    int ty = tid >> 4, tx = tid & 15;

    float acc[4][4] = {};
    for (int k0 = 0; k0 < CC; k0 += BK) {
        load_tile_D(As, A + (size_t)k0 * DD + d0, DD, kk, cs);
        load_tile_D(Bs, B + (size_t)k0 * DD + e0, DD, kk, cs);
        __syncthreads();
        microtile<BST, BST>(As, Bs, ty, tx, acc);
        __syncthreads();
    }

#pragma unroll
    for (int i = 0; i < 4; i++) {
        float4 v = make_float4(acc[i][0], acc[i][1], acc[i][2], acc[i][3]);
        *(float4*)&Cp[(size_t)(d0 + ty * 4 + i) * DD + e0 + tx * 4] = v;
    }
}

// ---------------------------------------------------------------------------
// 5) O[h][n][col] = sum_d q[h][n][d] * ctx[h][d][col]  (NN GEMM, K=DD)
//    Epilogue scatters: out[r][c][h*16+j] with col = r*16+j, n = c.
// ---------------------------------------------------------------------------
__global__ __launch_bounds__(256) void out_kernel(float* __restrict__ out) {
    __shared__ float As[BK * AST];
    __shared__ float Bs[BK * BST];
    int h = blockIdx.z;
    const float* A = g_Q + (size_t)h * CC * DD;
    const float* B = g_CTX + (size_t)h * DD * DD;

    int tid = threadIdx.x;
    int m0 = blockIdx.y * BM;   // n (gene/column index c)
    int n0 = blockIdx.x * BN;   // col (r*16+j)
    int row = tid >> 2, seg = tid & 3;
    int kk = tid >> 4, cs = tid & 15;
    int ty = tid >> 4, tx = tid & 15;

    float acc[4][4] = {};
    for (int k0 = 0; k0 < DD; k0 += BK) {
        load_tile_T(As, A + (size_t)m0 * DD + k0, DD, row, seg);
        load_tile_D(Bs, B + (size_t)k0 * DD + n0, DD, kk, cs);
        __syncthreads();
        microtile<AST, BST>(As, Bs, ty, tx, acc);
        __syncthreads();
    }

    int cb = n0 + tx * 4;
    int r = cb >> 4;        // which cell-row
    int j = cb & 15;        // offset within head_dim (0,4,8,12)
#pragma unroll
    for (int i = 0; i < 4; i++) {
        int n = m0 + ty * 4 + i;
        float4 v = make_float4(acc[i][0], acc[i][1], acc[i][2], acc[i][3]);
        *(float4*)&out[((size_t)r * CC + n) * EE + h * HDIM + j] = v;
    }
}

// ---------------------------------------------------------------------------
// launch
// ---------------------------------------------------------------------------
extern "C" void kernel_launch(void* const* d_in, const int* in_sizes, int n_in,
                              void* d_out, int out_size) {
    const float* x  = (const float*)d_in[0];
    const float* Wq = (const float*)d_in[1];
    const float* bq = (const float*)d_in[2];
    const float* Wk = (const float*)d_in[3];
    const float* bk = (const float*)d_in[4];
    const float* Wv = (const float*)d_in[5];
    const float* bv = (const float*)d_in[6];
    float* out = (float*)d_out;

    dim3 t(256);
    dim3 gproj(EE / BN, (RR * CC) / BM);            // (2, 2048)
    proj_kernel<<<gproj, t>>>(x, Wq, bq, 0);
    proj_kernel<<<gproj, t>>>(x, Wk, bk, 1);
    proj_kernel<<<gproj, t>>>(x, Wv, bv, 2);

    qsoft_kernel<<<(HH * CC * RR) / 256, t>>>();
    ksoft_kernel<<<dim3(DD / 256, HH), t>>>();

    attn_kernel<<<dim3(CC / BN, CC / BM, HH), t>>>(out);   // (32,32,8)
    ctx_kernel<<<dim3(DD / BN, DD / BM, HH), t>>>();       // (16,16,8)
    out_kernel<<<dim3(DD / BN, CC / BM, HH), t>>>(out);    // (16,32,8)
}

// round 2
// speedup vs baseline: 2.9573x; 2.9573x over previous
#include <cuda_runtime.h>
#include <cuda_bf16.h>
#include <cstdint>

// Gene Linear Attention — bf16 tensor-core pipeline (mma.sync m16n8k16, fp32 accum).
// proj(3-term split) -> q softmax(+split) -> k softmax(+transpose+split) -> v transpose+split
// -> attn = Qh·Kh^T (1-term) -> ctxT = VT·KT^T (3-term) -> out = Q·ctxT^T (3-term)

#define RR   64
#define CC   2048
#define EE   128
#define HH   8
#define HDIM 16
#define DD   1024   // RR*HDIM

typedef __nv_bfloat16 bf16;

// ---------------- device global scratch (allocation-free rule) ----------------
__device__ float g_Q[HH * CC * DD];
__device__ float g_K[HH * CC * DD];
__device__ float g_V[HH * CC * DD];
__device__ float g_ksum[HH * DD];

__device__ bf16 g_xh[RR * CC * EE];
__device__ bf16 g_xl[RR * CC * EE];
__device__ bf16 g_Wqh[EE * EE], g_Wql[EE * EE];
__device__ bf16 g_Wkh[EE * EE], g_Wkl[EE * EE];
__device__ bf16 g_Wvh[EE * EE], g_Wvl[EE * EE];

__device__ bf16 g_Qh[HH * CC * DD];
__device__ bf16 g_Ql[HH * CC * DD];
__device__ bf16 g_Kh[HH * CC * DD];          // softmaxed k, [h][c][d]
__device__ bf16 g_KTh[HH * DD * CC];         // softmaxed k transposed, [h][d][n]
__device__ bf16 g_KTl[HH * DD * CC];
__device__ bf16 g_VTh[HH * DD * CC];         // v transposed, [h][e][n]
__device__ bf16 g_VTl[HH * DD * CC];
__device__ bf16 g_CTh[HH * DD * DD];         // ctx transposed, [h][col=r*16+j][d]
__device__ bf16 g_CTl[HH * DD * DD];

// ---------------- ptx helpers ----------------
__device__ __forceinline__ uint32_t cvta(const void* p) {
    return (uint32_t)__cvta_generic_to_shared(p);
}
__device__ __forceinline__ void cp16(uint32_t dst, const void* src) {
    asm volatile("cp.async.cg.shared.global [%0], [%1], 16;\n" :: "r"(dst), "l"(src));
}
#define CP_COMMIT() asm volatile("cp.async.commit_group;\n" ::)
#define CP_WAIT0()  asm volatile("cp.async.wait_group 0;\n" ::)

__device__ __forceinline__ void ldmA(uint32_t (&a)[4], uint32_t addr) {
    asm volatile("ldmatrix.sync.aligned.m8n8.x4.shared.b16 {%0,%1,%2,%3}, [%4];"
                 : "=r"(a[0]), "=r"(a[1]), "=r"(a[2]), "=r"(a[3]) : "r"(addr));
}
__device__ __forceinline__ void ldmB(uint32_t (&b)[2], uint32_t addr) {
    asm volatile("ldmatrix.sync.aligned.m8n8.x2.shared.b16 {%0,%1}, [%2];"
                 : "=r"(b[0]), "=r"(b[1]) : "r"(addr));
}
__device__ __forceinline__ void mma16816(float (&c)[4], const uint32_t (&a)[4],
                                         const uint32_t (&b)[2]) {
    asm volatile(
        "mma.sync.aligned.m16n8k16.row.col.f32.bf16.bf16.f32 "
        "{%0,%1,%2,%3}, {%4,%5,%6,%7}, {%8,%9}, {%0,%1,%2,%3};"
        : "+f"(c[0]), "+f"(c[1]), "+f"(c[2]), "+f"(c[3])
        : "r"(a[0]), "r"(a[1]), "r"(a[2]), "r"(a[3]), "r"(b[0]), "r"(b[1]));
}

// ---------------------------------------------------------------------------
// Generic NT GEMM: C[m][n] = sum_k A[m][k] * B[n][k], bf16 in / fp32 accum.
// TERMS=1: Ah*Bh. TERMS=3: Ah*Bh + Al*Bh + Ah*Bl.
// EPI: 0 = attn store (fp32 row-major ldc), 1 = ctx store (bf16 hi/lo to E0/E1),
//      2 = out scatter (fp32, col=r*16+j), 3 = proj (+bias, scatter to [h][c][d] fp32)
// Tiles: 128x128xBK32, 256 threads, warp tile 64x32, double-buffered cp.async.
// ---------------------------------------------------------------------------
#define LDS 40   // bf16 row stride in smem (32 + 8 pad): conflict-free ldmatrix

template <int TERMS, int EPI>
__global__ __launch_bounds__(256) void mma_gemm(
    const bf16* __restrict__ Ah, const bf16* __restrict__ Al,
    const bf16* __restrict__ Bh, const bf16* __restrict__ Bl,
    float* __restrict__ C0, bf16* __restrict__ E0, bf16* __restrict__ E1,
    const float* __restrict__ bias,
    int Kdim, int ldA, int ldB, int ldc,
    size_t sAh, size_t sBh, size_t sCh)
{
    extern __shared__ __align__(16) char dynsmem[];
    bf16* smem = (bf16*)dynsmem;

    const int h = blockIdx.z;
    Ah += (size_t)h * sAh;
    Bh += (size_t)h * sBh;
    if (TERMS == 3) { Al += (size_t)h * sAh; Bl += (size_t)h * sBh; }

    const int tid = threadIdx.x, lane = tid & 31, warp = tid >> 5;
    const int wm = warp >> 2, wn = warp & 3;   // 2 x 4 warp grid
    const int m0 = blockIdx.y * 128, n0 = blockIdx.x * 128;

    const int TS = 128 * LDS;                     // bf16 per tile
    const int STAGE = (TERMS == 3 ? 4 : 2) * TS;  // bf16 per stage

    float acc[4][4][4];
#pragma unroll
    for (int i = 0; i < 4; i++)
#pragma unroll
        for (int j = 0; j < 4; j++)
#pragma unroll
            for (int q = 0; q < 4; q++) acc[i][j][q] = 0.f;

    auto load_stage = [&](int st, int k0) {
        bf16* s = smem + st * STAGE;
#pragma unroll
        for (int t = 0; t < 2; t++) {
            int slot = tid + t * 256;
            int row = slot >> 2, seg = slot & 3;
            int so = row * LDS + seg * 8;
            size_t ga = (size_t)(m0 + row) * ldA + k0 + seg * 8;
            size_t gb = (size_t)(n0 + row) * ldB + k0 + seg * 8;
            cp16(cvta(s + so), Ah + ga);
            cp16(cvta(s + TS + so), Bh + gb);
            if (TERMS == 3) {
                cp16(cvta(s + 2 * TS + so), Al + ga);
                cp16(cvta(s + 3 * TS + so), Bl + gb);
            }
        }
    };

    const int nk = Kdim >> 5;
    load_stage(0, 0);
    CP_COMMIT();

    for (int i = 0; i < nk; i++) {
        CP_WAIT0();
        __syncthreads();
        if (i + 1 < nk) { load_stage((i + 1) & 1, (i + 1) << 5); CP_COMMIT(); }

        bf16* s = smem + (i & 1) * STAGE;
        const uint32_t baseA = cvta(s);
        const uint32_t baseB = cvta(s + TS);

#pragma unroll
        for (int kk = 0; kk < 2; kk++) {
            uint32_t a[4][4], b[4][2];
#pragma unroll
            for (int mi = 0; mi < 4; mi++) {
                int m = wm * 64 + mi * 16 + (lane & 15);
                ldmA(a[mi], baseA + (uint32_t)(m * LDS + kk * 16 + (lane >> 4) * 8) * 2);
            }
#pragma unroll
            for (int ni = 0; ni < 4; ni++) {
                int n = wn * 32 + ni * 8 + (lane & 7);
                ldmB(b[ni], baseB + (uint32_t)(n * LDS + kk * 16 + ((lane >> 3) & 1) * 8) * 2);
            }
#pragma unroll
            for (int mi = 0; mi < 4; mi++)
#pragma unroll
                for (int ni = 0; ni < 4; ni++) mma16816(acc[mi][ni], a[mi], b[ni]);

            if (TERMS == 3) {
                const uint32_t baseAl = cvta(s + 2 * TS);
                const uint32_t baseBl = cvta(s + 3 * TS);
#pragma unroll
                for (int mi = 0; mi < 4; mi++) {
                    uint32_t al[4];
                    int m = wm * 64 + mi * 16 + (lane & 15);
                    ldmA(al, baseAl + (uint32_t)(m * LDS + kk * 16 + (lane >> 4) * 8) * 2);
#pragma unroll
                    for (int ni = 0; ni < 4; ni++) mma16816(acc[mi][ni], al, b[ni]);
                }
#pragma unroll
                for (int ni = 0; ni < 4; ni++) {
                    uint32_t bl[2];
                    int n = wn * 32 + ni * 8 + (lane & 7);
                    ldmB(bl, baseBl + (uint32_t)(n * LDS + kk * 16 + ((lane >> 3) & 1) * 8) * 2);
#pragma unroll
                    for (int mi = 0; mi < 4; mi++) mma16816(acc[mi][ni], a[mi], bl);
                }
            }
        }
        // next-iteration __syncthreads (after wait) protects buffer reuse
    }

    // ---------------- epilogue ----------------
#pragma unroll
    for (int mi = 0; mi < 4; mi++) {
#pragma unroll
        for (int ni = 0; ni < 4; ni++) {
            int grow = m0 + wm * 64 + mi * 16 + (lane >> 2);
            int gcol = n0 + wn * 32 + ni * 8 + (lane & 3) * 2;
            float v0 = acc[mi][ni][0], v1 = acc[mi][ni][1];
            float v2 = acc[mi][ni][2], v3 = acc[mi][ni][3];

            if (EPI == 0) {  // attn: fp32 row-major
                float* base = C0 + (size_t)h * sCh;
                *(float2*)&base[(size_t)grow * ldc + gcol] = make_float2(v0, v1);
                *(float2*)&base[(size_t)(grow + 8) * ldc + gcol] = make_float2(v2, v3);
            } else if (EPI == 1) {  // ctx: bf16 hi/lo pair stores
                bf16* bh = E0 + (size_t)h * sCh;
                bf16* blp = E1 + (size_t)h * sCh;
#pragma unroll
                for (int rr2 = 0; rr2 < 2; rr2++) {
                    int row = grow + rr2 * 8;
                    float a0 = rr2 ? v2 : v0, a1 = rr2 ? v3 : v1;
                    __nv_bfloat162 hv, lv;
                    hv.x = __float2bfloat16(a0);
                    hv.y = __float2bfloat16(a1);
                    lv.x = __float2bfloat16(a0 - __bfloat162float(hv.x));
                    lv.y = __float2bfloat16(a1 - __bfloat162float(hv.y));
                    *(__nv_bfloat162*)&bh[(size_t)row * ldc + gcol] = hv;
                    *(__nv_bfloat162*)&blp[(size_t)row * ldc + gcol] = lv;
                }
            } else if (EPI == 2) {  // out scatter: col = r*16+j, row = gene c
                int r = gcol >> 4, j = gcol & 15;
#pragma unroll
                for (int rr2 = 0; rr2 < 2; rr2++) {
                    int c = grow + rr2 * 8;
                    float a0 = rr2 ? v2 : v0, a1 = rr2 ? v3 : v1;
                    *(float2*)&C0[(((size_t)r * CC + c) << 7) + h * HDIM + j] =
                        make_float2(a0, a1);
                }
            } else {  // EPI == 3: proj (+bias), scatter to [hh][c][r*16+jj] fp32
                int e = gcol;
                int hh = e >> 4, jj = e & 15;
                float b0 = bias[e], b1 = bias[e + 1];
#pragma unroll
                for (int rr2 = 0; rr2 < 2; rr2++) {
                    int rc = grow + rr2 * 8;
                    int r = rc >> 11, c = rc & (CC - 1);
                    float a0 = (rr2 ? v2 : v0) + b0, a1 = (rr2 ? v3 : v1) + b1;
                    *(float2*)&C0[((size_t)hh * CC + c) * DD + (r << 4) + jj] =
                        make_float2(a0, a1);
                }
            }
        }
    }
}

// ---------------------------------------------------------------------------
// elementwise split fp32 -> bf16 hi/lo
// ---------------------------------------------------------------------------
__global__ __launch_bounds__(256) void split_kernel(const float* __restrict__ src,
                                                    bf16* __restrict__ dh,
                                                    bf16* __restrict__ dl, int n) {
    int i = blockIdx.x * 256 + threadIdx.x;
    if (i >= n) return;
    float v = src[i];
    bf16 h = __float2bfloat16(v);
    dh[i] = h;
    dl[i] = __float2bfloat16(v - __bfloat162float(h));
}

// ---------------------------------------------------------------------------
// q softmax over 16-groups (+1/32 scale), write bf16 hi/lo
// ---------------------------------------------------------------------------
__global__ __launch_bounds__(256) void qsoft_kernel() {
    size_t g = (size_t)blockIdx.x * blockDim.x + threadIdx.x;
    const float* p = g_Q + g * 16;
    float v[16];
    *(float4*)&v[0] = *(const float4*)&p[0];
    *(float4*)&v[4] = *(const float4*)&p[4];
    *(float4*)&v[8] = *(const float4*)&p[8];
    *(float4*)&v[12] = *(const float4*)&p[12];
    float mx = v[0];
#pragma unroll
    for (int i = 1; i < 16; i++) mx = fmaxf(mx, v[i]);
    float s = 0.f;
#pragma unroll
    for (int i = 0; i < 16; i++) { v[i] = __expf(v[i] - mx); s += v[i]; }
    float sc = 0.03125f / s;
    bf16* qh = g_Qh + g * 16;
    bf16* ql = g_Ql + g * 16;
#pragma unroll
    for (int i = 0; i < 16; i += 2) {
        float a0 = v[i] * sc, a1 = v[i + 1] * sc;
        __nv_bfloat162 hv, lv;
        hv.x = __float2bfloat16(a0);
        hv.y = __float2bfloat16(a1);
        lv.x = __float2bfloat16(a0 - __bfloat162float(hv.x));
        lv.y = __float2bfloat16(a1 - __bfloat162float(hv.y));
        *(__nv_bfloat162*)&qh[i] = hv;
        *(__nv_bfloat162*)&ql[i] = lv;
    }
}

// ---------------------------------------------------------------------------
// k column sums of exp over sequence axis
// ---------------------------------------------------------------------------
__global__ __launch_bounds__(256) void ksum_kernel() {
    int h = blockIdx.y;
    int d = blockIdx.x * 256 + threadIdx.x;
    const float* base = g_K + (size_t)h * CC * DD + d;
    float s = 0.f;
    for (int n = 0; n < CC; n++) s += __expf(base[(size_t)n * DD]);
    g_ksum[h * DD + d] = s;
}

// ---------------------------------------------------------------------------
// transpose + split. KMODE: apply exp()*inv(colsum) and also write direct bf16.
// src [h][n][d] fp32 -> dth/dtl [h][d][n] bf16 (+ dir [h][n][d] bf16 hi, KMODE)
// block (32,8), grid (DD/32, CC/32, HH)
// ---------------------------------------------------------------------------
template <bool KMODE>
__global__ __launch_bounds__(256) void trans_split_kernel(const float* __restrict__ src,
                                                          bf16* __restrict__ dir,
                                                          bf16* __restrict__ dth,
                                                          bf16* __restrict__ dtl) {
    __shared__ float t[32][33];
    int h = blockIdx.z;
    int d0 = blockIdx.x * 32, n0 = blockIdx.y * 32;
    int tx = threadIdx.x, ty = threadIdx.y;
    const float* sp = src + (size_t)h * CC * DD;

    float inv = 0.f;
    if (KMODE) inv = 1.0f / g_ksum[h * DD + d0 + tx];

#pragma unroll
    for (int i = 0; i < 4; i++) {
        int n = n0 + ty + i * 8;
        float v = sp[(size_t)n * DD + d0 + tx];
        if (KMODE) {
            v = __expf(v) * inv;
            dir[(size_t)h * CC * DD + (size_t)n * DD + d0 + tx] = __float2bfloat16(v);
        }
        t[ty + i * 8][tx] = v;
    }
    __syncthreads();
#pragma unroll
    for (int i = 0; i < 4; i++) {
        int dl = ty + i * 8;
        float v = t[tx][dl];
        bf16 hi = __float2bfloat16(v);
        bf16 lo = __float2bfloat16(v - __bfloat162float(hi));
        size_t o = (size_t)h * DD * CC + (size_t)(d0 + dl) * CC + n0 + tx;
        dth[o] = hi;
        dtl[o] = lo;
    }
}

// ---------------------------------------------------------------------------
// launch
// ---------------------------------------------------------------------------
extern "C" void kernel_launch(void* const* d_in, const int* in_sizes, int n_in,
                              void* d_out, int out_size) {
    const float* x  = (const float*)d_in[0];
    const float* Wq = (const float*)d_in[1];
    const float* bq = (const float*)d_in[2];
    const float* Wk = (const float*)d_in[3];
    const float* bk = (const float*)d_in[4];
    const float* Wv = (const float*)d_in[5];
    const float* bv = (const float*)d_in[6];
    float* out = (float*)d_out;

    // device-global pointers
    float *pQ, *pK, *pV;
    bf16 *pxh, *pxl, *pWqh, *pWql, *pWkh, *pWkl, *pWvh, *pWvl;
    bf16 *pQh, *pQl, *pKh, *pKTh, *pKTl, *pVTh, *pVTl, *pCTh, *pCTl;
    cudaGetSymbolAddress((void**)&pQ, g_Q);
    cudaGetSymbolAddress((void**)&pK, g_K);
    cudaGetSymbolAddress((void**)&pV, g_V);
    cudaGetSymbolAddress((void**)&pxh, g_xh);
    cudaGetSymbolAddress((void**)&pxl, g_xl);
    cudaGetSymbolAddress((void**)&pWqh, g_Wqh);
    cudaGetSymbolAddress((void**)&pWql, g_Wql);
    cudaGetSymbolAddress((void**)&pWkh, g_Wkh);
    cudaGetSymbolAddress((void**)&pWkl, g_Wkl);
    cudaGetSymbolAddress((void**)&pWvh, g_Wvh);
    cudaGetSymbolAddress((void**)&pWvl, g_Wvl);
    cudaGetSymbolAddress((void**)&pQh, g_Qh);
    cudaGetSymbolAddress((void**)&pQl, g_Ql);
    cudaGetSymbolAddress((void**)&pKh, g_Kh);
    cudaGetSymbolAddress((void**)&pKTh, g_KTh);
    cudaGetSymbolAddress((void**)&pKTl, g_KTl);
    cudaGetSymbolAddress((void**)&pVTh, g_VTh);
    cudaGetSymbolAddress((void**)&pVTl, g_VTl);
    cudaGetSymbolAddress((void**)&pCTh, g_CTh);
    cudaGetSymbolAddress((void**)&pCTl, g_CTl);

    const int SMEM1 = 2 * 2 * 128 * LDS * 2;  // 2 tiles x 2 stages x bytes = 40960
    const int SMEM3 = 4 * 2 * 128 * LDS * 2;  // 81920
    cudaFuncSetAttribute(mma_gemm<1, 0>, cudaFuncAttributeMaxDynamicSharedMemorySize, SMEM1);
    cudaFuncSetAttribute(mma_gemm<3, 1>, cudaFuncAttributeMaxDynamicSharedMemorySize, SMEM3);
    cudaFuncSetAttribute(mma_gemm<3, 2>, cudaFuncAttributeMaxDynamicSharedMemorySize, SMEM3);
    cudaFuncSetAttribute(mma_gemm<3, 3>, cudaFuncAttributeMaxDynamicSharedMemorySize, SMEM3);

    dim3 t256(256);

    // 1) splits
    split_kernel<<<(RR * CC * EE + 255) / 256, t256>>>(x, pxh, pxl, RR * CC * EE);
    split_kernel<<<(EE * EE + 255) / 256, t256>>>(Wq, pWqh, pWql, EE * EE);
    split_kernel<<<(EE * EE + 255) / 256, t256>>>(Wk, pWkh, pWkl, EE * EE);
    split_kernel<<<(EE * EE + 255) / 256, t256>>>(Wv, pWvh, pWvl, EE * EE);

    // 2) projections: M=RR*CC=131072, N=128, K=128 (3-term, EPI=3)
    dim3 gproj(1, (RR * CC) / 128, 1);
    mma_gemm<3, 3><<<gproj, t256, SMEM3>>>(pxh, pxl, pWqh, pWql, pQ, nullptr, nullptr,
                                           bq, EE, EE, EE, 0, 0, 0, 0);
    mma_gemm<3, 3><<<gproj, t256, SMEM3>>>(pxh, pxl, pWkh, pWkl, pK, nullptr, nullptr,
                                           bk, EE, EE, EE, 0, 0, 0, 0);
    mma_gemm<3, 3><<<gproj, t256, SMEM3>>>(pxh, pxl, pWvh, pWvl, pV, nullptr, nullptr,
                                           bv, EE, EE, EE, 0, 0, 0, 0);

    // 3) activations + layout conversion
    qsoft_kernel<<<(HH * CC * RR) / 256, t256>>>();
    ksum_kernel<<<dim3(DD / 256, HH), t256>>>();
    trans_split_kernel<true><<<dim3(DD / 32, CC / 32, HH), dim3(32, 8)>>>(pK, pKh, pKTh, pKTl);
    trans_split_kernel<false><<<dim3(DD / 32, CC / 32, HH), dim3(32, 8)>>>(pV, nullptr, pVTh, pVTl);

    // 4) attn[h][n][m] = sum_d Qh[n][d] Kh[m][d]  (1-term) -> out + RR*CC*EE
    mma_gemm<1, 0><<<dim3(CC / 128, CC / 128, HH), t256, SMEM1>>>(
        pQh, nullptr, pKh, nullptr, out + (size_t)RR * CC * EE, nullptr, nullptr,
        nullptr, DD, DD, DD, CC,
        (size_t)CC * DD, (size_t)CC * DD, (size_t)CC * CC);

    // 5) ctxT[e][d] = sum_n VT[e][n] KT[d][n]  (3-term) -> g_CTh/g_CTl
    mma_gemm<3, 1><<<dim3(DD / 128, DD / 128, HH), t256, SMEM3>>>(
        pVTh, pVTl, pKTh, pKTl, nullptr, pCTh, pCTl,
        nullptr, CC, CC, CC, DD,
        (size_t)DD * CC, (size_t)DD * CC, (size_t)DD * DD);

    // 6) out[c][col] = sum_d Q[c][d] ctxT[col][d]  (3-term), scatter epilogue
    mma_gemm<3, 2><<<dim3(DD / 128, CC / 128, HH), t256, SMEM3>>>(
        pQh, pQl, pCTh, pCTl, out, nullptr, nullptr,
        nullptr, DD, DD, DD, 0,
        (size_t)CC * DD, (size_t)DD * DD, 0);
}

// round 4
// speedup vs baseline: 3.2109x; 1.0857x over previous
#include <cuda_runtime.h>
#include <cuda_bf16.h>
#include <cstdint>

// Gene Linear Attention — bf16 mma.sync pipeline v2.
// CTA tile 256x128, warp tile 64x64 (8 warps), K-chunk 32, multi-stage cp.async.
// proj fused (N=384) -> q softmax -> k softmax+transpose -> v transpose
// -> attn = Qh Kh^T (1-term) -> ctxT = VT KT^T (3-term) -> out = Q ctxT^T (3-term)

#define RR   64
#define CC   2048
#define EE   128
#define HH   8
#define HDIM 16
#define DD   1024   // RR*HDIM

typedef __nv_bfloat16 bf16;

// ---------------- device global scratch ----------------
__device__ float g_Q[HH * CC * DD];
__device__ float g_K[HH * CC * DD];
__device__ float g_V[HH * CC * DD];
__device__ float g_ksum[HH * DD];
__device__ float g_ball[3 * EE];

__device__ bf16 g_xh[RR * CC * EE];
__device__ bf16 g_xl[RR * CC * EE];
__device__ bf16 g_Wallh[3 * EE * EE];   // Wq|Wk|Wv stacked rows
__device__ bf16 g_Walll[3 * EE * EE];

__device__ bf16 g_Qh[HH * CC * DD];
__device__ bf16 g_Ql[HH * CC * DD];
__device__ bf16 g_Kh[HH * CC * DD];
__device__ bf16 g_KTh[HH * DD * CC];
__device__ bf16 g_KTl[HH * DD * CC];
__device__ bf16 g_VTh[HH * DD * CC];
__device__ bf16 g_VTl[HH * DD * CC];
__device__ bf16 g_CTh[HH * DD * DD];
__device__ bf16 g_CTl[HH * DD * DD];

// ---------------- PTX helpers ----------------
__device__ __forceinline__ uint32_t cvta(const void* p) {
    return (uint32_t)__cvta_generic_to_shared(p);
}
__device__ __forceinline__ void cp16(uint32_t dst, const void* src) {
    asm volatile("cp.async.cg.shared.global [%0], [%1], 16;\n" :: "r"(dst), "l"(src));
}
#define CP_COMMIT() asm volatile("cp.async.commit_group;\n" ::)

__device__ __forceinline__ void ldm4(uint32_t (&a)[4], uint32_t addr) {
    asm volatile("ldmatrix.sync.aligned.m8n8.x4.shared.b16 {%0,%1,%2,%3}, [%4];"
                 : "=r"(a[0]), "=r"(a[1]), "=r"(a[2]), "=r"(a[3]) : "r"(addr));
}
__device__ __forceinline__ void mma16816(float (&c)[4], const uint32_t (&a)[4],
                                         const uint32_t b0, const uint32_t b1) {
    asm volatile(
        "mma.sync.aligned.m16n8k16.row.col.f32.bf16.bf16.f32 "
        "{%0,%1,%2,%3}, {%4,%5,%6,%7}, {%8,%9}, {%0,%1,%2,%3};"
        : "+f"(c[0]), "+f"(c[1]), "+f"(c[2]), "+f"(c[3])
        : "r"(a[0]), "r"(a[1]), "r"(a[2]), "r"(a[3]), "r"(b0), "r"(b1));
}

// ---------------------------------------------------------------------------
// NT GEMM: C[m][n] = sum_k A[m][k]*B[n][k].
// CTA 256x128, warps 4x2, warp tile 64x64, BK=32.
// TERMS=1: Ah*Bh. TERMS=3: Ah*Bh + Al*Bh + Ah*Bl.
// EPI: 0 attn fp32, 1 ctx bf16 hi/lo, 2 out scatter fp32, 3 proj scatter (+bias, Q/K/V select)
// ---------------------------------------------------------------------------
#define BM 256
#define BN 128
#define BK 32
#define LDSS 40                      // bf16 stride (32 + 8 pad)
#define OFF_BH (BM * LDSS)           // bf16 units
#define OFF_AL (OFF_BH + BN * LDSS)
#define OFF_BL (OFF_AL + BM * LDSS)

template <int TERMS, int EPI, int S>
__global__ __launch_bounds__(256, 1) void tc_gemm(
    const bf16* __restrict__ Ah, const bf16* __restrict__ Al,
    const bf16* __restrict__ Bh, const bf16* __restrict__ Bl,
    float* __restrict__ C0, float* __restrict__ C1, float* __restrict__ C2,
    bf16* __restrict__ E0, bf16* __restrict__ E1,
    const float* __restrict__ bias,
    int Kdim, int ldA, int ldB, int ldc,
    size_t sAh, size_t sBh, size_t sCh)
{
    extern __shared__ __align__(16) bf16 smem[];
    const int STAGE = (TERMS == 3) ? (2 * (BM + BN) * LDSS) : ((BM + BN) * LDSS);

    const int tid = threadIdx.x, lane = tid & 31, warp = tid >> 5;
    const int wm = warp >> 1, wn = warp & 1;       // 4 x 2 warp grid
    const int h = blockIdx.z;
    const bf16* pAh = Ah + (size_t)h * sAh;
    const bf16* pBh = Bh + (size_t)h * sBh;
    const bf16* pAl = (TERMS == 3) ? Al + (size_t)h * sAh : nullptr;
    const bf16* pBl = (TERMS == 3) ? Bl + (size_t)h * sBh : nullptr;
    const int m0 = blockIdx.y * BM, n0 = blockIdx.x * BN;

    float acc[4][8][4];
#pragma unroll
    for (int i = 0; i < 4; i++)
#pragma unroll
        for (int j = 0; j < 8; j++)
#pragma unroll
            for (int q = 0; q < 4; q++) acc[i][j][q] = 0.f;

    auto load_stage = [&](int st, int k0) {
        bf16* s = smem + st * STAGE;
        // A: 256 rows x 32 cols = 1024 x 16B
#pragma unroll
        for (int t = 0; t < 4; t++) {
            int slot = tid + t * 256;
            int r = slot >> 2, seg = slot & 3;
            uint32_t so = cvta(s + r * LDSS + seg * 8);
            size_t ga = (size_t)(m0 + r) * ldA + k0 + seg * 8;
            cp16(so, pAh + ga);
            if (TERMS == 3) cp16(so + OFF_AL * 2, pAl + ga);
        }
        // B: 128 rows x 32 cols = 512 x 16B
#pragma unroll
        for (int t = 0; t < 2; t++) {
            int slot = tid + t * 256;
            int r = slot >> 2, seg = slot & 3;
            uint32_t so = cvta(s + OFF_BH + r * LDSS + seg * 8);
            size_t gb = (size_t)(n0 + r) * ldB + k0 + seg * 8;
            cp16(so, pBh + gb);
            if (TERMS == 3) cp16(so + (OFF_BL - OFF_BH) * 2, pBl + gb);
        }
    };

    const int nk = Kdim / BK;
    for (int s = 0; s < S - 1; s++) {
        if (s < nk) load_stage(s, s * BK);
        CP_COMMIT();
    }

    for (int i = 0; i < nk; i++) {
        asm volatile("cp.async.wait_group %0;\n" :: "n"(S - 2));
        __syncthreads();
        {
            int j = i + S - 1;
            if (j < nk) load_stage(j % S, j * BK);
            CP_COMMIT();
        }

        const bf16* s = smem + (i % S) * STAGE;
        const uint32_t baseA = cvta(s);
        const uint32_t baseB = cvta(s + OFF_BH);

#pragma unroll
        for (int kk = 0; kk < 2; kk++) {
            uint32_t a[4][4], a2[4][4], b[4][4];
            // a-frags: rows wm*64 + mi*16
#pragma unroll
            for (int mi = 0; mi < 4; mi++) {
                int m = wm * 64 + mi * 16 + (lane & 15);
                ldm4(a[mi], baseA + (uint32_t)(m * LDSS + kk * 16 + (lane >> 4) * 8) * 2);
            }
            // b-frags: 16 cols per ldm4: cols wn*64 + nb*16
#pragma unroll
            for (int nb = 0; nb < 4; nb++) {
                int n = wn * 64 + nb * 16 + ((lane >> 4) << 3) + (lane & 7);
                ldm4(b[nb], baseB + (uint32_t)(n * LDSS + kk * 16 + ((lane >> 3) & 1) * 8) * 2);
            }
#pragma unroll
            for (int mi = 0; mi < 4; mi++)
#pragma unroll
                for (int nb = 0; nb < 4; nb++) {
                    mma16816(acc[mi][nb * 2], a[mi], b[nb][0], b[nb][1]);
                    mma16816(acc[mi][nb * 2 + 1], a[mi], b[nb][2], b[nb][3]);
                }

            if (TERMS == 3) {
                // a_lo * b_hi
#pragma unroll
                for (int mi = 0; mi < 4; mi++) {
                    int m = wm * 64 + mi * 16 + (lane & 15);
                    ldm4(a2[mi], baseA + (uint32_t)(OFF_AL + m * LDSS + kk * 16 + (lane >> 4) * 8) * 2);
                }
#pragma unroll
                for (int mi = 0; mi < 4; mi++)
#pragma unroll
                    for (int nb = 0; nb < 4; nb++) {
                        mma16816(acc[mi][nb * 2], a2[mi], b[nb][0], b[nb][1]);
                        mma16816(acc[mi][nb * 2 + 1], a2[mi], b[nb][2], b[nb][3]);
                    }
                // a_hi * b_lo (overwrite b regs)
#pragma unroll
                for (int nb = 0; nb < 4; nb++) {
                    int n = wn * 64 + nb * 16 + ((lane >> 4) << 3) + (lane & 7);
                    ldm4(b[nb], baseB + (uint32_t)((OFF_BL - OFF_BH) + n * LDSS + kk * 16 + ((lane >> 3) & 1) * 8) * 2);
                }
#pragma unroll
                for (int mi = 0; mi < 4; mi++)
#pragma unroll
                    for (int nb = 0; nb < 4; nb++) {
                        mma16816(acc[mi][nb * 2], a[mi], b[nb][0], b[nb][1]);
                        mma16816(acc[mi][nb * 2 + 1], a[mi], b[nb][2], b[nb][3]);
                    }
            }
        }
    }

    // ---------------- epilogue ----------------
    float* dst3 = nullptr;
    if (EPI == 3) {
        int sel = n0 >> 7;           // 0:Q 1:K 2:V (BN=128 aligned)
        dst3 = (sel == 0) ? C0 : (sel == 1) ? C1 : C2;
    }
#pragma unroll
    for (int mi = 0; mi < 4; mi++) {
#pragma unroll
        for (int ni = 0; ni < 8; ni++) {
            int grow = m0 + wm * 64 + mi * 16 + (lane >> 2);
            int gcol = n0 + wn * 64 + ni * 8 + (lane & 3) * 2;
            float v0 = acc[mi][ni][0], v1 = acc[mi][ni][1];
            float v2 = acc[mi][ni][2], v3 = acc[mi][ni][3];

            if (EPI == 0) {          // attn fp32 row-major
                float* base = C0 + (size_t)h * sCh;
                *(float2*)&base[(size_t)grow * ldc + gcol] = make_float2(v0, v1);
                *(float2*)&base[(size_t)(grow + 8) * ldc + gcol] = make_float2(v2, v3);
            } else if (EPI == 1) {   // ctx bf16 hi/lo
                bf16* bh = E0 + (size_t)h * sCh;
                bf16* bl = E1 + (size_t)h * sCh;
#pragma unroll
                for (int rr2 = 0; rr2 < 2; rr2++) {
                    int row = grow + rr2 * 8;
                    float a0 = rr2 ? v2 : v0, a1 = rr2 ? v3 : v1;
                    __nv_bfloat162 hv, lv;
                    hv.x = __float2bfloat16(a0);
                    hv.y = __float2bfloat16(a1);
                    lv.x = __float2bfloat16(a0 - __bfloat162float(hv.x));
                    lv.y = __float2bfloat16(a1 - __bfloat162float(hv.y));
                    *(__nv_bfloat162*)&bh[(size_t)row * ldc + gcol] = hv;
                    *(__nv_bfloat162*)&bl[(size_t)row * ldc + gcol] = lv;
                }
            } else if (EPI == 2) {   // out scatter: col=r*16+j, row=c
                int r = gcol >> 4, j = gcol & 15;
#pragma unroll
                for (int rr2 = 0; rr2 < 2; rr2++) {
                    int c = grow + rr2 * 8;
                    float a0 = rr2 ? v2 : v0, a1 = rr2 ? v3 : v1;
                    *(float2*)&C0[(((size_t)r * CC + c) << 7) + h * HDIM + j] =
                        make_float2(a0, a1);
                }
            } else {                 // proj scatter (+bias) to fp32 [hh][c][r*16+jj]
                int e = gcol & 127;
                int hh = e >> 4, jj = e & 15;
                float b0 = bias[gcol], b1 = bias[gcol + 1];
#pragma unroll
                for (int rr2 = 0; rr2 < 2; rr2++) {
                    int rc = grow + rr2 * 8;
                    int r = rc >> 11, c = rc & (CC - 1);
                    float a0 = (rr2 ? v2 : v0) + b0, a1 = (rr2 ? v3 : v1) + b1;
                    *(float2*)&dst3[((size_t)hh * CC + c) * DD + (r << 4) + jj] =
                        make_float2(a0, a1);
                }
            }
        }
    }
}

// ---------------------------------------------------------------------------
// elementwise kernels
// ---------------------------------------------------------------------------
__global__ __launch_bounds__(256) void split_kernel(const float* __restrict__ src,
                                                    bf16* __restrict__ dh,
                                                    bf16* __restrict__ dl, int n) {
    int i = blockIdx.x * 256 + threadIdx.x;
    if (i >= n) return;
    float v = src[i];
    bf16 h = __float2bfloat16(v);
    dh[i] = h;
    dl[i] = __float2bfloat16(v - __bfloat162float(h));
}

__global__ void pack_bias_kernel(const float* bq, const float* bk, const float* bv) {
    int i = threadIdx.x;  // 384
    float v = (i < 128) ? bq[i] : (i < 256) ? bk[i - 128] : bv[i - 256];
    g_ball[i] = v;
}

__global__ __launch_bounds__(256) void qsoft_kernel() {
    size_t g = (size_t)blockIdx.x * blockDim.x + threadIdx.x;
    const float* p = g_Q + g * 16;
    float v[16];
    *(float4*)&v[0] = *(const float4*)&p[0];
    *(float4*)&v[4] = *(const float4*)&p[4];
    *(float4*)&v[8] = *(const float4*)&p[8];
    *(float4*)&v[12] = *(const float4*)&p[12];
    float mx = v[0];
#pragma unroll
    for (int i = 1; i < 16; i++) mx = fmaxf(mx, v[i]);
    float s = 0.f;
#pragma unroll
    for (int i = 0; i < 16; i++) { v[i] = __expf(v[i] - mx); s += v[i]; }
    float sc = 0.03125f / s;
    bf16* qh = g_Qh + g * 16;
    bf16* ql = g_Ql + g * 16;
#pragma unroll
    for (int i = 0; i < 16; i += 2) {
        float a0 = v[i] * sc, a1 = v[i + 1] * sc;
        __nv_bfloat162 hv, lv;
        hv.x = __float2bfloat16(a0);
        hv.y = __float2bfloat16(a1);
        lv.x = __float2bfloat16(a0 - __bfloat162float(hv.x));
        lv.y = __float2bfloat16(a1 - __bfloat162float(hv.y));
        *(__nv_bfloat162*)&qh[i] = hv;
        *(__nv_bfloat162*)&ql[i] = lv;
    }
}

__global__ __launch_bounds__(256) void ksum_kernel() {
    int h = blockIdx.y;
    int d = blockIdx.x * 256 + threadIdx.x;
    const float* base = g_K + (size_t)h * CC * DD + d;
    float s = 0.f;
    for (int n = 0; n < CC; n++) s += __expf(base[(size_t)n * DD]);
    g_ksum[h * DD + d] = s;
}

template <bool KMODE>
__global__ __launch_bounds__(256) void trans_split_kernel(const float* __restrict__ src,
                                                          bf16* __restrict__ dir,
                                                          bf16* __restrict__ dth,
                                                          bf16* __restrict__ dtl) {
    __shared__ float t[32][33];
    int h = blockIdx.z;
    int d0 = blockIdx.x * 32, n0 = blockIdx.y * 32;
    int tx = threadIdx.x, ty = threadIdx.y;
    const float* sp = src + (size_t)h * CC * DD;

    float inv = 0.f;
    if (KMODE) inv = 1.0f / g_ksum[h * DD + d0 + tx];

#pragma unroll
    for (int i = 0; i < 4; i++) {
        int n = n0 + ty + i * 8;
        float v = sp[(size_t)n * DD + d0 + tx];
        if (KMODE) {
            v = __expf(v) * inv;
            dir[(size_t)h * CC * DD + (size_t)n * DD + d0 + tx] = __float2bfloat16(v);
        }
        t[ty + i * 8][tx] = v;
    }
    __syncthreads();
#pragma unroll
    for (int i = 0; i < 4; i++) {
        int dl = ty + i * 8;
        float v = t[tx][dl];
        bf16 hi = __float2bfloat16(v);
        bf16 lo = __float2bfloat16(v - __bfloat162float(hi));
        size_t o = (size_t)h * DD * CC + (size_t)(d0 + dl) * CC + n0 + tx;
        dth[o] = hi;
        dtl[o] = lo;
    }
}

// ---------------------------------------------------------------------------
// launch
// ---------------------------------------------------------------------------
extern "C" void kernel_launch(void* const* d_in, const int* in_sizes, int n_in,
                              void* d_out, int out_size) {
    const float* x  = (const float*)d_in[0];
    const float* Wq = (const float*)d_in[1];
    const float* bq = (const float*)d_in[2];
    const float* Wk = (const float*)d_in[3];
    const float* bk = (const float*)d_in[4];
    const float* Wv = (const float*)d_in[5];
    const float* bv = (const float*)d_in[6];
    float* out = (float*)d_out;

    float *pQ, *pK, *pV, *pball;
    bf16 *pxh, *pxl, *pWh, *pWl;
    bf16 *pQh, *pQl, *pKh, *pKTh, *pKTl, *pVTh, *pVTl, *pCTh, *pCTl;
    cudaGetSymbolAddress((void**)&pQ, g_Q);
    cudaGetSymbolAddress((void**)&pK, g_K);
    cudaGetSymbolAddress((void**)&pV, g_V);
    cudaGetSymbolAddress((void**)&pball, g_ball);
    cudaGetSymbolAddress((void**)&pxh, g_xh);
    cudaGetSymbolAddress((void**)&pxl, g_xl);
    cudaGetSymbolAddress((void**)&pWh, g_Wallh);
    cudaGetSymbolAddress((void**)&pWl, g_Walll);
    cudaGetSymbolAddress((void**)&pQh, g_Qh);
    cudaGetSymbolAddress((void**)&pQl, g_Ql);
    cudaGetSymbolAddress((void**)&pKh, g_Kh);
    cudaGetSymbolAddress((void**)&pKTh, g_KTh);
    cudaGetSymbolAddress((void**)&pKTl, g_KTl);
    cudaGetSymbolAddress((void**)&pVTh, g_VTh);
    cudaGetSymbolAddress((void**)&pVTl, g_VTl);
    cudaGetSymbolAddress((void**)&pCTh, g_CTh);
    cudaGetSymbolAddress((void**)&pCTl, g_CTl);

    const int ST1 = (BM + BN) * LDSS * 2;       // bytes per 1-term stage = 30720
    const int ST3 = 2 * (BM + BN) * LDSS * 2;   // 61440
    const int SMEM1 = 4 * ST1;                  // 122880
    const int SMEM3 = 3 * ST3;                  // 184320
    cudaFuncSetAttribute(tc_gemm<1, 0, 4>, cudaFuncAttributeMaxDynamicSharedMemorySize, SMEM1);
    cudaFuncSetAttribute(tc_gemm<3, 1, 3>, cudaFuncAttributeMaxDynamicSharedMemorySize, SMEM3);
    cudaFuncSetAttribute(tc_gemm<3, 2, 3>, cudaFuncAttributeMaxDynamicSharedMemorySize, SMEM3);
    cudaFuncSetAttribute(tc_gemm<3, 3, 3>, cudaFuncAttributeMaxDynamicSharedMemorySize, SMEM3);

    dim3 t256(256);

    // 1) splits + bias pack
    split_kernel<<<(RR * CC * EE + 255) / 256, t256>>>(x, pxh, pxl, RR * CC * EE);
    split_kernel<<<(EE * EE + 255) / 256, t256>>>(Wq, pWh, pWl, EE * EE);
    split_kernel<<<(EE * EE + 255) / 256, t256>>>(Wk, pWh + EE * EE, pWl + EE * EE, EE * EE);
    split_kernel<<<(EE * EE + 255) / 256, t256>>>(Wv, pWh + 2 * EE * EE, pWl + 2 * EE * EE, EE * EE);
    pack_bias_kernel<<<1, 384>>>(bq, bk, bv);

    // 2) fused projection: M=131072, N=384, K=128 (3-term, EPI=3)
    tc_gemm<3, 3, 3><<<dim3(3, (RR * CC) / BM, 1), t256, SMEM3>>>(
        pxh, pxl, pWh, pWl, pQ, pK, pV, nullptr, nullptr,
        pball, EE, EE, EE, 0, 0, 0, 0);

    // 3) activations + layout conversion
    qsoft_kernel<<<(HH * CC * RR) / 256, t256>>>();
    ksum_kernel<<<dim3(DD / 256, HH), t256>>>();
    trans_split_kernel<true><<<dim3(DD / 32, CC / 32, HH), dim3(32, 8)>>>(pK, pKh, pKTh, pKTl);
    trans_split_kernel<false><<<dim3(DD / 32, CC / 32, HH), dim3(32, 8)>>>(pV, nullptr, pVTh, pVTl);

    // 4) attn[h][n][m] = sum_d Qh[n][d] Kh[m][d]  (1-term) -> out + RR*CC*EE
    tc_gemm<1, 0, 4><<<dim3(CC / BN, CC / BM, HH), t256, SMEM1>>>(
        pQh, nullptr, pKh, nullptr, out + (size_t)RR * CC * EE, nullptr, nullptr,
        nullptr, nullptr, nullptr, DD, DD, DD, CC,
        (size_t)CC * DD, (size_t)CC * DD, (size_t)CC * CC);

    // 5) ctxT[e][d] = sum_n VT[e][n] KT[d][n]  (3-term) -> g_CTh/g_CTl
    tc_gemm<3, 1, 3><<<dim3(DD / BN, DD / BM, HH), t256, SMEM3>>>(
        pVTh, pVTl, pKTh, pKTl, nullptr, nullptr, nullptr, pCTh, pCTl,
        nullptr, CC, CC, CC, DD,
        (size_t)DD * CC, (size_t)DD * CC, (size_t)DD * DD);

    // 6) out[c][col] = sum_d Q[c][d] ctxT[col][d]  (3-term), scatter epilogue
    tc_gemm<3, 2, 3><<<dim3(DD / BN, CC / BM, HH), t256, SMEM3>>>(
        pQh, pQl, pCTh, pCTl, out, nullptr, nullptr, nullptr, nullptr,
        nullptr, DD, DD, DD, 0,
        (size_t)CC * DD, (size_t)DD * DD, 0);
}

// round 5
// speedup vs baseline: 4.7538x; 1.4805x over previous
#include <cuda_runtime.h>
#include <cuda_fp16.h>
#include <cstdint>

// Gene Linear Attention — fp16 mma.sync pipeline v3.
// fp16 ε=2^-11 lets attn/ctx/out run 1-term; proj stays 3-term for clean logits.
// q softmax fused into proj epilogue (quad shuffles).

#define RR   64
#define CC   2048
#define EE   128
#define HH   8
#define HDIM 16
#define DD   1024   // RR*HDIM

typedef __half hf;

// ---------------- device global scratch ----------------
__device__ float g_K[HH * CC * DD];     // k logits fp32
__device__ float g_V[HH * CC * DD];     // v fp32
__device__ float g_ksum[HH * DD];
__device__ float g_ball[3 * EE];

__device__ hf g_xh[RR * CC * EE];
__device__ hf g_xl[RR * CC * EE];
__device__ hf g_Wallh[3 * EE * EE];     // Wq|Wk|Wv stacked rows
__device__ hf g_Walll[3 * EE * EE];

__device__ hf g_Qh[HH * CC * DD];       // softmaxed+scaled q, [h][c][d]
__device__ hf g_Kh[HH * CC * DD];       // softmaxed k, [h][n][d]
__device__ hf g_KTh[HH * DD * CC];      // softmaxed k transposed [h][d][n]
__device__ hf g_VTh[HH * DD * CC];      // v transposed [h][e][n]
__device__ hf g_CTh[HH * DD * DD];      // ctxT [h][col][d]

// ---------------- PTX helpers ----------------
__device__ __forceinline__ uint32_t cvta(const void* p) {
    return (uint32_t)__cvta_generic_to_shared(p);
}
__device__ __forceinline__ void cp16(uint32_t dst, const void* src) {
    asm volatile("cp.async.cg.shared.global [%0], [%1], 16;\n" :: "r"(dst), "l"(src));
}
#define CP_COMMIT() asm volatile("cp.async.commit_group;\n" ::)

__device__ __forceinline__ void ldm4(uint32_t (&a)[4], uint32_t addr) {
    asm volatile("ldmatrix.sync.aligned.m8n8.x4.shared.b16 {%0,%1,%2,%3}, [%4];"
                 : "=r"(a[0]), "=r"(a[1]), "=r"(a[2]), "=r"(a[3]) : "r"(addr));
}
__device__ __forceinline__ void mma16816(float (&c)[4], const uint32_t (&a)[4],
                                         const uint32_t b0, const uint32_t b1) {
    asm volatile(
        "mma.sync.aligned.m16n8k16.row.col.f32.f16.f16.f32 "
        "{%0,%1,%2,%3}, {%4,%5,%6,%7}, {%8,%9}, {%0,%1,%2,%3};"
        : "+f"(c[0]), "+f"(c[1]), "+f"(c[2]), "+f"(c[3])
        : "r"(a[0]), "r"(a[1]), "r"(a[2]), "r"(a[3]), "r"(b0), "r"(b1));
}

// ---------------------------------------------------------------------------
// NT GEMM: C[m][n] = sum_k A[m][k]*B[n][k].  CTA 256x128, warps 4x2 (64x64), BK=32.
// TERMS=1: Ah*Bh. TERMS=3: + Al*Bh + Ah*Bl.
// EPI: 0 attn fp32 store, 1 ctx fp16 store, 2 out scatter fp32,
//      3 proj: Q block -> fused 16-group softmax -> fp16; K/V blocks -> fp32 scatter (+bias)
// ---------------------------------------------------------------------------
#define BM 256
#define BN 128
#define BK 32
#define LDSS 40                      // half stride (32 + 8 pad)
#define OFF_BH (BM * LDSS)
#define OFF_AL (OFF_BH + BN * LDSS)
#define OFF_BL (OFF_AL + BM * LDSS)

template <int TERMS, int EPI, int S>
__global__ __launch_bounds__(256, 1) void tc_gemm(
    const hf* __restrict__ Ah, const hf* __restrict__ Al,
    const hf* __restrict__ Bh, const hf* __restrict__ Bl,
    float* __restrict__ C0, float* __restrict__ C1, float* __restrict__ C2,
    hf* __restrict__ E0,
    const float* __restrict__ bias,
    int Kdim, int ldA, int ldB, int ldc,
    size_t sAh, size_t sBh, size_t sCh)
{
    extern __shared__ __align__(16) hf smem[];
    const int STAGE = (TERMS == 3) ? (2 * (BM + BN) * LDSS) : ((BM + BN) * LDSS);

    const int tid = threadIdx.x, lane = tid & 31, warp = tid >> 5;
    const int wm = warp >> 1, wn = warp & 1;
    const int h = blockIdx.z;
    const hf* pAh = Ah + (size_t)h * sAh;
    const hf* pBh = Bh + (size_t)h * sBh;
    const hf* pAl = (TERMS == 3) ? Al + (size_t)h * sAh : nullptr;
    const hf* pBl = (TERMS == 3) ? Bl + (size_t)h * sBh : nullptr;
    const int m0 = blockIdx.y * BM, n0 = blockIdx.x * BN;

    float acc[4][8][4];
#pragma unroll
    for (int i = 0; i < 4; i++)
#pragma unroll
        for (int j = 0; j < 8; j++)
#pragma unroll
            for (int q = 0; q < 4; q++) acc[i][j][q] = 0.f;

    auto load_stage = [&](int st, int k0) {
        hf* s = smem + st * STAGE;
#pragma unroll
        for (int t = 0; t < 4; t++) {
            int slot = tid + t * 256;
            int r = slot >> 2, seg = slot & 3;
            uint32_t so = cvta(s + r * LDSS + seg * 8);
            size_t ga = (size_t)(m0 + r) * ldA + k0 + seg * 8;
            cp16(so, pAh + ga);
            if (TERMS == 3) cp16(so + OFF_AL * 2, pAl + ga);
        }
#pragma unroll
        for (int t = 0; t < 2; t++) {
            int slot = tid + t * 256;
            int r = slot >> 2, seg = slot & 3;
            uint32_t so = cvta(s + OFF_BH + r * LDSS + seg * 8);
            size_t gb = (size_t)(n0 + r) * ldB + k0 + seg * 8;
            cp16(so, pBh + gb);
            if (TERMS == 3) cp16(so + (OFF_BL - OFF_BH) * 2, pBl + gb);
        }
    };

    const int nk = Kdim / BK;
    for (int s = 0; s < S - 1; s++) {
        if (s < nk) load_stage(s, s * BK);
        CP_COMMIT();
    }

    for (int i = 0; i < nk; i++) {
        asm volatile("cp.async.wait_group %0;\n" :: "n"(S - 2));
        __syncthreads();
        {
            int j = i + S - 1;
            if (j < nk) load_stage(j % S, j * BK);
            CP_COMMIT();
        }

        const hf* s = smem + (i % S) * STAGE;
        const uint32_t baseA = cvta(s);
        const uint32_t baseB = cvta(s + OFF_BH);

#pragma unroll
        for (int kk = 0; kk < 2; kk++) {
            uint32_t a[4][4], a2[4][4], b[4][4];
#pragma unroll
            for (int mi = 0; mi < 4; mi++) {
                int m = wm * 64 + mi * 16 + (lane & 15);
                ldm4(a[mi], baseA + (uint32_t)(m * LDSS + kk * 16 + (lane >> 4) * 8) * 2);
            }
#pragma unroll
            for (int nb = 0; nb < 4; nb++) {
                int n = wn * 64 + nb * 16 + ((lane >> 4) << 3) + (lane & 7);
                ldm4(b[nb], baseB + (uint32_t)(n * LDSS + kk * 16 + ((lane >> 3) & 1) * 8) * 2);
            }
#pragma unroll
            for (int mi = 0; mi < 4; mi++)
#pragma unroll
                for (int nb = 0; nb < 4; nb++) {
                    mma16816(acc[mi][nb * 2], a[mi], b[nb][0], b[nb][1]);
                    mma16816(acc[mi][nb * 2 + 1], a[mi], b[nb][2], b[nb][3]);
                }

            if (TERMS == 3) {
#pragma unroll
                for (int mi = 0; mi < 4; mi++) {
                    int m = wm * 64 + mi * 16 + (lane & 15);
                    ldm4(a2[mi], baseA + (uint32_t)(OFF_AL + m * LDSS + kk * 16 + (lane >> 4) * 8) * 2);
                }
#pragma unroll
                for (int mi = 0; mi < 4; mi++)
#pragma unroll
                    for (int nb = 0; nb < 4; nb++) {
                        mma16816(acc[mi][nb * 2], a2[mi], b[nb][0], b[nb][1]);
                        mma16816(acc[mi][nb * 2 + 1], a2[mi], b[nb][2], b[nb][3]);
                    }
#pragma unroll
                for (int nb = 0; nb < 4; nb++) {
                    int n = wn * 64 + nb * 16 + ((lane >> 4) << 3) + (lane & 7);
                    ldm4(b[nb], baseB + (uint32_t)((OFF_BL - OFF_BH) + n * LDSS + kk * 16 + ((lane >> 3) & 1) * 8) * 2);
                }
#pragma unroll
                for (int mi = 0; mi < 4; mi++)
#pragma unroll
                    for (int nb = 0; nb < 4; nb++) {
                        mma16816(acc[mi][nb * 2], a[mi], b[nb][0], b[nb][1]);
                        mma16816(acc[mi][nb * 2 + 1], a[mi], b[nb][2], b[nb][3]);
                    }
            }
        }
    }

    // ---------------- epilogue ----------------
    if (EPI == 3 && n0 == 0) {
        // fused q softmax over 16-col groups (+bias, *1/32), write fp16 to E0=Qh
#pragma unroll
        for (int mi = 0; mi < 4; mi++) {
            int rc0 = m0 + wm * 64 + mi * 16 + (lane >> 2);
#pragma unroll
            for (int nb = 0; nb < 8; nb += 2) {
                int e0 = wn * 64 + nb * 8 + (lane & 3) * 2;  // group base hh*16
                float b0 = bias[e0], b1 = bias[e0 + 1];
                float b2 = bias[e0 + 8], b3 = bias[e0 + 9];
                float r0[4] = {acc[mi][nb][0] + b0, acc[mi][nb][1] + b1,
                               acc[mi][nb + 1][0] + b2, acc[mi][nb + 1][1] + b3};
                float r1[4] = {acc[mi][nb][2] + b0, acc[mi][nb][3] + b1,
                               acc[mi][nb + 1][2] + b2, acc[mi][nb + 1][3] + b3};
                float mx0 = fmaxf(fmaxf(r0[0], r0[1]), fmaxf(r0[2], r0[3]));
                float mx1 = fmaxf(fmaxf(r1[0], r1[1]), fmaxf(r1[2], r1[3]));
                mx0 = fmaxf(mx0, __shfl_xor_sync(0xffffffffu, mx0, 1));
                mx0 = fmaxf(mx0, __shfl_xor_sync(0xffffffffu, mx0, 2));
                mx1 = fmaxf(mx1, __shfl_xor_sync(0xffffffffu, mx1, 1));
                mx1 = fmaxf(mx1, __shfl_xor_sync(0xffffffffu, mx1, 2));
                float s0 = 0.f, s1 = 0.f;
#pragma unroll
                for (int q = 0; q < 4; q++) { r0[q] = __expf(r0[q] - mx0); s0 += r0[q]; }
#pragma unroll
                for (int q = 0; q < 4; q++) { r1[q] = __expf(r1[q] - mx1); s1 += r1[q]; }
                s0 += __shfl_xor_sync(0xffffffffu, s0, 1);
                s0 += __shfl_xor_sync(0xffffffffu, s0, 2);
                s1 += __shfl_xor_sync(0xffffffffu, s1, 1);
                s1 += __shfl_xor_sync(0xffffffffu, s1, 2);
                float sc0 = 0.03125f / s0, sc1 = 0.03125f / s1;

                int hh = e0 >> 4, jj = e0 & 15;
#pragma unroll
                for (int rr2 = 0; rr2 < 2; rr2++) {
                    int rc = rc0 + rr2 * 8;
                    int r = rc >> 11, c = rc & (CC - 1);
                    float* vv = rr2 ? r1 : r0;
                    float sc = rr2 ? sc1 : sc0;
                    hf* dst = E0 + ((size_t)hh * CC + c) * DD + (r << 4) + jj;
                    *(__half2*)dst = __floats2half2_rn(vv[0] * sc, vv[1] * sc);
                    *(__half2*)(dst + 8) = __floats2half2_rn(vv[2] * sc, vv[3] * sc);
                }
            }
        }
        return;
    }

    float* dst3 = nullptr;
    if (EPI == 3) dst3 = (n0 == 128) ? C1 : C2;
#pragma unroll
    for (int mi = 0; mi < 4; mi++) {
#pragma unroll
        for (int ni = 0; ni < 8; ni++) {
            int grow = m0 + wm * 64 + mi * 16 + (lane >> 2);
            int gcol = n0 + wn * 64 + ni * 8 + (lane & 3) * 2;
            float v0 = acc[mi][ni][0], v1 = acc[mi][ni][1];
            float v2 = acc[mi][ni][2], v3 = acc[mi][ni][3];

            if (EPI == 0) {          // attn fp32 row-major
                float* base = C0 + (size_t)h * sCh;
                *(float2*)&base[(size_t)grow * ldc + gcol] = make_float2(v0, v1);
                *(float2*)&base[(size_t)(grow + 8) * ldc + gcol] = make_float2(v2, v3);
            } else if (EPI == 1) {   // ctx fp16
                hf* bh = E0 + (size_t)h * sCh;
                *(__half2*)&bh[(size_t)grow * ldc + gcol] = __floats2half2_rn(v0, v1);
                *(__half2*)&bh[(size_t)(grow + 8) * ldc + gcol] = __floats2half2_rn(v2, v3);
            } else if (EPI == 2) {   // out scatter: col=r*16+j, row=c
                int r = gcol >> 4, j = gcol & 15;
#pragma unroll
                for (int rr2 = 0; rr2 < 2; rr2++) {
                    int c = grow + rr2 * 8;
                    float a0 = rr2 ? v2 : v0, a1 = rr2 ? v3 : v1;
                    *(float2*)&C0[(((size_t)r * CC + c) << 7) + h * HDIM + j] =
                        make_float2(a0, a1);
                }
            } else {                 // proj K/V fp32 scatter (+bias)
                int e = gcol & 127;
                int hh = e >> 4, jj = e & 15;
                float b0 = bias[gcol], b1 = bias[gcol + 1];
#pragma unroll
                for (int rr2 = 0; rr2 < 2; rr2++) {
                    int rc = grow + rr2 * 8;
                    int r = rc >> 11, c = rc & (CC - 1);
                    float a0 = (rr2 ? v2 : v0) + b0, a1 = (rr2 ? v3 : v1) + b1;
                    *(float2*)&dst3[((size_t)hh * CC + c) * DD + (r << 4) + jj] =
                        make_float2(a0, a1);
                }
            }
        }
    }
}

// ---------------------------------------------------------------------------
// elementwise kernels
// ---------------------------------------------------------------------------
__global__ __launch_bounds__(256) void split_kernel(const float* __restrict__ src,
                                                    hf* __restrict__ dh,
                                                    hf* __restrict__ dl, int n) {
    int i = blockIdx.x * 256 + threadIdx.x;
    if (i >= n) return;
    float v = src[i];
    hf h = __float2half_rn(v);
    dh[i] = h;
    dl[i] = __float2half_rn(v - __half2float(h));
}

__global__ void pack_bias_kernel(const float* bq, const float* bk, const float* bv) {
    int i = threadIdx.x;  // 384
    float v = (i < 128) ? bq[i] : (i < 256) ? bk[i - 128] : bv[i - 256];
    g_ball[i] = v;
}

__global__ __launch_bounds__(256) void ksum_kernel() {
    int h = blockIdx.y;
    int d = blockIdx.x * 256 + threadIdx.x;
    const float* base = g_K + (size_t)h * CC * DD + d;
    float s = 0.f;
    for (int n = 0; n < CC; n++) s += __expf(base[(size_t)n * DD]);
    g_ksum[h * DD + d] = s;
}

// transpose fp32 -> fp16; KMODE applies exp()*inv(colsum) and writes direct copy too
template <bool KMODE>
__global__ __launch_bounds__(256) void trans_kernel(const float* __restrict__ src,
                                                    hf* __restrict__ dir,
                                                    hf* __restrict__ dth) {
    __shared__ float t[32][33];
    int h = blockIdx.z;
    int d0 = blockIdx.x * 32, n0 = blockIdx.y * 32;
    int tx = threadIdx.x, ty = threadIdx.y;
    const float* sp = src + (size_t)h * CC * DD;

    float inv = 0.f;
    if (KMODE) inv = 1.0f / g_ksum[h * DD + d0 + tx];

#pragma unroll
    for (int i = 0; i < 4; i++) {
        int n = n0 + ty + i * 8;
        float v = sp[(size_t)n * DD + d0 + tx];
        if (KMODE) {
            v = __expf(v) * inv;
            dir[(size_t)h * CC * DD + (size_t)n * DD + d0 + tx] = __float2half_rn(v);
        }
        t[ty + i * 8][tx] = v;
    }
    __syncthreads();
#pragma unroll
    for (int i = 0; i < 4; i++) {
        int dl = ty + i * 8;
        float v = t[tx][dl];
        dth[(size_t)h * DD * CC + (size_t)(d0 + dl) * CC + n0 + tx] = __float2half_rn(v);
    }
}

// ---------------------------------------------------------------------------
// launch
// ---------------------------------------------------------------------------
extern "C" void kernel_launch(void* const* d_in, const int* in_sizes, int n_in,
                              void* d_out, int out_size) {
    const float* x  = (const float*)d_in[0];
    const float* Wq = (const float*)d_in[1];
    const float* bq = (const float*)d_in[2];
    const float* Wk = (const float*)d_in[3];
    const float* bk = (const float*)d_in[4];
    const float* Wv = (const float*)d_in[5];
    const float* bv = (const float*)d_in[6];
    float* out = (float*)d_out;

    float *pK, *pV, *pball;
    hf *pxh, *pxl, *pWh, *pWl, *pQh, *pKh, *pKTh, *pVTh, *pCTh;
    cudaGetSymbolAddress((void**)&pK, g_K);
    cudaGetSymbolAddress((void**)&pV, g_V);
    cudaGetSymbolAddress((void**)&pball, g_ball);
    cudaGetSymbolAddress((void**)&pxh, g_xh);
    cudaGetSymbolAddress((void**)&pxl, g_xl);
    cudaGetSymbolAddress((void**)&pWh, g_Wallh);
    cudaGetSymbolAddress((void**)&pWl, g_Walll);
    cudaGetSymbolAddress((void**)&pQh, g_Qh);
    cudaGetSymbolAddress((void**)&pKh, g_Kh);
    cudaGetSymbolAddress((void**)&pKTh, g_KTh);
    cudaGetSymbolAddress((void**)&pVTh, g_VTh);
    cudaGetSymbolAddress((void**)&pCTh, g_CTh);

    const int SMEM1 = 4 * (BM + BN) * LDSS * 2;       // S=4, 1-term = 122880
    const int SMEM3 = 3 * 2 * (BM + BN) * LDSS * 2;   // S=3, 3-term = 184320
    cudaFuncSetAttribute(tc_gemm<3, 3, 3>, cudaFuncAttributeMaxDynamicSharedMemorySize, SMEM3);
    cudaFuncSetAttribute(tc_gemm<1, 0, 4>, cudaFuncAttributeMaxDynamicSharedMemorySize, SMEM1);
    cudaFuncSetAttribute(tc_gemm<1, 1, 4>, cudaFuncAttributeMaxDynamicSharedMemorySize, SMEM1);
    cudaFuncSetAttribute(tc_gemm<1, 2, 4>, cudaFuncAttributeMaxDynamicSharedMemorySize, SMEM1);

    dim3 t256(256);

    // 1) splits + bias pack
    split_kernel<<<(RR * CC * EE + 255) / 256, t256>>>(x, pxh, pxl, RR * CC * EE);
    split_kernel<<<(EE * EE + 255) / 256, t256>>>(Wq, pWh, pWl, EE * EE);
    split_kernel<<<(EE * EE + 255) / 256, t256>>>(Wk, pWh + EE * EE, pWl + EE * EE, EE * EE);
    split_kernel<<<(EE * EE + 255) / 256, t256>>>(Wv, pWh + 2 * EE * EE, pWl + 2 * EE * EE, EE * EE);
    pack_bias_kernel<<<1, 384>>>(bq, bk, bv);

    // 2) fused projection: M=131072, N=384, K=128 (3-term), q softmax fused for N-block 0
    tc_gemm<3, 3, 3><<<dim3(3, (RR * CC) / BM, 1), t256, SMEM3>>>(
        pxh, pxl, pWh, pWl, nullptr, pK, pV, pQh,
        pball, EE, EE, EE, 0, 0, 0, 0);

    // 3) k softmax + transposes
    ksum_kernel<<<dim3(DD / 256, HH), t256>>>();
    trans_kernel<true><<<dim3(DD / 32, CC / 32, HH), dim3(32, 8)>>>(pK, pKh, pKTh);
    trans_kernel<false><<<dim3(DD / 32, CC / 32, HH), dim3(32, 8)>>>(pV, nullptr, pVTh);

    // 4) attn[h][n][m] = sum_d Qh[n][d] Kh[m][d]  -> out + RR*CC*EE
    tc_gemm<1, 0, 4><<<dim3(CC / BN, CC / BM, HH), t256, SMEM1>>>(
        pQh, nullptr, pKh, nullptr, out + (size_t)RR * CC * EE, nullptr, nullptr, nullptr,
        nullptr, DD, DD, DD, CC,
        (size_t)CC * DD, (size_t)CC * DD, (size_t)CC * CC);

    // 5) ctxT[e][d] = sum_n VT[e][n] KT[d][n]  -> g_CTh (fp16)
    tc_gemm<1, 1, 4><<<dim3(DD / BN, DD / BM, HH), t256, SMEM1>>>(
        pVTh, nullptr, pKTh, nullptr, nullptr, nullptr, nullptr, pCTh,
        nullptr, CC, CC, CC, DD,
        (size_t)DD * CC, (size_t)DD * CC, (size_t)DD * DD);

    // 6) out[c][col] = sum_d Q[c][d] ctxT[col][d]  (scatter epilogue)
    tc_gemm<1, 2, 4><<<dim3(DD / BN, CC / BM, HH), t256, SMEM1>>>(
        pQh, nullptr, pCTh, nullptr, out, nullptr, nullptr, nullptr,
        nullptr, DD, DD, DD, 0,
        (size_t)CC * DD, (size_t)DD * DD, 0);
}

// round 6
// speedup vs baseline: 5.2973x; 1.1143x over previous
#include <cuda_runtime.h>
#include <cuda_fp16.h>
#include <cstdint>

// Gene Linear Attention — fp16 mma.sync pipeline v4 (all GEMMs 1-term).
// proj (1-term, fused q-softmax, fp16 K/V out) -> ksum -> k/v transpose
// -> attn = Qh Kh^T -> ctxT = VT KT^T -> out = Q ctxT^T

#define RR   64
#define CC   2048
#define EE   128
#define HH   8
#define HDIM 16
#define DD   1024   // RR*HDIM

typedef __half hf;

// ---------------- device global scratch ----------------
__device__ float g_ksum[HH * DD];
__device__ float g_ball[3 * EE];

__device__ hf g_xh[RR * CC * EE];
__device__ hf g_Wallh[3 * EE * EE];     // Wq|Wk|Wv stacked rows

__device__ hf g_Qh[HH * CC * DD];       // softmaxed+scaled q [h][c][d]
__device__ hf g_Klog[HH * CC * DD];     // k logits fp16 [h][c][d]
__device__ hf g_Vh[HH * CC * DD];       // v fp16 [h][c][d]
__device__ hf g_Kh[HH * CC * DD];       // softmaxed k [h][n][d]
__device__ hf g_KTh[HH * DD * CC];      // softmaxed k transposed [h][d][n]
__device__ hf g_VTh[HH * DD * CC];      // v transposed [h][e][n]
__device__ hf g_CTh[HH * DD * DD];      // ctxT [h][col][d]

// ---------------- PTX helpers ----------------
__device__ __forceinline__ uint32_t cvta(const void* p) {
    return (uint32_t)__cvta_generic_to_shared(p);
}
__device__ __forceinline__ void cp16(uint32_t dst, const void* src) {
    asm volatile("cp.async.cg.shared.global [%0], [%1], 16;\n" :: "r"(dst), "l"(src));
}
#define CP_COMMIT() asm volatile("cp.async.commit_group;\n" ::)

__device__ __forceinline__ void ldm4(uint32_t (&a)[4], uint32_t addr) {
    asm volatile("ldmatrix.sync.aligned.m8n8.x4.shared.b16 {%0,%1,%2,%3}, [%4];"
                 : "=r"(a[0]), "=r"(a[1]), "=r"(a[2]), "=r"(a[3]) : "r"(addr));
}
__device__ __forceinline__ void mma16816(float (&c)[4], const uint32_t (&a)[4],
                                         const uint32_t b0, const uint32_t b1) {
    asm volatile(
        "mma.sync.aligned.m16n8k16.row.col.f32.f16.f16.f32 "
        "{%0,%1,%2,%3}, {%4,%5,%6,%7}, {%8,%9}, {%0,%1,%2,%3};"
        : "+f"(c[0]), "+f"(c[1]), "+f"(c[2]), "+f"(c[3])
        : "r"(a[0]), "r"(a[1]), "r"(a[2]), "r"(a[3]), "r"(b0), "r"(b1));
}

// ---------------------------------------------------------------------------
// NT GEMM: C[m][n] = sum_k A[m][k]*B[n][k].  CTA 256x128, warps 4x2 (64x64), BK=32.
// EPI: 0 attn fp32 store, 1 ctx fp16 store, 2 out scatter fp32,
//      3 proj: nblock0 Q fused-softmax->E0 fp16; nblock1 K logits->E1 fp16;
//              nblock2 V->E2 fp16 (all +bias, scatter to [hh][c][r*16+jj])
// ---------------------------------------------------------------------------
#define BM 256
#define BN 128
#define BK 32
#define LDSS 40                      // half stride (32 + 8 pad)
#define OFF_BH (BM * LDSS)

template <int EPI, int S>
__global__ __launch_bounds__(256, 1) void tc_gemm(
    const hf* __restrict__ Ah, const hf* __restrict__ Bh,
    float* __restrict__ C0, hf* __restrict__ E0,
    hf* __restrict__ E1, hf* __restrict__ E2,
    const float* __restrict__ bias,
    int Kdim, int ldA, int ldB, int ldc,
    size_t sAh, size_t sBh, size_t sCh)
{
    extern __shared__ __align__(16) hf smem[];
    const int STAGE = (BM + BN) * LDSS;

    const int tid = threadIdx.x, lane = tid & 31, warp = tid >> 5;
    const int wm = warp >> 1, wn = warp & 1;
    const int h = blockIdx.z;
    const hf* pAh = Ah + (size_t)h * sAh;
    const hf* pBh = Bh + (size_t)h * sBh;
    const int m0 = blockIdx.y * BM, n0 = blockIdx.x * BN;

    float acc[4][8][4];
#pragma unroll
    for (int i = 0; i < 4; i++)
#pragma unroll
        for (int j = 0; j < 8; j++)
#pragma unroll
            for (int q = 0; q < 4; q++) acc[i][j][q] = 0.f;

    auto load_stage = [&](int st, int k0) {
        hf* s = smem + st * STAGE;
#pragma unroll
        for (int t = 0; t < 4; t++) {
            int slot = tid + t * 256;
            int r = slot >> 2, seg = slot & 3;
            cp16(cvta(s + r * LDSS + seg * 8), pAh + (size_t)(m0 + r) * ldA + k0 + seg * 8);
        }
#pragma unroll
        for (int t = 0; t < 2; t++) {
            int slot = tid + t * 256;
            int r = slot >> 2, seg = slot & 3;
            cp16(cvta(s + OFF_BH + r * LDSS + seg * 8), pBh + (size_t)(n0 + r) * ldB + k0 + seg * 8);
        }
    };

    const int nk = Kdim / BK;
    for (int s = 0; s < S - 1; s++) {
        if (s < nk) load_stage(s, s * BK);
        CP_COMMIT();
    }

    for (int i = 0; i < nk; i++) {
        asm volatile("cp.async.wait_group %0;\n" :: "n"(S - 2));
        __syncthreads();
        {
            int j = i + S - 1;
            if (j < nk) load_stage(j % S, j * BK);
            CP_COMMIT();
        }

        const hf* s = smem + (i % S) * STAGE;
        const uint32_t baseA = cvta(s);
        const uint32_t baseB = cvta(s + OFF_BH);

#pragma unroll
        for (int kk = 0; kk < 2; kk++) {
            uint32_t a[4][4], b[4][4];
#pragma unroll
            for (int mi = 0; mi < 4; mi++) {
                int m = wm * 64 + mi * 16 + (lane & 15);
                ldm4(a[mi], baseA + (uint32_t)(m * LDSS + kk * 16 + (lane >> 4) * 8) * 2);
            }
#pragma unroll
            for (int nb = 0; nb < 4; nb++) {
                int n = wn * 64 + nb * 16 + ((lane >> 4) << 3) + (lane & 7);
                ldm4(b[nb], baseB + (uint32_t)(n * LDSS + kk * 16 + ((lane >> 3) & 1) * 8) * 2);
            }
#pragma unroll
            for (int mi = 0; mi < 4; mi++)
#pragma unroll
                for (int nb = 0; nb < 4; nb++) {
                    mma16816(acc[mi][nb * 2], a[mi], b[nb][0], b[nb][1]);
                    mma16816(acc[mi][nb * 2 + 1], a[mi], b[nb][2], b[nb][3]);
                }
        }
    }

    // ---------------- epilogue ----------------
    if (EPI == 3 && n0 == 0) {
        // fused q softmax over 16-col groups (+bias, *1/32), write fp16 to E0
#pragma unroll
        for (int mi = 0; mi < 4; mi++) {
            int rc0 = m0 + wm * 64 + mi * 16 + (lane >> 2);
#pragma unroll
            for (int nb = 0; nb < 8; nb += 2) {
                int e0 = wn * 64 + nb * 8 + (lane & 3) * 2;
                float b0 = bias[e0], b1 = bias[e0 + 1];
                float b2 = bias[e0 + 8], b3 = bias[e0 + 9];
                float r0[4] = {acc[mi][nb][0] + b0, acc[mi][nb][1] + b1,
                               acc[mi][nb + 1][0] + b2, acc[mi][nb + 1][1] + b3};
                float r1[4] = {acc[mi][nb][2] + b0, acc[mi][nb][3] + b1,
                               acc[mi][nb + 1][2] + b2, acc[mi][nb + 1][3] + b3};
                float mx0 = fmaxf(fmaxf(r0[0], r0[1]), fmaxf(r0[2], r0[3]));
                float mx1 = fmaxf(fmaxf(r1[0], r1[1]), fmaxf(r1[2], r1[3]));
                mx0 = fmaxf(mx0, __shfl_xor_sync(0xffffffffu, mx0, 1));
                mx0 = fmaxf(mx0, __shfl_xor_sync(0xffffffffu, mx0, 2));
                mx1 = fmaxf(mx1, __shfl_xor_sync(0xffffffffu, mx1, 1));
                mx1 = fmaxf(mx1, __shfl_xor_sync(0xffffffffu, mx1, 2));
                float s0 = 0.f, s1 = 0.f;
#pragma unroll
                for (int q = 0; q < 4; q++) { r0[q] = __expf(r0[q] - mx0); s0 += r0[q]; }
#pragma unroll
                for (int q = 0; q < 4; q++) { r1[q] = __expf(r1[q] - mx1); s1 += r1[q]; }
                s0 += __shfl_xor_sync(0xffffffffu, s0, 1);
                s0 += __shfl_xor_sync(0xffffffffu, s0, 2);
                s1 += __shfl_xor_sync(0xffffffffu, s1, 1);
                s1 += __shfl_xor_sync(0xffffffffu, s1, 2);
                float sc0 = 0.03125f / s0, sc1 = 0.03125f / s1;

                int hh = e0 >> 4, jj = e0 & 15;
#pragma unroll
                for (int rr2 = 0; rr2 < 2; rr2++) {
                    int rc = rc0 + rr2 * 8;
                    int r = rc >> 11, c = rc & (CC - 1);
                    float* vv = rr2 ? r1 : r0;
                    float sc = rr2 ? sc1 : sc0;
                    hf* dst = E0 + ((size_t)hh * CC + c) * DD + (r << 4) + jj;
                    *(__half2*)dst = __floats2half2_rn(vv[0] * sc, vv[1] * sc);
                    *(__half2*)(dst + 8) = __floats2half2_rn(vv[2] * sc, vv[3] * sc);
                }
            }
        }
        return;
    }

    hf* dst3 = nullptr;
    if (EPI == 3) dst3 = (n0 == 128) ? E1 : E2;
#pragma unroll
    for (int mi = 0; mi < 4; mi++) {
#pragma unroll
        for (int ni = 0; ni < 8; ni++) {
            int grow = m0 + wm * 64 + mi * 16 + (lane >> 2);
            int gcol = n0 + wn * 64 + ni * 8 + (lane & 3) * 2;
            float v0 = acc[mi][ni][0], v1 = acc[mi][ni][1];
            float v2 = acc[mi][ni][2], v3 = acc[mi][ni][3];

            if (EPI == 0) {          // attn fp32 row-major
                float* base = C0 + (size_t)h * sCh;
                *(float2*)&base[(size_t)grow * ldc + gcol] = make_float2(v0, v1);
                *(float2*)&base[(size_t)(grow + 8) * ldc + gcol] = make_float2(v2, v3);
            } else if (EPI == 1) {   // ctx fp16
                hf* bh = E0 + (size_t)h * sCh;
                *(__half2*)&bh[(size_t)grow * ldc + gcol] = __floats2half2_rn(v0, v1);
                *(__half2*)&bh[(size_t)(grow + 8) * ldc + gcol] = __floats2half2_rn(v2, v3);
            } else if (EPI == 2) {   // out scatter: col=r*16+j, row=c
                int r = gcol >> 4, j = gcol & 15;
#pragma unroll
                for (int rr2 = 0; rr2 < 2; rr2++) {
                    int c = grow + rr2 * 8;
                    float a0 = rr2 ? v2 : v0, a1 = rr2 ? v3 : v1;
                    *(float2*)&C0[(((size_t)r * CC + c) << 7) + h * HDIM + j] =
                        make_float2(a0, a1);
                }
            } else {                 // proj K/V fp16 scatter (+bias)
                int e = gcol & 127;
                int hh = e >> 4, jj = e & 15;
                float b0 = bias[gcol], b1 = bias[gcol + 1];
#pragma unroll
                for (int rr2 = 0; rr2 < 2; rr2++) {
                    int rc = grow + rr2 * 8;
                    int r = rc >> 11, c = rc & (CC - 1);
                    float a0 = (rr2 ? v2 : v0) + b0, a1 = (rr2 ? v3 : v1) + b1;
                    *(__half2*)&dst3[((size_t)hh * CC + c) * DD + (r << 4) + jj] =
                        __floats2half2_rn(a0, a1);
                }
            }
        }
    }
}

// ---------------------------------------------------------------------------
// elementwise kernels
// ---------------------------------------------------------------------------
__global__ __launch_bounds__(256) void cvt_kernel(const float* __restrict__ src,
                                                  hf* __restrict__ dst, int n4) {
    int i = blockIdx.x * 256 + threadIdx.x;
    if (i >= n4) return;
    float4 v = *(const float4*)(src + i * 4);
    __half2 h0 = __floats2half2_rn(v.x, v.y);
    __half2 h1 = __floats2half2_rn(v.z, v.w);
    *(__half2*)(dst + i * 4) = h0;
    *(__half2*)(dst + i * 4 + 2) = h1;
}

__global__ void pack_bias_kernel(const float* bq, const float* bk, const float* bv) {
    int i = threadIdx.x;  // 384
    float v = (i < 128) ? bq[i] : (i < 256) ? bk[i - 128] : bv[i - 256];
    g_ball[i] = v;
}

__global__ __launch_bounds__(256) void ksum_kernel() {
    int h = blockIdx.y;
    int d = blockIdx.x * 256 + threadIdx.x;
    const hf* base = g_Klog + (size_t)h * CC * DD + d;
    float s = 0.f;
    for (int n = 0; n < CC; n++) s += __expf(__half2float(base[(size_t)n * DD]));
    g_ksum[h * DD + d] = s;
}

// transpose fp16 -> fp16; KMODE applies exp()*inv(colsum) and writes direct copy too
template <bool KMODE>
__global__ __launch_bounds__(256) void trans_kernel(const hf* __restrict__ src,
                                                    hf* __restrict__ dir,
                                                    hf* __restrict__ dth) {
    __shared__ float t[32][33];
    int h = blockIdx.z;
    int d0 = blockIdx.x * 32, n0 = blockIdx.y * 32;
    int tx = threadIdx.x, ty = threadIdx.y;
    const hf* sp = src + (size_t)h * CC * DD;

    float inv = 0.f;
    if (KMODE) inv = 1.0f / g_ksum[h * DD + d0 + tx];

#pragma unroll
    for (int i = 0; i < 4; i++) {
        int n = n0 + ty + i * 8;
        float v = __half2float(sp[(size_t)n * DD + d0 + tx]);
        if (KMODE) {
            v = __expf(v) * inv;
            dir[(size_t)h * CC * DD + (size_t)n * DD + d0 + tx] = __float2half_rn(v);
        }
        t[ty + i * 8][tx] = v;
    }
    __syncthreads();
#pragma unroll
    for (int i = 0; i < 4; i++) {
        int dl = ty + i * 8;
        dth[(size_t)h * DD * CC + (size_t)(d0 + dl) * CC + n0 + tx] =
            __float2half_rn(t[tx][dl]);
    }
}

// ---------------------------------------------------------------------------
// launch
// ---------------------------------------------------------------------------
extern "C" void kernel_launch(void* const* d_in, const int* in_sizes, int n_in,
                              void* d_out, int out_size) {
    const float* x  = (const float*)d_in[0];
    const float* Wq = (const float*)d_in[1];
    const float* bq = (const float*)d_in[2];
    const float* Wk = (const float*)d_in[3];
    const float* bk = (const float*)d_in[4];
    const float* Wv = (const float*)d_in[5];
    const float* bv = (const float*)d_in[6];
    float* out = (float*)d_out;

    float* pball;
    hf *pxh, *pWh, *pQh, *pKlog, *pVh, *pKh, *pKTh, *pVTh, *pCTh;
    cudaGetSymbolAddress((void**)&pball, g_ball);
    cudaGetSymbolAddress((void**)&pxh, g_xh);
    cudaGetSymbolAddress((void**)&pWh, g_Wallh);
    cudaGetSymbolAddress((void**)&pQh, g_Qh);
    cudaGetSymbolAddress((void**)&pKlog, g_Klog);
    cudaGetSymbolAddress((void**)&pVh, g_Vh);
    cudaGetSymbolAddress((void**)&pKh, g_Kh);
    cudaGetSymbolAddress((void**)&pKTh, g_KTh);
    cudaGetSymbolAddress((void**)&pVTh, g_VTh);
    cudaGetSymbolAddress((void**)&pCTh, g_CTh);

    const int STB = (BM + BN) * LDSS * 2;   // 30720 bytes per stage
    cudaFuncSetAttribute(tc_gemm<3, 3>, cudaFuncAttributeMaxDynamicSharedMemorySize, 3 * STB);
    cudaFuncSetAttribute(tc_gemm<0, 4>, cudaFuncAttributeMaxDynamicSharedMemorySize, 4 * STB);
    cudaFuncSetAttribute(tc_gemm<1, 4>, cudaFuncAttributeMaxDynamicSharedMemorySize, 4 * STB);
    cudaFuncSetAttribute(tc_gemm<2, 4>, cudaFuncAttributeMaxDynamicSharedMemorySize, 4 * STB);

    dim3 t256(256);

    // 1) fp16 conversions + bias pack
    cvt_kernel<<<(RR * CC * EE / 4 + 255) / 256, t256>>>(x, pxh, RR * CC * EE / 4);
    cvt_kernel<<<(EE * EE / 4 + 255) / 256, t256>>>(Wq, pWh, EE * EE / 4);
    cvt_kernel<<<(EE * EE / 4 + 255) / 256, t256>>>(Wk, pWh + EE * EE, EE * EE / 4);
    cvt_kernel<<<(EE * EE / 4 + 255) / 256, t256>>>(Wv, pWh + 2 * EE * EE, EE * EE / 4);
    pack_bias_kernel<<<1, 384>>>(bq, bk, bv);

    // 2) fused projection: M=131072, N=384, K=128; q softmax fused for N-block 0
    tc_gemm<3, 3><<<dim3(3, (RR * CC) / BM, 1), t256, 3 * STB>>>(
        pxh, pWh, nullptr, pQh, pKlog, pVh,
        pball, EE, EE, EE, 0, 0, 0, 0);

    // 3) k softmax + transposes
    ksum_kernel<<<dim3(DD / 256, HH), t256>>>();
    trans_kernel<true><<<dim3(DD / 32, CC / 32, HH), dim3(32, 8)>>>(pKlog, pKh, pKTh);
    trans_kernel<false><<<dim3(DD / 32, CC / 32, HH), dim3(32, 8)>>>(pVh, nullptr, pVTh);

    // 4) attn[h][n][m] = sum_d Qh[n][d] Kh[m][d]  -> out + RR*CC*EE
    tc_gemm<0, 4><<<dim3(CC / BN, CC / BM, HH), t256, 4 * STB>>>(
        pQh, pKh, out + (size_t)RR * CC * EE, nullptr, nullptr, nullptr,
        nullptr, DD, DD, DD, CC,
        (size_t)CC * DD, (size_t)CC * DD, (size_t)CC * CC);

    // 5) ctxT[e][d] = sum_n VT[e][n] KT[d][n]  -> g_CTh (fp16)
    tc_gemm<1, 4><<<dim3(DD / BN, DD / BM, HH), t256, 4 * STB>>>(
        pVTh, pKTh, nullptr, pCTh, nullptr, nullptr,
        nullptr, CC, CC, CC, DD,
        (size_t)DD * CC, (size_t)DD * CC, (size_t)DD * DD);

    // 6) out[c][col] = sum_d Q[c][d] ctxT[col][d]  (scatter epilogue)
    tc_gemm<2, 4><<<dim3(DD / BN, CC / BM, HH), t256, 4 * STB>>>(
        pQh, pCTh, out, nullptr, nullptr, nullptr,
        nullptr, DD, DD, DD, 0,
        (size_t)CC * DD, (size_t)DD * DD, 0);
}

// round 7
// speedup vs baseline: 6.1095x; 1.1533x over previous
#include <cuda_runtime.h>
#include <cuda_fp16.h>
#include <cstdint>

// Gene Linear Attention — fp16 mma.sync pipeline v5.
// Pair-chunk S=6 cp.async pipeline (half the barriers), attn+ctx packed in one
// launch (ctx long CTAs first), prep/trans launches merged. Numerics identical to v4.

#define RR   64
#define CC   2048
#define EE   128
#define HH   8
#define HDIM 16
#define DD   1024   // RR*HDIM

typedef __half hf;

// ---------------- device global scratch ----------------
__device__ float g_ksum[HH * DD];
__device__ float g_ball[3 * EE];

__device__ hf g_xh[RR * CC * EE];
__device__ hf g_Wallh[3 * EE * EE];     // Wq|Wk|Wv stacked rows

__device__ hf g_Qh[HH * CC * DD];       // softmaxed+scaled q [h][c][d]
__device__ hf g_Klog[HH * CC * DD];     // k logits fp16 [h][c][d]
__device__ hf g_Vh[HH * CC * DD];       // v fp16 [h][c][d]
__device__ hf g_Kh[HH * CC * DD];       // softmaxed k [h][n][d]
__device__ hf g_KTh[HH * DD * CC];      // softmaxed k transposed [h][d][n]
__device__ hf g_VTh[HH * DD * CC];      // v transposed [h][e][n]
__device__ hf g_CTh[HH * DD * DD];      // ctxT [h][col][d]

// ---------------- PTX helpers ----------------
__device__ __forceinline__ uint32_t cvta(const void* p) {
    return (uint32_t)__cvta_generic_to_shared(p);
}
__device__ __forceinline__ void cp16(uint32_t dst, const void* src) {
    asm volatile("cp.async.cg.shared.global [%0], [%1], 16;\n" :: "r"(dst), "l"(src));
}
#define CP_COMMIT() asm volatile("cp.async.commit_group;\n" ::)

__device__ __forceinline__ void ldm4(uint32_t (&a)[4], uint32_t addr) {
    asm volatile("ldmatrix.sync.aligned.m8n8.x4.shared.b16 {%0,%1,%2,%3}, [%4];"
                 : "=r"(a[0]), "=r"(a[1]), "=r"(a[2]), "=r"(a[3]) : "r"(addr));
}
__device__ __forceinline__ void mma16816(float (&c)[4], const uint32_t (&a)[4],
                                         const uint32_t b0, const uint32_t b1) {
    asm volatile(
        "mma.sync.aligned.m16n8k16.row.col.f32.f16.f16.f32 "
        "{%0,%1,%2,%3}, {%4,%5,%6,%7}, {%8,%9}, {%0,%1,%2,%3};"
        : "+f"(c[0]), "+f"(c[1]), "+f"(c[2]), "+f"(c[3])
        : "r"(a[0]), "r"(a[1]), "r"(a[2]), "r"(a[3]), "r"(b0), "r"(b1));
}

// ---------------------------------------------------------------------------
// Shared NT-GEMM mainloop: CTA 256x128, warps 4x2 (64x64 each), BK=32, S=6,
// pair-chunk: one wait_group+barrier per TWO K-chunks. Requires nk even, >=4.
// ---------------------------------------------------------------------------
#define BM 256
#define BN 128
#define BK 32
#define LDSS 40                      // half stride (32 + 8 pad)
#define OFF_BH (BM * LDSS)
#define GSTAGE ((BM + BN) * LDSS)    // halfs per stage
#define NSTAGE 6
#define SMEM_BYTES (NSTAGE * GSTAGE * 2)   // 184320

__device__ __forceinline__ void gemm_mainloop(
    const hf* __restrict__ pA, const hf* __restrict__ pB,
    int ldA, int ldB, int Kdim, int m0, int n0,
    hf* smem, int tid, int lane, int wm, int wn,
    float (&acc)[4][8][4])
{
    auto load_stage = [&](int st, int k0) {
        hf* s = smem + st * GSTAGE;
#pragma unroll
        for (int t = 0; t < 4; t++) {
            int slot = tid + t * 256;
            int r = slot >> 2, seg = slot & 3;
            cp16(cvta(s + r * LDSS + seg * 8), pA + (size_t)(m0 + r) * ldA + k0 + seg * 8);
        }
#pragma unroll
        for (int t = 0; t < 2; t++) {
            int slot = tid + t * 256;
            int r = slot >> 2, seg = slot & 3;
            cp16(cvta(s + OFF_BH + r * LDSS + seg * 8), pB + (size_t)(n0 + r) * ldB + k0 + seg * 8);
        }
    };
    auto compute_stage = [&](int st) {
        const hf* s = smem + st * GSTAGE;
        const uint32_t baseA = cvta(s);
        const uint32_t baseB = cvta(s + OFF_BH);
#pragma unroll
        for (int kk = 0; kk < 2; kk++) {
            uint32_t a[4][4], b[4][4];
#pragma unroll
            for (int mi = 0; mi < 4; mi++) {
                int m = wm * 64 + mi * 16 + (lane & 15);
                ldm4(a[mi], baseA + (uint32_t)(m * LDSS + kk * 16 + (lane >> 4) * 8) * 2);
            }
#pragma unroll
            for (int nb = 0; nb < 4; nb++) {
                int n = wn * 64 + nb * 16 + ((lane >> 4) << 3) + (lane & 7);
                ldm4(b[nb], baseB + (uint32_t)(n * LDSS + kk * 16 + ((lane >> 3) & 1) * 8) * 2);
            }
#pragma unroll
            for (int mi = 0; mi < 4; mi++)
#pragma unroll
                for (int nb = 0; nb < 4; nb++) {
                    mma16816(acc[mi][nb * 2], a[mi], b[nb][0], b[nb][1]);
                    mma16816(acc[mi][nb * 2 + 1], a[mi], b[nb][2], b[nb][3]);
                }
        }
    };

    const int nk = Kdim / BK;   // 4 (proj), 32 (attn/out), 64 (ctx)
#pragma unroll 1
    for (int s = 0; s < 4; s++) { if (s < nk) load_stage(s, s * BK); CP_COMMIT(); }
#pragma unroll 1
    for (int p = 0; p < nk; p += 2) {
        asm volatile("cp.async.wait_group 2;\n" ::);
        __syncthreads();
        compute_stage(p % NSTAGE);
        if (p + 4 < nk) load_stage((p + 4) % NSTAGE, (p + 4) * BK);
        CP_COMMIT();
        compute_stage((p + 1) % NSTAGE);
        if (p + 5 < nk) load_stage((p + 5) % NSTAGE, (p + 5) * BK);
        CP_COMMIT();
    }
}

// ---------------------------------------------------------------------------
// proj kernel: M=131072, N=384 (3 x-blocks), K=128. Fused q softmax on block 0.
// ---------------------------------------------------------------------------
__global__ __launch_bounds__(256, 1) void proj_kernel() {
    extern __shared__ __align__(16) hf smem[];
    const int tid = threadIdx.x, lane = tid & 31, warp = tid >> 5;
    const int wm = warp >> 1, wn = warp & 1;
    const int m0 = blockIdx.y * BM, n0 = blockIdx.x * BN;

    float acc[4][8][4];
#pragma unroll
    for (int i = 0; i < 4; i++)
#pragma unroll
        for (int j = 0; j < 8; j++)
#pragma unroll
            for (int q = 0; q < 4; q++) acc[i][j][q] = 0.f;

    gemm_mainloop(g_xh, g_Wallh, EE, EE, EE, m0, n0, smem, tid, lane, wm, wn, acc);

    const float* bias = g_ball;
    if (n0 == 0) {
        // q path: fused 16-group softmax (+bias, *1/32) -> g_Qh fp16
#pragma unroll
        for (int mi = 0; mi < 4; mi++) {
            int rc0 = m0 + wm * 64 + mi * 16 + (lane >> 2);
#pragma unroll
            for (int nb = 0; nb < 8; nb += 2) {
                int e0 = wn * 64 + nb * 8 + (lane & 3) * 2;
                float b0 = bias[e0], b1 = bias[e0 + 1];
                float b2 = bias[e0 + 8], b3 = bias[e0 + 9];
                float r0[4] = {acc[mi][nb][0] + b0, acc[mi][nb][1] + b1,
                               acc[mi][nb + 1][0] + b2, acc[mi][nb + 1][1] + b3};
                float r1[4] = {acc[mi][nb][2] + b0, acc[mi][nb][3] + b1,
                               acc[mi][nb + 1][2] + b2, acc[mi][nb + 1][3] + b3};
                float mx0 = fmaxf(fmaxf(r0[0], r0[1]), fmaxf(r0[2], r0[3]));
                float mx1 = fmaxf(fmaxf(r1[0], r1[1]), fmaxf(r1[2], r1[3]));
                mx0 = fmaxf(mx0, __shfl_xor_sync(0xffffffffu, mx0, 1));
                mx0 = fmaxf(mx0, __shfl_xor_sync(0xffffffffu, mx0, 2));
                mx1 = fmaxf(mx1, __shfl_xor_sync(0xffffffffu, mx1, 1));
                mx1 = fmaxf(mx1, __shfl_xor_sync(0xffffffffu, mx1, 2));
                float s0 = 0.f, s1 = 0.f;
#pragma unroll
                for (int q = 0; q < 4; q++) { r0[q] = __expf(r0[q] - mx0); s0 += r0[q]; }
#pragma unroll
                for (int q = 0; q < 4; q++) { r1[q] = __expf(r1[q] - mx1); s1 += r1[q]; }
                s0 += __shfl_xor_sync(0xffffffffu, s0, 1);
                s0 += __shfl_xor_sync(0xffffffffu, s0, 2);
                s1 += __shfl_xor_sync(0xffffffffu, s1, 1);
                s1 += __shfl_xor_sync(0xffffffffu, s1, 2);
                float sc0 = 0.03125f / s0, sc1 = 0.03125f / s1;

                int hh = e0 >> 4, jj = e0 & 15;
#pragma unroll
                for (int rr2 = 0; rr2 < 2; rr2++) {
                    int rc = rc0 + rr2 * 8;
                    int r = rc >> 11, c = rc & (CC - 1);
                    float* vv = rr2 ? r1 : r0;
                    float sc = rr2 ? sc1 : sc0;
                    hf* dst = g_Qh + ((size_t)hh * CC + c) * DD + (r << 4) + jj;
                    *(__half2*)dst = __floats2half2_rn(vv[0] * sc, vv[1] * sc);
                    *(__half2*)(dst + 8) = __floats2half2_rn(vv[2] * sc, vv[3] * sc);
                }
            }
        }
        return;
    }

    hf* dst3 = (n0 == 128) ? g_Klog : g_Vh;
#pragma unroll
    for (int mi = 0; mi < 4; mi++) {
#pragma unroll
        for (int ni = 0; ni < 8; ni++) {
            int grow = m0 + wm * 64 + mi * 16 + (lane >> 2);
            int gcol = n0 + wn * 64 + ni * 8 + (lane & 3) * 2;
            float v0 = acc[mi][ni][0], v1 = acc[mi][ni][1];
            float v2 = acc[mi][ni][2], v3 = acc[mi][ni][3];
            int e = gcol & 127;
            int hh = e >> 4, jj = e & 15;
            float b0 = bias[gcol], b1 = bias[gcol + 1];
#pragma unroll
            for (int rr2 = 0; rr2 < 2; rr2++) {
                int rc = grow + rr2 * 8;
                int r = rc >> 11, c = rc & (CC - 1);
                float a0 = (rr2 ? v2 : v0) + b0, a1 = (rr2 ? v3 : v1) + b1;
                *(__half2*)&dst3[((size_t)hh * CC + c) * DD + (r << 4) + jj] =
                    __floats2half2_rn(a0, a1);
            }
        }
    }
}

// ---------------------------------------------------------------------------
// merged attn + ctx kernel. blockIdx.x in [0,1280):
//   [0,256):   ctx  — ctxT[e][d] = sum_n VT[e][n] KT[d][n]  (long CTAs, scheduled first)
//   [256,1280): attn — attn[n][m] = sum_d Qh[n][d] Kh[m][d]
// ---------------------------------------------------------------------------
__global__ __launch_bounds__(256, 1) void attnctx_kernel(float* __restrict__ attn_out) {
    extern __shared__ __align__(16) hf smem[];
    const int tid = threadIdx.x, lane = tid & 31, warp = tid >> 5;
    const int wm = warp >> 1, wn = warp & 1;
    const int id = blockIdx.x;

    float acc[4][8][4];
#pragma unroll
    for (int i = 0; i < 4; i++)
#pragma unroll
        for (int j = 0; j < 8; j++)
#pragma unroll
            for (int q = 0; q < 4; q++) acc[i][j][q] = 0.f;

    if (id < 256) {
        // ctx: per head 4 x 8 blocks (DD/BM x DD/BN)
        int z = id >> 5, by = (id >> 3) & 3, bx = id & 7;
        int m0 = by * BM, n0 = bx * BN;
        gemm_mainloop(g_VTh + (size_t)z * DD * CC, g_KTh + (size_t)z * DD * CC,
                      CC, CC, CC, m0, n0, smem, tid, lane, wm, wn, acc);
        hf* bh = g_CTh + (size_t)z * DD * DD;
#pragma unroll
        for (int mi = 0; mi < 4; mi++)
#pragma unroll
            for (int ni = 0; ni < 8; ni++) {
                int grow = m0 + wm * 64 + mi * 16 + (lane >> 2);
                int gcol = n0 + wn * 64 + ni * 8 + (lane & 3) * 2;
                *(__half2*)&bh[(size_t)grow * DD + gcol] =
                    __floats2half2_rn(acc[mi][ni][0], acc[mi][ni][1]);
                *(__half2*)&bh[(size_t)(grow + 8) * DD + gcol] =
                    __floats2half2_rn(acc[mi][ni][2], acc[mi][ni][3]);
            }
    } else {
        // attn: per head 8 x 16 blocks (CC/BM x CC/BN)
        int id2 = id - 256;
        int z = id2 >> 7, by = (id2 >> 4) & 7, bx = id2 & 15;
        int m0 = by * BM, n0 = bx * BN;
        gemm_mainloop(g_Qh + (size_t)z * CC * DD, g_Kh + (size_t)z * CC * DD,
                      DD, DD, DD, m0, n0, smem, tid, lane, wm, wn, acc);
        float* base = attn_out + (size_t)z * CC * CC;
#pragma unroll
        for (int mi = 0; mi < 4; mi++)
#pragma unroll
            for (int ni = 0; ni < 8; ni++) {
                int grow = m0 + wm * 64 + mi * 16 + (lane >> 2);
                int gcol = n0 + wn * 64 + ni * 8 + (lane & 3) * 2;
                *(float2*)&base[(size_t)grow * CC + gcol] =
                    make_float2(acc[mi][ni][0], acc[mi][ni][1]);
                *(float2*)&base[(size_t)(grow + 8) * CC + gcol] =
                    make_float2(acc[mi][ni][2], acc[mi][ni][3]);
            }
    }
}

// ---------------------------------------------------------------------------
// out kernel: out[c][col] = sum_d Qh[c][d] CTh[col][d], scatter epilogue
// ---------------------------------------------------------------------------
__global__ __launch_bounds__(256, 1) void out_kernel(float* __restrict__ out) {
    extern __shared__ __align__(16) hf smem[];
    const int tid = threadIdx.x, lane = tid & 31, warp = tid >> 5;
    const int wm = warp >> 1, wn = warp & 1;
    const int h = blockIdx.z;
    const int m0 = blockIdx.y * BM, n0 = blockIdx.x * BN;

    float acc[4][8][4];
#pragma unroll
    for (int i = 0; i < 4; i++)
#pragma unroll
        for (int j = 0; j < 8; j++)
#pragma unroll
            for (int q = 0; q < 4; q++) acc[i][j][q] = 0.f;

    gemm_mainloop(g_Qh + (size_t)h * CC * DD, g_CTh + (size_t)h * DD * DD,
                  DD, DD, DD, m0, n0, smem, tid, lane, wm, wn, acc);

#pragma unroll
    for (int mi = 0; mi < 4; mi++)
#pragma unroll
        for (int ni = 0; ni < 8; ni++) {
            int grow = m0 + wm * 64 + mi * 16 + (lane >> 2);
            int gcol = n0 + wn * 64 + ni * 8 + (lane & 3) * 2;
            int r = gcol >> 4, j = gcol & 15;
#pragma unroll
            for (int rr2 = 0; rr2 < 2; rr2++) {
                int c = grow + rr2 * 8;
                float a0 = rr2 ? acc[mi][ni][2] : acc[mi][ni][0];
                float a1 = rr2 ? acc[mi][ni][3] : acc[mi][ni][1];
                *(float2*)&out[(((size_t)r * CC + c) << 7) + h * HDIM + j] =
                    make_float2(a0, a1);
            }
        }
}

// ---------------------------------------------------------------------------
// merged prep: x->fp16 (16384 blocks), W->fp16 (48), bias pack (2)
// ---------------------------------------------------------------------------
__global__ __launch_bounds__(256) void prep_kernel(
    const float* __restrict__ x, const float* __restrict__ Wq,
    const float* __restrict__ Wk, const float* __restrict__ Wv,
    const float* __restrict__ bq, const float* __restrict__ bk,
    const float* __restrict__ bv) {
    int b = blockIdx.x, tid = threadIdx.x;
    if (b < 16384) {
        int i = b * 256 + tid;                      // quad index
        float4 v = *(const float4*)(x + (size_t)i * 4);
        *(__half2*)(g_xh + (size_t)i * 4) = __floats2half2_rn(v.x, v.y);
        *(__half2*)(g_xh + (size_t)i * 4 + 2) = __floats2half2_rn(v.z, v.w);
    } else if (b < 16432) {
        int q = (b - 16384) * 256 + tid;            // quad into 3*EE*EE
        int w = q >> 12, j = q & 4095;
        const float* W = (w == 0) ? Wq : (w == 1) ? Wk : Wv;
        float4 v = *(const float4*)(W + j * 4);
        hf* dst = g_Wallh + w * EE * EE + j * 4;
        *(__half2*)dst = __floats2half2_rn(v.x, v.y);
        *(__half2*)(dst + 2) = __floats2half2_rn(v.z, v.w);
    } else {
        int i = (b - 16432) * 256 + tid;
        if (i < 384)
            g_ball[i] = (i < 128) ? bq[i] : (i < 256) ? bk[i - 128] : bv[i - 256];
    }
}

__global__ __launch_bounds__(256) void ksum_kernel() {
    int h = blockIdx.y;
    int d = blockIdx.x * 256 + threadIdx.x;
    const hf* base = g_Klog + (size_t)h * CC * DD + d;
    float s = 0.f;
    for (int n = 0; n < CC; n++) s += __expf(__half2float(base[(size_t)n * DD]));
    g_ksum[h * DD + d] = s;
}

// merged transpose: z<8 -> K mode (exp*inv + direct write), z>=8 -> V mode
__global__ __launch_bounds__(256) void trans_kernel() {
    __shared__ float t[32][33];
    int zz = blockIdx.z;
    bool KM = zz < HH;
    int h = KM ? zz : zz - HH;
    int d0 = blockIdx.x * 32, n0 = blockIdx.y * 32;
    int tx = threadIdx.x, ty = threadIdx.y;
    const hf* sp = (KM ? g_Klog : g_Vh) + (size_t)h * CC * DD;
    hf* dth = (KM ? g_KTh : g_VTh) + (size_t)h * DD * CC;

    float inv = 0.f;
    if (KM) inv = 1.0f / g_ksum[h * DD + d0 + tx];

#pragma unroll
    for (int i = 0; i < 4; i++) {
        int n = n0 + ty + i * 8;
        float v = __half2float(sp[(size_t)n * DD + d0 + tx]);
        if (KM) {
            v = __expf(v) * inv;
            g_Kh[(size_t)h * CC * DD + (size_t)n * DD + d0 + tx] = __float2half_rn(v);
        }
        t[ty + i * 8][tx] = v;
    }
    __syncthreads();
#pragma unroll
    for (int i = 0; i < 4; i++) {
        int dl = ty + i * 8;
        dth[(size_t)(d0 + dl) * CC + n0 + tx] = __float2half_rn(t[tx][dl]);
    }
}

// ---------------------------------------------------------------------------
// launch
// ---------------------------------------------------------------------------
extern "C" void kernel_launch(void* const* d_in, const int* in_sizes, int n_in,
                              void* d_out, int out_size) {
    const float* x  = (const float*)d_in[0];
    const float* Wq = (const float*)d_in[1];
    const float* bq = (const float*)d_in[2];
    const float* Wk = (const float*)d_in[3];
    const float* bk = (const float*)d_in[4];
    const float* Wv = (const float*)d_in[5];
    const float* bv = (const float*)d_in[6];
    float* out = (float*)d_out;

    cudaFuncSetAttribute(proj_kernel, cudaFuncAttributeMaxDynamicSharedMemorySize, SMEM_BYTES);
    cudaFuncSetAttribute(attnctx_kernel, cudaFuncAttributeMaxDynamicSharedMemorySize, SMEM_BYTES);
    cudaFuncSetAttribute(out_kernel, cudaFuncAttributeMaxDynamicSharedMemorySize, SMEM_BYTES);

    dim3 t256(256);

    // 1) prep: x/W fp16 conversion + bias pack (16434 blocks)
    prep_kernel<<<16434, t256>>>(x, Wq, Wk, Wv, bq, bk, bv);

    // 2) fused projection: grid (3 N-blocks, 512 M-blocks)
    proj_kernel<<<dim3(3, (RR * CC) / BM, 1), t256, SMEM_BYTES>>>();

    // 3) k softmax denominators + merged transposes
    ksum_kernel<<<dim3(DD / 256, HH), t256>>>();
    trans_kernel<<<dim3(DD / 32, CC / 32, 2 * HH), dim3(32, 8)>>>();

    // 4) merged ctx (256 CTAs, first) + attn (1024 CTAs)
    attnctx_kernel<<<1280, t256, SMEM_BYTES>>>(out + (size_t)RR * CC * EE);

    // 5) out GEMM with scatter epilogue
    out_kernel<<<dim3(DD / BN, CC / BM, HH), t256, SMEM_BYTES>>>(out);
}

// round 8
// speedup vs baseline: 7.2590x; 1.1881x over previous
#include <cuda_runtime.h>
#include <cuda_fp16.h>
#include <cstdint>

// Gene Linear Attention — fp16 mma.sync pipeline v6.
// Transposes eliminated: ctx runs as TN GEMM (ldmatrix.trans) on Vh/Kh directly.
// prep -> proj(fused q softmax) -> ksum(coalesced) -> inv -> ksoft -> attn+ctx -> out

#define RR   64
#define CC   2048
#define EE   128
#define HH   8
#define HDIM 16
#define DD   1024   // RR*HDIM

typedef __half hf;

// ---------------- device global scratch ----------------
__device__ float g_ksum[HH * DD];
__device__ float g_ball[3 * EE];

__device__ hf g_xh[RR * CC * EE];
__device__ hf g_Wallh[3 * EE * EE];     // Wq|Wk|Wv stacked rows

__device__ hf g_Qh[HH * CC * DD];       // softmaxed+scaled q [h][c][d]
__device__ hf g_Klog[HH * CC * DD];     // k logits fp16 [h][n][d]
__device__ hf g_Vh[HH * CC * DD];       // v fp16 [h][n][e]
__device__ hf g_Kh[HH * CC * DD];       // softmaxed k [h][n][d]
__device__ hf g_CTh[HH * DD * DD];      // ctxT [h][col=e][d]

// ---------------- PTX helpers ----------------
__device__ __forceinline__ uint32_t cvta(const void* p) {
    return (uint32_t)__cvta_generic_to_shared(p);
}
__device__ __forceinline__ void cp16(uint32_t dst, const void* src) {
    asm volatile("cp.async.cg.shared.global [%0], [%1], 16;\n" :: "r"(dst), "l"(src));
}
#define CP_COMMIT() asm volatile("cp.async.commit_group;\n" ::)

__device__ __forceinline__ void ldm4(uint32_t (&a)[4], uint32_t addr) {
    asm volatile("ldmatrix.sync.aligned.m8n8.x4.shared.b16 {%0,%1,%2,%3}, [%4];"
                 : "=r"(a[0]), "=r"(a[1]), "=r"(a[2]), "=r"(a[3]) : "r"(addr));
}
__device__ __forceinline__ void ldm4t(uint32_t (&a)[4], uint32_t addr) {
    asm volatile("ldmatrix.sync.aligned.m8n8.x4.trans.shared.b16 {%0,%1,%2,%3}, [%4];"
                 : "=r"(a[0]), "=r"(a[1]), "=r"(a[2]), "=r"(a[3]) : "r"(addr));
}
__device__ __forceinline__ void mma16816(float (&c)[4], const uint32_t (&a)[4],
                                         const uint32_t b0, const uint32_t b1) {
    asm volatile(
        "mma.sync.aligned.m16n8k16.row.col.f32.f16.f16.f32 "
        "{%0,%1,%2,%3}, {%4,%5,%6,%7}, {%8,%9}, {%0,%1,%2,%3};"
        : "+f"(c[0]), "+f"(c[1]), "+f"(c[2]), "+f"(c[3])
        : "r"(a[0]), "r"(a[1]), "r"(a[2]), "r"(a[3]), "r"(b0), "r"(b1));
}

// ---------------------------------------------------------------------------
// Tile config: CTA 256x128, warps 4x2 (64x64 each), BK=32, S=6 pair-chunk pipeline
// ---------------------------------------------------------------------------
#define BM 256
#define BN 128
#define BK 32
#define LDSS 40                      // NT half stride (32 + 8 pad)
#define OFF_BH (BM * LDSS)
#define GSTAGE ((BM + BN) * LDSS)    // halfs per stage (NT; TN fits inside)
#define NSTAGE 6
#define SMEM_BYTES (NSTAGE * GSTAGE * 2)   // 184320

// TN layout inside a stage: A tile 32 x 256 (stride 264), B tile 32 x 128 (stride 136)
#define TLDA 264
#define TLDB 136
#define OFF_TB (32 * TLDA)           // 8448 halfs

// ---------------- NT mainloop (A[m][k], B[n][k], k contiguous) ----------------
__device__ __forceinline__ void gemm_nt(
    const hf* __restrict__ pA, const hf* __restrict__ pB,
    int ldA, int ldB, int Kdim, int m0, int n0,
    hf* smem, int tid, int lane, int wm, int wn,
    float (&acc)[4][8][4])
{
    auto load_stage = [&](int st, int k0) {
        hf* s = smem + st * GSTAGE;
#pragma unroll
        for (int t = 0; t < 4; t++) {
            int slot = tid + t * 256;
            int r = slot >> 2, seg = slot & 3;
            cp16(cvta(s + r * LDSS + seg * 8), pA + (size_t)(m0 + r) * ldA + k0 + seg * 8);
        }
#pragma unroll
        for (int t = 0; t < 2; t++) {
            int slot = tid + t * 256;
            int r = slot >> 2, seg = slot & 3;
            cp16(cvta(s + OFF_BH + r * LDSS + seg * 8), pB + (size_t)(n0 + r) * ldB + k0 + seg * 8);
        }
    };
    auto compute_stage = [&](int st) {
        const hf* s = smem + st * GSTAGE;
        const uint32_t baseA = cvta(s);
        const uint32_t baseB = cvta(s + OFF_BH);
#pragma unroll
        for (int kk = 0; kk < 2; kk++) {
            uint32_t a[4][4], b[4][4];
#pragma unroll
            for (int mi = 0; mi < 4; mi++) {
                int m = wm * 64 + mi * 16 + (lane & 15);
                ldm4(a[mi], baseA + (uint32_t)(m * LDSS + kk * 16 + (lane >> 4) * 8) * 2);
            }
#pragma unroll
            for (int nb = 0; nb < 4; nb++) {
                int n = wn * 64 + nb * 16 + ((lane >> 4) << 3) + (lane & 7);
                ldm4(b[nb], baseB + (uint32_t)(n * LDSS + kk * 16 + ((lane >> 3) & 1) * 8) * 2);
            }
#pragma unroll
            for (int mi = 0; mi < 4; mi++)
#pragma unroll
                for (int nb = 0; nb < 4; nb++) {
                    mma16816(acc[mi][nb * 2], a[mi], b[nb][0], b[nb][1]);
                    mma16816(acc[mi][nb * 2 + 1], a[mi], b[nb][2], b[nb][3]);
                }
        }
    };

    const int nk = Kdim / BK;
#pragma unroll 1
    for (int s = 0; s < 4; s++) { if (s < nk) load_stage(s, s * BK); CP_COMMIT(); }
#pragma unroll 1
    for (int p = 0; p < nk; p += 2) {
        asm volatile("cp.async.wait_group 2;\n" ::);
        __syncthreads();
        compute_stage(p % NSTAGE);
        if (p + 4 < nk) load_stage((p + 4) % NSTAGE, (p + 4) * BK);
        CP_COMMIT();
        compute_stage((p + 1) % NSTAGE);
        if (p + 5 < nk) load_stage((p + 5) % NSTAGE, (p + 5) * BK);
        CP_COMMIT();
    }
}

// ---------------- TN mainloop (A[k][m], B[k][n], m/n contiguous; ldmatrix.trans) ----------------
__device__ __forceinline__ void gemm_tn(
    const hf* __restrict__ pA, const hf* __restrict__ pB,
    int ldA, int ldB, int Kdim, int m0, int n0,
    hf* smem, int tid, int lane, int wm, int wn,
    float (&acc)[4][8][4])
{
    auto load_stage = [&](int st, int k0) {
        hf* s = smem + st * GSTAGE;
#pragma unroll
        for (int t = 0; t < 4; t++) {
            int slot = tid + t * 256;             // 1024 slots: 32 rows x 32 segs
            int r = slot >> 5, seg = slot & 31;
            cp16(cvta(s + r * TLDA + seg * 8), pA + (size_t)(k0 + r) * ldA + m0 + seg * 8);
        }
#pragma unroll
        for (int t = 0; t < 2; t++) {
            int slot = tid + t * 256;             // 512 slots: 32 rows x 16 segs
            int r = slot >> 4, seg = slot & 15;
            cp16(cvta(s + OFF_TB + r * TLDB + seg * 8), pB + (size_t)(k0 + r) * ldB + n0 + seg * 8);
        }
    };
    auto compute_stage = [&](int st) {
        const hf* s = smem + st * GSTAGE;
        const uint32_t baseA = cvta(s);
        const uint32_t baseB = cvta(s + OFF_TB);
#pragma unroll
        for (int kk = 0; kk < 2; kk++) {
            uint32_t a[4][4], b[4][4];
            int krA = kk * 16 + (lane & 7) + ((lane >> 4) & 1) * 8;
            int krB = kk * 16 + (lane & 7) + ((lane >> 3) & 1) * 8;
#pragma unroll
            for (int mi = 0; mi < 4; mi++) {
                int m = wm * 64 + mi * 16 + ((lane >> 3) & 1) * 8;
                ldm4t(a[mi], baseA + (uint32_t)(krA * TLDA + m) * 2);
            }
#pragma unroll
            for (int nb = 0; nb < 4; nb++) {
                int n = wn * 64 + nb * 16 + ((lane >> 4) & 1) * 8;
                ldm4t(b[nb], baseB + (uint32_t)(krB * TLDB + n) * 2);
            }
#pragma unroll
            for (int mi = 0; mi < 4; mi++)
#pragma unroll
                for (int nb = 0; nb < 4; nb++) {
                    mma16816(acc[mi][nb * 2], a[mi], b[nb][0], b[nb][1]);
                    mma16816(acc[mi][nb * 2 + 1], a[mi], b[nb][2], b[nb][3]);
                }
        }
    };

    const int nk = Kdim / BK;
#pragma unroll 1
    for (int s = 0; s < 4; s++) { if (s < nk) load_stage(s, s * BK); CP_COMMIT(); }
#pragma unroll 1
    for (int p = 0; p < nk; p += 2) {
        asm volatile("cp.async.wait_group 2;\n" ::);
        __syncthreads();
        compute_stage(p % NSTAGE);
        if (p + 4 < nk) load_stage((p + 4) % NSTAGE, (p + 4) * BK);
        CP_COMMIT();
        compute_stage((p + 1) % NSTAGE);
        if (p + 5 < nk) load_stage((p + 5) % NSTAGE, (p + 5) * BK);
        CP_COMMIT();
    }
}

// ---------------------------------------------------------------------------
// proj kernel: M=131072, N=384 (3 x-blocks), K=128. Fused q softmax on block 0.
// ---------------------------------------------------------------------------
__global__ __launch_bounds__(256, 1) void proj_kernel() {
    extern __shared__ __align__(16) hf smem[];
    const int tid = threadIdx.x, lane = tid & 31, warp = tid >> 5;
    const int wm = warp >> 1, wn = warp & 1;
    const int m0 = blockIdx.y * BM, n0 = blockIdx.x * BN;

    float acc[4][8][4];
#pragma unroll
    for (int i = 0; i < 4; i++)
#pragma unroll
        for (int j = 0; j < 8; j++)
#pragma unroll
            for (int q = 0; q < 4; q++) acc[i][j][q] = 0.f;

    gemm_nt(g_xh, g_Wallh, EE, EE, EE, m0, n0, smem, tid, lane, wm, wn, acc);

    const float* bias = g_ball;
    if (n0 == 0) {
#pragma unroll
        for (int mi = 0; mi < 4; mi++) {
            int rc0 = m0 + wm * 64 + mi * 16 + (lane >> 2);
#pragma unroll
            for (int nb = 0; nb < 8; nb += 2) {
                int e0 = wn * 64 + nb * 8 + (lane & 3) * 2;
                float b0 = bias[e0], b1 = bias[e0 + 1];
                float b2 = bias[e0 + 8], b3 = bias[e0 + 9];
                float r0[4] = {acc[mi][nb][0] + b0, acc[mi][nb][1] + b1,
                               acc[mi][nb + 1][0] + b2, acc[mi][nb + 1][1] + b3};
                float r1[4] = {acc[mi][nb][2] + b0, acc[mi][nb][3] + b1,
                               acc[mi][nb + 1][2] + b2, acc[mi][nb + 1][3] + b3};
                float mx0 = fmaxf(fmaxf(r0[0], r0[1]), fmaxf(r0[2], r0[3]));
                float mx1 = fmaxf(fmaxf(r1[0], r1[1]), fmaxf(r1[2], r1[3]));
                mx0 = fmaxf(mx0, __shfl_xor_sync(0xffffffffu, mx0, 1));
                mx0 = fmaxf(mx0, __shfl_xor_sync(0xffffffffu, mx0, 2));
                mx1 = fmaxf(mx1, __shfl_xor_sync(0xffffffffu, mx1, 1));
                mx1 = fmaxf(mx1, __shfl_xor_sync(0xffffffffu, mx1, 2));
                float s0 = 0.f, s1 = 0.f;
#pragma unroll
                for (int q = 0; q < 4; q++) { r0[q] = __expf(r0[q] - mx0); s0 += r0[q]; }
#pragma unroll
                for (int q = 0; q < 4; q++) { r1[q] = __expf(r1[q] - mx1); s1 += r1[q]; }
                s0 += __shfl_xor_sync(0xffffffffu, s0, 1);
                s0 += __shfl_xor_sync(0xffffffffu, s0, 2);
                s1 += __shfl_xor_sync(0xffffffffu, s1, 1);
                s1 += __shfl_xor_sync(0xffffffffu, s1, 2);
                float sc0 = 0.03125f / s0, sc1 = 0.03125f / s1;

                int hh = e0 >> 4, jj = e0 & 15;
#pragma unroll
                for (int rr2 = 0; rr2 < 2; rr2++) {
                    int rc = rc0 + rr2 * 8;
                    int r = rc >> 11, c = rc & (CC - 1);
                    float* vv = rr2 ? r1 : r0;
                    float sc = rr2 ? sc1 : sc0;
                    hf* dst = g_Qh + ((size_t)hh * CC + c) * DD + (r << 4) + jj;
                    *(__half2*)dst = __floats2half2_rn(vv[0] * sc, vv[1] * sc);
                    *(__half2*)(dst + 8) = __floats2half2_rn(vv[2] * sc, vv[3] * sc);
                }
            }
        }
        return;
    }

    hf* dst3 = (n0 == 128) ? g_Klog : g_Vh;
#pragma unroll
    for (int mi = 0; mi < 4; mi++) {
#pragma unroll
        for (int ni = 0; ni < 8; ni++) {
            int grow = m0 + wm * 64 + mi * 16 + (lane >> 2);
            int gcol = n0 + wn * 64 + ni * 8 + (lane & 3) * 2;
            int e = gcol & 127;
            int hh = e >> 4, jj = e & 15;
            float b0 = bias[gcol], b1 = bias[gcol + 1];
#pragma unroll
            for (int rr2 = 0; rr2 < 2; rr2++) {
                int rc = grow + rr2 * 8;
                int r = rc >> 11, c = rc & (CC - 1);
                float a0 = (rr2 ? acc[mi][ni][2] : acc[mi][ni][0]) + b0;
                float a1 = (rr2 ? acc[mi][ni][3] : acc[mi][ni][1]) + b1;
                *(__half2*)&dst3[((size_t)hh * CC + c) * DD + (r << 4) + jj] =
                    __floats2half2_rn(a0, a1);
            }
        }
    }
}

// ---------------------------------------------------------------------------
// merged attn + ctx kernel. blockIdx.x in [0,1280):
//   [0,256):   ctx (TN) — ctxT[e][d] = sum_n Vh[n][e] Kh[n][d]
//   [256,1280): attn (NT) — attn[nq][m] = sum_d Qh[nq][d] Kh[m][d]
// ---------------------------------------------------------------------------
__global__ __launch_bounds__(256, 1) void attnctx_kernel(float* __restrict__ attn_out) {
    extern __shared__ __align__(16) hf smem[];
    const int tid = threadIdx.x, lane = tid & 31, warp = tid >> 5;
    const int wm = warp >> 1, wn = warp & 1;
    const int id = blockIdx.x;

    float acc[4][8][4];
#pragma unroll
    for (int i = 0; i < 4; i++)
#pragma unroll
        for (int j = 0; j < 8; j++)
#pragma unroll
            for (int q = 0; q < 4; q++) acc[i][j][q] = 0.f;

    if (id < 256) {
        int z = id >> 5, by = (id >> 3) & 3, bx = id & 7;
        int m0 = by * BM, n0 = bx * BN;
        gemm_tn(g_Vh + (size_t)z * CC * DD, g_Kh + (size_t)z * CC * DD,
                DD, DD, CC, m0, n0, smem, tid, lane, wm, wn, acc);
        hf* bh = g_CTh + (size_t)z * DD * DD;
#pragma unroll
        for (int mi = 0; mi < 4; mi++)
#pragma unroll
            for (int ni = 0; ni < 8; ni++) {
                int grow = m0 + wm * 64 + mi * 16 + (lane >> 2);
                int gcol = n0 + wn * 64 + ni * 8 + (lane & 3) * 2;
                *(__half2*)&bh[(size_t)grow * DD + gcol] =
                    __floats2half2_rn(acc[mi][ni][0], acc[mi][ni][1]);
                *(__half2*)&bh[(size_t)(grow + 8) * DD + gcol] =
                    __floats2half2_rn(acc[mi][ni][2], acc[mi][ni][3]);
            }
    } else {
        int id2 = id - 256;
        int z = id2 >> 7, by = (id2 >> 4) & 7, bx = id2 & 15;
        int m0 = by * BM, n0 = bx * BN;
        gemm_nt(g_Qh + (size_t)z * CC * DD, g_Kh + (size_t)z * CC * DD,
                DD, DD, DD, m0, n0, smem, tid, lane, wm, wn, acc);
        float* base = attn_out + (size_t)z * CC * CC;
#pragma unroll
        for (int mi = 0; mi < 4; mi++)
#pragma unroll
            for (int ni = 0; ni < 8; ni++) {
                int grow = m0 + wm * 64 + mi * 16 + (lane >> 2);
                int gcol = n0 + wn * 64 + ni * 8 + (lane & 3) * 2;
                *(float2*)&base[(size_t)grow * CC + gcol] =
                    make_float2(acc[mi][ni][0], acc[mi][ni][1]);
                *(float2*)&base[(size_t)(grow + 8) * CC + gcol] =
                    make_float2(acc[mi][ni][2], acc[mi][ni][3]);
            }
    }
}

// ---------------------------------------------------------------------------
// out kernel: out[c][col] = sum_d Qh[c][d] CTh[col][d], scatter epilogue
// ---------------------------------------------------------------------------
__global__ __launch_bounds__(256, 1) void out_kernel(float* __restrict__ out) {
    extern __shared__ __align__(16) hf smem[];
    const int tid = threadIdx.x, lane = tid & 31, warp = tid >> 5;
    const int wm = warp >> 1, wn = warp & 1;
    const int h = blockIdx.z;
    const int m0 = blockIdx.y * BM, n0 = blockIdx.x * BN;

    float acc[4][8][4];
#pragma unroll
    for (int i = 0; i < 4; i++)
#pragma unroll
        for (int j = 0; j < 8; j++)
#pragma unroll
            for (int q = 0; q < 4; q++) acc[i][j][q] = 0.f;

    gemm_nt(g_Qh + (size_t)h * CC * DD, g_CTh + (size_t)h * DD * DD,
            DD, DD, DD, m0, n0, smem, tid, lane, wm, wn, acc);

#pragma unroll
    for (int mi = 0; mi < 4; mi++)
#pragma unroll
        for (int ni = 0; ni < 8; ni++) {
            int grow = m0 + wm * 64 + mi * 16 + (lane >> 2);
            int gcol = n0 + wn * 64 + ni * 8 + (lane & 3) * 2;
            int r = gcol >> 4, j = gcol & 15;
#pragma unroll
            for (int rr2 = 0; rr2 < 2; rr2++) {
                int c = grow + rr2 * 8;
                float a0 = rr2 ? acc[mi][ni][2] : acc[mi][ni][0];
                float a1 = rr2 ? acc[mi][ni][3] : acc[mi][ni][1];
                *(float2*)&out[(((size_t)r * CC + c) << 7) + h * HDIM + j] =
                    make_float2(a0, a1);
            }
        }
}

// ---------------------------------------------------------------------------
// prep: x->fp16 (16384), W->fp16 (48), bias (2), zero ksum (32)
// ---------------------------------------------------------------------------
__global__ __launch_bounds__(256) void prep_kernel(
    const float* __restrict__ x, const float* __restrict__ Wq,
    const float* __restrict__ Wk, const float* __restrict__ Wv,
    const float* __restrict__ bq, const float* __restrict__ bk,
    const float* __restrict__ bv) {
    int b = blockIdx.x, tid = threadIdx.x;
    if (b < 16384) {
        int i = b * 256 + tid;
        float4 v = *(const float4*)(x + (size_t)i * 4);
        *(__half2*)(g_xh + (size_t)i * 4) = __floats2half2_rn(v.x, v.y);
        *(__half2*)(g_xh + (size_t)i * 4 + 2) = __floats2half2_rn(v.z, v.w);
    } else if (b < 16432) {
        int q = (b - 16384) * 256 + tid;
        int w = q >> 12, j = q & 4095;
        const float* W = (w == 0) ? Wq : (w == 1) ? Wk : Wv;
        float4 v = *(const float4*)(W + j * 4);
        hf* dst = g_Wallh + w * EE * EE + j * 4;
        *(__half2*)dst = __floats2half2_rn(v.x, v.y);
        *(__half2*)(dst + 2) = __floats2half2_rn(v.z, v.w);
    } else if (b < 16434) {
        int i = (b - 16432) * 256 + tid;
        if (i < 384)
            g_ball[i] = (i < 128) ? bq[i] : (i < 256) ? bk[i - 128] : bv[i - 256];
    } else {
        g_ksum[(b - 16434) * 256 + tid] = 0.f;
    }
}

// ---------------------------------------------------------------------------
// ksum: coalesced partial exp-sums over n, atomicAdd into g_ksum
// grid (8 n-chunks, HH), 256 threads: thread -> (d-oct, n-parity)
// ---------------------------------------------------------------------------
__global__ __launch_bounds__(256) void ksum_kernel() {
    int h = blockIdx.y;
    int n0 = blockIdx.x * 256;
    int tid = threadIdx.x;
    int dv = (tid & 127) * 8, np = tid >> 7;
    const hf* base = g_Klog + (size_t)h * CC * DD;
    float s[8] = {};
    for (int n = n0 + np; n < n0 + 256; n += 2) {
        float4 raw = *(const float4*)(base + (size_t)n * DD + dv);
        const __half2* h2 = (const __half2*)&raw;
#pragma unroll
        for (int j = 0; j < 4; j++) {
            float2 f = __half22float2(h2[j]);
            s[2 * j] += __expf(f.x);
            s[2 * j + 1] += __expf(f.y);
        }
    }
#pragma unroll
    for (int j = 0; j < 8; j++) atomicAdd(&g_ksum[h * DD + dv + j], s[j]);
}

__global__ __launch_bounds__(256) void inv_kernel() {
    int i = blockIdx.x * 256 + threadIdx.x;
    g_ksum[i] = 1.0f / g_ksum[i];
}

// ksoft: Kh = exp(Klog) * ksum_inv  (8 halfs per thread, coalesced)
__global__ __launch_bounds__(256) void ksoft_kernel() {
    size_t i8 = (size_t)blockIdx.x * 256 + threadIdx.x;
    size_t base = i8 * 8;
    int h = (int)(base >> 21);                 // / (CC*DD)
    int d = (int)(base & (DD - 1));
    float4 raw = *(const float4*)(g_Klog + base);
    const __half2* h2 = (const __half2*)&raw;
    const float* inv = g_ksum + h * DD + d;
    float4 iv0 = *(const float4*)inv;
    float4 iv1 = *(const float4*)(inv + 4);
    float iv[8] = {iv0.x, iv0.y, iv0.z, iv0.w, iv1.x, iv1.y, iv1.z, iv1.w};
    __half2 outv[4];
#pragma unroll
    for (int j = 0; j < 4; j++) {
        float2 f = __half22float2(h2[j]);
        outv[j] = __floats2half2_rn(__expf(f.x) * iv[2 * j], __expf(f.y) * iv[2 * j + 1]);
    }
    *(float4*)(g_Kh + base) = *(float4*)outv;
}

// ---------------------------------------------------------------------------
// launch
// ---------------------------------------------------------------------------
extern "C" void kernel_launch(void* const* d_in, const int* in_sizes, int n_in,
                              void* d_out, int out_size) {
    const float* x  = (const float*)d_in[0];
    const float* Wq = (const float*)d_in[1];
    const float* bq = (const float*)d_in[2];
    const float* Wk = (const float*)d_in[3];
    const float* bk = (const float*)d_in[4];
    const float* Wv = (const float*)d_in[5];
    const float* bv = (const float*)d_in[6];
    float* out = (float*)d_out;

    cudaFuncSetAttribute(proj_kernel, cudaFuncAttributeMaxDynamicSharedMemorySize, SMEM_BYTES);
    cudaFuncSetAttribute(attnctx_kernel, cudaFuncAttributeMaxDynamicSharedMemorySize, SMEM_BYTES);
    cudaFuncSetAttribute(out_kernel, cudaFuncAttributeMaxDynamicSharedMemorySize, SMEM_BYTES);

    dim3 t256(256);

    // 1) prep (x/W fp16, bias, zero ksum)
    prep_kernel<<<16466, t256>>>(x, Wq, Wk, Wv, bq, bk, bv);

    // 2) fused projection (q softmax fused on N-block 0)
    proj_kernel<<<dim3(3, (RR * CC) / BM, 1), t256, SMEM_BYTES>>>();

    // 3) k softmax: coalesced sums -> invert -> apply
    ksum_kernel<<<dim3(8, HH), t256>>>();
    inv_kernel<<<HH * DD / 256, t256>>>();
    ksoft_kernel<<<HH * CC * DD / 8 / 256, t256>>>();

    // 4) merged ctx (TN, 256 CTAs first) + attn (NT, 1024 CTAs)
    attnctx_kernel<<<1280, t256, SMEM_BYTES>>>(out + (size_t)RR * CC * EE);

    // 5) out GEMM with scatter epilogue
    out_kernel<<<dim3(DD / BN, CC / BM, HH), t256, SMEM_BYTES>>>(out);
}

// round 10
// speedup vs baseline: 7.5587x; 1.0413x over previous
#include <cuda_runtime.h>
#include <cuda_fp16.h>
#include <cstdint>

// Gene Linear Attention — fp16 mma.sync pipeline v8.
// Mega-GEMM launch: ctx (TN, 256) + attn (NT, 1024) + out (NT, 512, waits on ctx)
// in ONE kernel with device-side ordering. Fixes v7's out-decomposition bug.

#define RR   64
#define CC   2048
#define EE   128
#define HH   8
#define HDIM 16
#define DD   1024   // RR*HDIM

typedef __half hf;

// ---------------- device global scratch ----------------
__device__ float g_ksum[HH * DD];
__device__ float g_ball[3 * EE];
__device__ int   g_ctx_done;

__device__ hf g_xh[RR * CC * EE];
__device__ hf g_Wallh[3 * EE * EE];     // Wq|Wk|Wv stacked rows

__device__ hf g_Qh[HH * CC * DD];       // softmaxed+scaled q [h][c][d]
__device__ hf g_Klog[HH * CC * DD];     // k logits fp16 [h][n][d]
__device__ hf g_Vh[HH * CC * DD];       // v fp16 [h][n][e]
__device__ hf g_Kh[HH * CC * DD];       // softmaxed k [h][n][d]
__device__ hf g_CTh[HH * DD * DD];      // ctxT [h][col=e][d]

// ---------------- PTX helpers ----------------
__device__ __forceinline__ uint32_t cvta(const void* p) {
    return (uint32_t)__cvta_generic_to_shared(p);
}
__device__ __forceinline__ void cp16(uint32_t dst, const void* src) {
    asm volatile("cp.async.cg.shared.global [%0], [%1], 16;\n" :: "r"(dst), "l"(src));
}
#define CP_COMMIT() asm volatile("cp.async.commit_group;\n" ::)

__device__ __forceinline__ void ldm4(uint32_t (&a)[4], uint32_t addr) {
    asm volatile("ldmatrix.sync.aligned.m8n8.x4.shared.b16 {%0,%1,%2,%3}, [%4];"
                 : "=r"(a[0]), "=r"(a[1]), "=r"(a[2]), "=r"(a[3]) : "r"(addr));
}
__device__ __forceinline__ void ldm4t(uint32_t (&a)[4], uint32_t addr) {
    asm volatile("ldmatrix.sync.aligned.m8n8.x4.trans.shared.b16 {%0,%1,%2,%3}, [%4];"
                 : "=r"(a[0]), "=r"(a[1]), "=r"(a[2]), "=r"(a[3]) : "r"(addr));
}
__device__ __forceinline__ void mma16816(float (&c)[4], const uint32_t (&a)[4],
                                         const uint32_t b0, const uint32_t b1) {
    asm volatile(
        "mma.sync.aligned.m16n8k16.row.col.f32.f16.f16.f32 "
        "{%0,%1,%2,%3}, {%4,%5,%6,%7}, {%8,%9}, {%0,%1,%2,%3};"
        : "+f"(c[0]), "+f"(c[1]), "+f"(c[2]), "+f"(c[3])
        : "r"(a[0]), "r"(a[1]), "r"(a[2]), "r"(a[3]), "r"(b0), "r"(b1));
}

// ---------------------------------------------------------------------------
// Tile config: CTA 256x128, warps 4x2 (64x64 each), BK=32, S=6 pair-chunk pipeline
// ---------------------------------------------------------------------------
#define BM 256
#define BN 128
#define BK 32
#define LDSS 40
#define OFF_BH (BM * LDSS)
#define GSTAGE ((BM + BN) * LDSS)
#define NSTAGE 6
#define SMEM_BYTES (NSTAGE * GSTAGE * 2)   // 184320

// TN layout inside a stage: A 32x256 (stride 264), B 32x128 (stride 136)
#define TLDA 264
#define TLDB 136
#define OFF_TB (32 * TLDA)

// ---------------- NT mainloop (A[m][k], B[n][k]) ----------------
__device__ __forceinline__ void gemm_nt(
    const hf* __restrict__ pA, const hf* __restrict__ pB,
    int ldA, int ldB, int Kdim, int m0, int n0,
    hf* smem, int tid, int lane, int wm, int wn,
    float (&acc)[4][8][4])
{
    auto load_stage = [&](int st, int k0) {
        hf* s = smem + st * GSTAGE;
#pragma unroll
        for (int t = 0; t < 4; t++) {
            int slot = tid + t * 256;
            int r = slot >> 2, seg = slot & 3;
            cp16(cvta(s + r * LDSS + seg * 8), pA + (size_t)(m0 + r) * ldA + k0 + seg * 8);
        }
#pragma unroll
        for (int t = 0; t < 2; t++) {
            int slot = tid + t * 256;
            int r = slot >> 2, seg = slot & 3;
            cp16(cvta(s + OFF_BH + r * LDSS + seg * 8), pB + (size_t)(n0 + r) * ldB + k0 + seg * 8);
        }
    };
    auto compute_stage = [&](int st) {
        const hf* s = smem + st * GSTAGE;
        const uint32_t baseA = cvta(s);
        const uint32_t baseB = cvta(s + OFF_BH);
#pragma unroll
        for (int kk = 0; kk < 2; kk++) {
            uint32_t a[4][4], b[4][4];
#pragma unroll
            for (int mi = 0; mi < 4; mi++) {
                int m = wm * 64 + mi * 16 + (lane & 15);
                ldm4(a[mi], baseA + (uint32_t)(m * LDSS + kk * 16 + (lane >> 4) * 8) * 2);
            }
#pragma unroll
            for (int nb = 0; nb < 4; nb++) {
                int n = wn * 64 + nb * 16 + ((lane >> 4) << 3) + (lane & 7);
                ldm4(b[nb], baseB + (uint32_t)(n * LDSS + kk * 16 + ((lane >> 3) & 1) * 8) * 2);
            }
#pragma unroll
            for (int mi = 0; mi < 4; mi++)
#pragma unroll
                for (int nb = 0; nb < 4; nb++) {
                    mma16816(acc[mi][nb * 2], a[mi], b[nb][0], b[nb][1]);
                    mma16816(acc[mi][nb * 2 + 1], a[mi], b[nb][2], b[nb][3]);
                }
        }
    };

    const int nk = Kdim / BK;
#pragma unroll 1
    for (int s = 0; s < 4; s++) { if (s < nk) load_stage(s, s * BK); CP_COMMIT(); }
#pragma unroll 1
    for (int p = 0; p < nk; p += 2) {
        asm volatile("cp.async.wait_group 2;\n" ::);
        __syncthreads();
        compute_stage(p % NSTAGE);
        if (p + 4 < nk) load_stage((p + 4) % NSTAGE, (p + 4) * BK);
        CP_COMMIT();
        compute_stage((p + 1) % NSTAGE);
        if (p + 5 < nk) load_stage((p + 5) % NSTAGE, (p + 5) * BK);
        CP_COMMIT();
    }
}

// ---------------- TN mainloop (A[k][m], B[k][n]; ldmatrix.trans) ----------------
__device__ __forceinline__ void gemm_tn(
    const hf* __restrict__ pA, const hf* __restrict__ pB,
    int ldA, int ldB, int Kdim, int m0, int n0,
    hf* smem, int tid, int lane, int wm, int wn,
    float (&acc)[4][8][4])
{
    auto load_stage = [&](int st, int k0) {
        hf* s = smem + st * GSTAGE;
#pragma unroll
        for (int t = 0; t < 4; t++) {
            int slot = tid + t * 256;
            int r = slot >> 5, seg = slot & 31;
            cp16(cvta(s + r * TLDA + seg * 8), pA + (size_t)(k0 + r) * ldA + m0 + seg * 8);
        }
#pragma unroll
        for (int t = 0; t < 2; t++) {
            int slot = tid + t * 256;
            int r = slot >> 4, seg = slot & 15;
            cp16(cvta(s + OFF_TB + r * TLDB + seg * 8), pB + (size_t)(k0 + r) * ldB + n0 + seg * 8);
        }
    };
    auto compute_stage = [&](int st) {
        const hf* s = smem + st * GSTAGE;
        const uint32_t baseA = cvta(s);
        const uint32_t baseB = cvta(s + OFF_TB);
#pragma unroll
        for (int kk = 0; kk < 2; kk++) {
            uint32_t a[4][4], b[4][4];
            int krA = kk * 16 + (lane & 7) + ((lane >> 4) & 1) * 8;
            int krB = kk * 16 + (lane & 7) + ((lane >> 3) & 1) * 8;
#pragma unroll
            for (int mi = 0; mi < 4; mi++) {
                int m = wm * 64 + mi * 16 + ((lane >> 3) & 1) * 8;
                ldm4t(a[mi], baseA + (uint32_t)(krA * TLDA + m) * 2);
            }
#pragma unroll
            for (int nb = 0; nb < 4; nb++) {
                int n = wn * 64 + nb * 16 + ((lane >> 4) & 1) * 8;
                ldm4t(b[nb], baseB + (uint32_t)(krB * TLDB + n) * 2);
            }
#pragma unroll
            for (int mi = 0; mi < 4; mi++)
#pragma unroll
                for (int nb = 0; nb < 4; nb++) {
                    mma16816(acc[mi][nb * 2], a[mi], b[nb][0], b[nb][1]);
                    mma16816(acc[mi][nb * 2 + 1], a[mi], b[nb][2], b[nb][3]);
                }
        }
    };

    const int nk = Kdim / BK;
#pragma unroll 1
    for (int s = 0; s < 4; s++) { if (s < nk) load_stage(s, s * BK); CP_COMMIT(); }
#pragma unroll 1
    for (int p = 0; p < nk; p += 2) {
        asm volatile("cp.async.wait_group 2;\n" ::);
        __syncthreads();
        compute_stage(p % NSTAGE);
        if (p + 4 < nk) load_stage((p + 4) % NSTAGE, (p + 4) * BK);
        CP_COMMIT();
        compute_stage((p + 1) % NSTAGE);
        if (p + 5 < nk) load_stage((p + 5) % NSTAGE, (p + 5) * BK);
        CP_COMMIT();
    }
}

// ---------------------------------------------------------------------------
// proj kernel: M=131072, N=384, K=128. Fused q softmax on N-block 0.
// ---------------------------------------------------------------------------
__global__ __launch_bounds__(256, 1) void proj_kernel() {
    extern __shared__ __align__(16) hf smem[];
    const int tid = threadIdx.x, lane = tid & 31, warp = tid >> 5;
    const int wm = warp >> 1, wn = warp & 1;
    const int m0 = blockIdx.y * BM, n0 = blockIdx.x * BN;

    float acc[4][8][4];
#pragma unroll
    for (int i = 0; i < 4; i++)
#pragma unroll
        for (int j = 0; j < 8; j++)
#pragma unroll
            for (int q = 0; q < 4; q++) acc[i][j][q] = 0.f;

    gemm_nt(g_xh, g_Wallh, EE, EE, EE, m0, n0, smem, tid, lane, wm, wn, acc);

    const float* bias = g_ball;
    if (n0 == 0) {
#pragma unroll
        for (int mi = 0; mi < 4; mi++) {
            int rc0 = m0 + wm * 64 + mi * 16 + (lane >> 2);
#pragma unroll
            for (int nb = 0; nb < 8; nb += 2) {
                int e0 = wn * 64 + nb * 8 + (lane & 3) * 2;
                float b0 = bias[e0], b1 = bias[e0 + 1];
                float b2 = bias[e0 + 8], b3 = bias[e0 + 9];
                float r0[4] = {acc[mi][nb][0] + b0, acc[mi][nb][1] + b1,
                               acc[mi][nb + 1][0] + b2, acc[mi][nb + 1][1] + b3};
                float r1[4] = {acc[mi][nb][2] + b0, acc[mi][nb][3] + b1,
                               acc[mi][nb + 1][2] + b2, acc[mi][nb + 1][3] + b3};
                float mx0 = fmaxf(fmaxf(r0[0], r0[1]), fmaxf(r0[2], r0[3]));
                float mx1 = fmaxf(fmaxf(r1[0], r1[1]), fmaxf(r1[2], r1[3]));
                mx0 = fmaxf(mx0, __shfl_xor_sync(0xffffffffu, mx0, 1));
                mx0 = fmaxf(mx0, __shfl_xor_sync(0xffffffffu, mx0, 2));
                mx1 = fmaxf(mx1, __shfl_xor_sync(0xffffffffu, mx1, 1));
                mx1 = fmaxf(mx1, __shfl_xor_sync(0xffffffffu, mx1, 2));
                float s0 = 0.f, s1 = 0.f;
#pragma unroll
                for (int q = 0; q < 4; q++) { r0[q] = __expf(r0[q] - mx0); s0 += r0[q]; }
#pragma unroll
                for (int q = 0; q < 4; q++) { r1[q] = __expf(r1[q] - mx1); s1 += r1[q]; }
                s0 += __shfl_xor_sync(0xffffffffu, s0, 1);
                s0 += __shfl_xor_sync(0xffffffffu, s0, 2);
                s1 += __shfl_xor_sync(0xffffffffu, s1, 1);
                s1 += __shfl_xor_sync(0xffffffffu, s1, 2);
                float sc0 = 0.03125f / s0, sc1 = 0.03125f / s1;

                int hh = e0 >> 4, jj = e0 & 15;
#pragma unroll
                for (int rr2 = 0; rr2 < 2; rr2++) {
                    int rc = rc0 + rr2 * 8;
                    int r = rc >> 11, c = rc & (CC - 1);
                    float* vv = rr2 ? r1 : r0;
                    float sc = rr2 ? sc1 : sc0;
                    hf* dst = g_Qh + ((size_t)hh * CC + c) * DD + (r << 4) + jj;
                    *(__half2*)dst = __floats2half2_rn(vv[0] * sc, vv[1] * sc);
                    *(__half2*)(dst + 8) = __floats2half2_rn(vv[2] * sc, vv[3] * sc);
                }
            }
        }
        return;
    }

    hf* dst3 = (n0 == 128) ? g_Klog : g_Vh;
#pragma unroll
    for (int mi = 0; mi < 4; mi++) {
#pragma unroll
        for (int ni = 0; ni < 8; ni++) {
            int grow = m0 + wm * 64 + mi * 16 + (lane >> 2);
            int gcol = n0 + wn * 64 + ni * 8 + (lane & 3) * 2;
            int e = gcol & 127;
            int hh = e >> 4, jj = e & 15;
            float b0 = bias[gcol], b1 = bias[gcol + 1];
#pragma unroll
            for (int rr2 = 0; rr2 < 2; rr2++) {
                int rc = grow + rr2 * 8;
                int r = rc >> 11, c = rc & (CC - 1);
                float a0 = (rr2 ? acc[mi][ni][2] : acc[mi][ni][0]) + b0;
                float a1 = (rr2 ? acc[mi][ni][3] : acc[mi][ni][1]) + b1;
                *(__half2*)&dst3[((size_t)hh * CC + c) * DD + (r << 4) + jj] =
                    __floats2half2_rn(a0, a1);
            }
        }
    }
}

// ---------------------------------------------------------------------------
// MEGA kernel: blockIdx.x in [0, 1792):
//   [0,256):     ctx (TN)  — per head 4x8 blocks; signals g_ctx_done
//   [256,1280):  attn (NT) — per head 8x16 blocks
//   [1280,1792): out (NT)  — per head 8x8 blocks; waits for ctx
// ---------------------------------------------------------------------------
__global__ __launch_bounds__(256, 1) void mega_kernel(float* __restrict__ attn_out,
                                                      float* __restrict__ out) {
    extern __shared__ __align__(16) hf smem[];
    const int tid = threadIdx.x, lane = tid & 31, warp = tid >> 5;
    const int wm = warp >> 1, wn = warp & 1;
    const int id = blockIdx.x;

    float acc[4][8][4];
#pragma unroll
    for (int i = 0; i < 4; i++)
#pragma unroll
        for (int j = 0; j < 8; j++)
#pragma unroll
            for (int q = 0; q < 4; q++) acc[i][j][q] = 0.f;

    if (id < 256) {
        // ---- ctx: z in [0,8), by in [0,4), bx in [0,8) ----
        int z = id >> 5, by = (id >> 3) & 3, bx = id & 7;
        int m0 = by * BM, n0 = bx * BN;
        gemm_tn(g_Vh + (size_t)z * CC * DD, g_Kh + (size_t)z * CC * DD,
                DD, DD, CC, m0, n0, smem, tid, lane, wm, wn, acc);
        hf* bh = g_CTh + (size_t)z * DD * DD;
#pragma unroll
        for (int mi = 0; mi < 4; mi++)
#pragma unroll
            for (int ni = 0; ni < 8; ni++) {
                int grow = m0 + wm * 64 + mi * 16 + (lane >> 2);
                int gcol = n0 + wn * 64 + ni * 8 + (lane & 3) * 2;
                *(__half2*)&bh[(size_t)grow * DD + gcol] =
                    __floats2half2_rn(acc[mi][ni][0], acc[mi][ni][1]);
                *(__half2*)&bh[(size_t)(grow + 8) * DD + gcol] =
                    __floats2half2_rn(acc[mi][ni][2], acc[mi][ni][3]);
            }
        __syncthreads();
        if (tid == 0) {
            __threadfence();
            atomicAdd(&g_ctx_done, 1);
        }
    } else if (id < 1280) {
        // ---- attn: z in [0,8), by in [0,8), bx in [0,16) ----
        int id2 = id - 256;
        int z = id2 >> 7, by = (id2 >> 4) & 7, bx = id2 & 15;
        int m0 = by * BM, n0 = bx * BN;
        gemm_nt(g_Qh + (size_t)z * CC * DD, g_Kh + (size_t)z * CC * DD,
                DD, DD, DD, m0, n0, smem, tid, lane, wm, wn, acc);
        float* base = attn_out + (size_t)z * CC * CC;
#pragma unroll
        for (int mi = 0; mi < 4; mi++)
#pragma unroll
            for (int ni = 0; ni < 8; ni++) {
                int grow = m0 + wm * 64 + mi * 16 + (lane >> 2);
                int gcol = n0 + wn * 64 + ni * 8 + (lane & 3) * 2;
                *(float2*)&base[(size_t)grow * CC + gcol] =
                    make_float2(acc[mi][ni][0], acc[mi][ni][1]);
                *(float2*)&base[(size_t)(grow + 8) * CC + gcol] =
                    make_float2(acc[mi][ni][2], acc[mi][ni][3]);
            }
    } else {
        // ---- out: z in [0,8), by in [0,8), bx in [0,8); waits for ctx ----
        if (tid == 0) {
            while (atomicAdd(&g_ctx_done, 0) < 256) { __nanosleep(128); }
        }
        __syncthreads();
        __threadfence();

        int id2 = id - 1280;                 // [0,512)
        int z = id2 >> 6, by = (id2 >> 3) & 7, bx = id2 & 7;
        int m0 = by * BM, n0 = bx * BN;
        gemm_nt(g_Qh + (size_t)z * CC * DD, g_CTh + (size_t)z * DD * DD,
                DD, DD, DD, m0, n0, smem, tid, lane, wm, wn, acc);
#pragma unroll
        for (int mi = 0; mi < 4; mi++)
#pragma unroll
            for (int ni = 0; ni < 8; ni++) {
                int grow = m0 + wm * 64 + mi * 16 + (lane >> 2);
                int gcol = n0 + wn * 64 + ni * 8 + (lane & 3) * 2;
                int r = gcol >> 4, j = gcol & 15;
#pragma unroll
                for (int rr2 = 0; rr2 < 2; rr2++) {
                    int c = grow + rr2 * 8;
                    float a0 = rr2 ? acc[mi][ni][2] : acc[mi][ni][0];
                    float a1 = rr2 ? acc[mi][ni][3] : acc[mi][ni][1];
                    *(float2*)&out[(((size_t)r * CC + c) << 7) + z * HDIM + j] =
                        make_float2(a0, a1);
                }
            }
    }
}

// ---------------------------------------------------------------------------
// prep: x->fp16 (16384), W->fp16 (48), bias+flag (2), zero ksum (32)
// ---------------------------------------------------------------------------
__global__ __launch_bounds__(256) void prep_kernel(
    const float* __restrict__ x, const float* __restrict__ Wq,
    const float* __restrict__ Wk, const float* __restrict__ Wv,
    const float* __restrict__ bq, const float* __restrict__ bk,
    const float* __restrict__ bv) {
    int b = blockIdx.x, tid = threadIdx.x;
    if (b < 16384) {
        int i = b * 256 + tid;
        float4 v = *(const float4*)(x + (size_t)i * 4);
        *(__half2*)(g_xh + (size_t)i * 4) = __floats2half2_rn(v.x, v.y);
        *(__half2*)(g_xh + (size_t)i * 4 + 2) = __floats2half2_rn(v.z, v.w);
    } else if (b < 16432) {
        int q = (b - 16384) * 256 + tid;
        int w = q >> 12, j = q & 4095;
        const float* W = (w == 0) ? Wq : (w == 1) ? Wk : Wv;
        float4 v = *(const float4*)(W + j * 4);
        hf* dst = g_Wallh + w * EE * EE + j * 4;
        *(__half2*)dst = __floats2half2_rn(v.x, v.y);
        *(__half2*)(dst + 2) = __floats2half2_rn(v.z, v.w);
    } else if (b < 16434) {
        int i = (b - 16432) * 256 + tid;
        if (i < 384)
            g_ball[i] = (i < 128) ? bq[i] : (i < 256) ? bk[i - 128] : bv[i - 256];
        if (b == 16432 && tid == 0) g_ctx_done = 0;
    } else {
        g_ksum[(b - 16434) * 256 + tid] = 0.f;
    }
}

// ---------------------------------------------------------------------------
// ksum / inv / ksoft
// ---------------------------------------------------------------------------
__global__ __launch_bounds__(256) void ksum_kernel() {
    int h = blockIdx.y;
    int n0 = blockIdx.x * 256;
    int tid = threadIdx.x;
    int dv = (tid & 127) * 8, np = tid >> 7;
    const hf* base = g_Klog + (size_t)h * CC * DD;
    float s[8] = {};
    for (int n = n0 + np; n < n0 + 256; n += 2) {
        float4 raw = *(const float4*)(base + (size_t)n * DD + dv);
        const __half2* h2 = (const __half2*)&raw;
#pragma unroll
        for (int j = 0; j < 4; j++) {
            float2 f = __half22float2(h2[j]);
            s[2 * j] += __expf(f.x);
            s[2 * j + 1] += __expf(f.y);
        }
    }
#pragma unroll
    for (int j = 0; j < 8; j++) atomicAdd(&g_ksum[h * DD + dv + j], s[j]);
}

__global__ __launch_bounds__(256) void inv_kernel() {
    int i = blockIdx.x * 256 + threadIdx.x;
    g_ksum[i] = 1.0f / g_ksum[i];
}

__global__ __launch_bounds__(256) void ksoft_kernel() {
    size_t i8 = (size_t)blockIdx.x * 256 + threadIdx.x;
    size_t base = i8 * 8;
    int h = (int)(base >> 21);
    int d = (int)(base & (DD - 1));
    float4 raw = *(const float4*)(g_Klog + base);
    const __half2* h2 = (const __half2*)&raw;
    const float* inv = g_ksum + h * DD + d;
    float4 iv0 = *(const float4*)inv;
    float4 iv1 = *(const float4*)(inv + 4);
    float iv[8] = {iv0.x, iv0.y, iv0.z, iv0.w, iv1.x, iv1.y, iv1.z, iv1.w};
    __half2 outv[4];
#pragma unroll
    for (int j = 0; j < 4; j++) {
        float2 f = __half22float2(h2[j]);
        outv[j] = __floats2half2_rn(__expf(f.x) * iv[2 * j], __expf(f.y) * iv[2 * j + 1]);
    }
    *(float4*)(g_Kh + base) = *(float4*)outv;
}

// ---------------------------------------------------------------------------
// launch
// ---------------------------------------------------------------------------
extern "C" void kernel_launch(void* const* d_in, const int* in_sizes, int n_in,
                              void* d_out, int out_size) {
    const float* x  = (const float*)d_in[0];
    const float* Wq = (const float*)d_in[1];
    const float* bq = (const float*)d_in[2];
    const float* Wk = (const float*)d_in[3];
    const float* bk = (const float*)d_in[4];
    const float* Wv = (const float*)d_in[5];
    const float* bv = (const float*)d_in[6];
    float* out = (float*)d_out;

    cudaFuncSetAttribute(proj_kernel, cudaFuncAttributeMaxDynamicSharedMemorySize, SMEM_BYTES);
    cudaFuncSetAttribute(mega_kernel, cudaFuncAttributeMaxDynamicSharedMemorySize, SMEM_BYTES);

    dim3 t256(256);

    // 1) prep (x/W fp16, bias, zero ksum + ctx flag)
    prep_kernel<<<16466, t256>>>(x, Wq, Wk, Wv, bq, bk, bv);

    // 2) fused projection (q softmax fused on N-block 0)
    proj_kernel<<<dim3(3, (RR * CC) / BM, 1), t256, SMEM_BYTES>>>();

    // 3) k softmax: coalesced sums -> invert -> apply
    ksum_kernel<<<dim3(8, HH), t256>>>();
    inv_kernel<<<HH * DD / 256, t256>>>();
    ksoft_kernel<<<HH * CC * DD / 8 / 256, t256>>>();

    // 4) mega: ctx (256) + attn (1024) + out (512, waits on ctx)
    mega_kernel<<<1792, t256, SMEM_BYTES>>>(out + (size_t)RR * CC * EE, out);
}

// round 11
// speedup vs baseline: 8.2006x; 1.0849x over previous
#include <cuda_runtime.h>
#include <cuda_fp16.h>
#include <cstdint>

// Gene Linear Attention — fp16 mma.sync pipeline v9.
// k-softmax column sums fused into proj epilogue (shuffle-reduce + atomicAdd);
// ksum/inv kernels deleted; ksoft is a pure scale pass. 4 launches total.

#define RR   64
#define CC   2048
#define EE   128
#define HH   8
#define HDIM 16
#define DD   1024   // RR*HDIM

typedef __half hf;

// ---------------- device global scratch ----------------
__device__ float g_ksum[HH * DD];
__device__ float g_ball[3 * EE];
__device__ int   g_ctx_done;

__device__ hf g_xh[RR * CC * EE];
__device__ hf g_Wallh[3 * EE * EE];     // Wq|Wk|Wv stacked rows

__device__ hf g_Qh[HH * CC * DD];       // softmaxed+scaled q [h][c][d]
__device__ hf g_Kexp[HH * CC * DD];     // exp(k logits) fp16 [h][n][d]
__device__ hf g_Vh[HH * CC * DD];       // v fp16 [h][n][e]
__device__ hf g_Kh[HH * CC * DD];       // softmaxed k [h][n][d]
__device__ hf g_CTh[HH * DD * DD];      // ctxT [h][col=e][d]

// ---------------- PTX helpers ----------------
__device__ __forceinline__ uint32_t cvta(const void* p) {
    return (uint32_t)__cvta_generic_to_shared(p);
}
__device__ __forceinline__ void cp16(uint32_t dst, const void* src) {
    asm volatile("cp.async.cg.shared.global [%0], [%1], 16;\n" :: "r"(dst), "l"(src));
}
#define CP_COMMIT() asm volatile("cp.async.commit_group;\n" ::)

__device__ __forceinline__ void ldm4(uint32_t (&a)[4], uint32_t addr) {
    asm volatile("ldmatrix.sync.aligned.m8n8.x4.shared.b16 {%0,%1,%2,%3}, [%4];"
                 : "=r"(a[0]), "=r"(a[1]), "=r"(a[2]), "=r"(a[3]) : "r"(addr));
}
__device__ __forceinline__ void ldm4t(uint32_t (&a)[4], uint32_t addr) {
    asm volatile("ldmatrix.sync.aligned.m8n8.x4.trans.shared.b16 {%0,%1,%2,%3}, [%4];"
                 : "=r"(a[0]), "=r"(a[1]), "=r"(a[2]), "=r"(a[3]) : "r"(addr));
}
__device__ __forceinline__ void mma16816(float (&c)[4], const uint32_t (&a)[4],
                                         const uint32_t b0, const uint32_t b1) {
    asm volatile(
        "mma.sync.aligned.m16n8k16.row.col.f32.f16.f16.f32 "
        "{%0,%1,%2,%3}, {%4,%5,%6,%7}, {%8,%9}, {%0,%1,%2,%3};"
        : "+f"(c[0]), "+f"(c[1]), "+f"(c[2]), "+f"(c[3])
        : "r"(a[0]), "r"(a[1]), "r"(a[2]), "r"(a[3]), "r"(b0), "r"(b1));
}

// ---------------------------------------------------------------------------
// Tile config: CTA 256x128, warps 4x2 (64x64 each), BK=32, S=6 pair-chunk pipeline
// ---------------------------------------------------------------------------
#define BM 256
#define BN 128
#define BK 32
#define LDSS 40
#define OFF_BH (BM * LDSS)
#define GSTAGE ((BM + BN) * LDSS)
#define NSTAGE 6
#define SMEM_BYTES (NSTAGE * GSTAGE * 2)   // 184320

// TN layout inside a stage: A 32x256 (stride 264), B 32x128 (stride 136)
#define TLDA 264
#define TLDB 136
#define OFF_TB (32 * TLDA)

// ---------------- NT mainloop (A[m][k], B[n][k]) ----------------
__device__ __forceinline__ void gemm_nt(
    const hf* __restrict__ pA, const hf* __restrict__ pB,
    int ldA, int ldB, int Kdim, int m0, int n0,
    hf* smem, int tid, int lane, int wm, int wn,
    float (&acc)[4][8][4])
{
    auto load_stage = [&](int st, int k0) {
        hf* s = smem + st * GSTAGE;
#pragma unroll
        for (int t = 0; t < 4; t++) {
            int slot = tid + t * 256;
            int r = slot >> 2, seg = slot & 3;
            cp16(cvta(s + r * LDSS + seg * 8), pA + (size_t)(m0 + r) * ldA + k0 + seg * 8);
        }
#pragma unroll
        for (int t = 0; t < 2; t++) {
            int slot = tid + t * 256;
            int r = slot >> 2, seg = slot & 3;
            cp16(cvta(s + OFF_BH + r * LDSS + seg * 8), pB + (size_t)(n0 + r) * ldB + k0 + seg * 8);
        }
    };
    auto compute_stage = [&](int st) {
        const hf* s = smem + st * GSTAGE;
        const uint32_t baseA = cvta(s);
        const uint32_t baseB = cvta(s + OFF_BH);
#pragma unroll
        for (int kk = 0; kk < 2; kk++) {
            uint32_t a[4][4], b[4][4];
#pragma unroll
            for (int mi = 0; mi < 4; mi++) {
                int m = wm * 64 + mi * 16 + (lane & 15);
                ldm4(a[mi], baseA + (uint32_t)(m * LDSS + kk * 16 + (lane >> 4) * 8) * 2);
            }
#pragma unroll
            for (int nb = 0; nb < 4; nb++) {
                int n = wn * 64 + nb * 16 + ((lane >> 4) << 3) + (lane & 7);
                ldm4(b[nb], baseB + (uint32_t)(n * LDSS + kk * 16 + ((lane >> 3) & 1) * 8) * 2);
            }
#pragma unroll
            for (int mi = 0; mi < 4; mi++)
#pragma unroll
                for (int nb = 0; nb < 4; nb++) {
                    mma16816(acc[mi][nb * 2], a[mi], b[nb][0], b[nb][1]);
                    mma16816(acc[mi][nb * 2 + 1], a[mi], b[nb][2], b[nb][3]);
                }
        }
    };

    const int nk = Kdim / BK;
#pragma unroll 1
    for (int s = 0; s < 4; s++) { if (s < nk) load_stage(s, s * BK); CP_COMMIT(); }
#pragma unroll 1
    for (int p = 0; p < nk; p += 2) {
        asm volatile("cp.async.wait_group 2;\n" ::);
        __syncthreads();
        compute_stage(p % NSTAGE);
        if (p + 4 < nk) load_stage((p + 4) % NSTAGE, (p + 4) * BK);
        CP_COMMIT();
        compute_stage((p + 1) % NSTAGE);
        if (p + 5 < nk) load_stage((p + 5) % NSTAGE, (p + 5) * BK);
        CP_COMMIT();
    }
}

// ---------------- TN mainloop (A[k][m], B[k][n]; ldmatrix.trans) ----------------
__device__ __forceinline__ void gemm_tn(
    const hf* __restrict__ pA, const hf* __restrict__ pB,
    int ldA, int ldB, int Kdim, int m0, int n0,
    hf* smem, int tid, int lane, int wm, int wn,
    float (&acc)[4][8][4])
{
    auto load_stage = [&](int st, int k0) {
        hf* s = smem + st * GSTAGE;
#pragma unroll
        for (int t = 0; t < 4; t++) {
            int slot = tid + t * 256;
            int r = slot >> 5, seg = slot & 31;
            cp16(cvta(s + r * TLDA + seg * 8), pA + (size_t)(k0 + r) * ldA + m0 + seg * 8);
        }
#pragma unroll
        for (int t = 0; t < 2; t++) {
            int slot = tid + t * 256;
            int r = slot >> 4, seg = slot & 15;
            cp16(cvta(s + OFF_TB + r * TLDB + seg * 8), pB + (size_t)(k0 + r) * ldB + n0 + seg * 8);
        }
    };
    auto compute_stage = [&](int st) {
        const hf* s = smem + st * GSTAGE;
        const uint32_t baseA = cvta(s);
        const uint32_t baseB = cvta(s + OFF_TB);
#pragma unroll
        for (int kk = 0; kk < 2; kk++) {
            uint32_t a[4][4], b[4][4];
            int krA = kk * 16 + (lane & 7) + ((lane >> 4) & 1) * 8;
            int krB = kk * 16 + (lane & 7) + ((lane >> 3) & 1) * 8;
#pragma unroll
            for (int mi = 0; mi < 4; mi++) {
                int m = wm * 64 + mi * 16 + ((lane >> 3) & 1) * 8;
                ldm4t(a[mi], baseA + (uint32_t)(krA * TLDA + m) * 2);
            }
#pragma unroll
            for (int nb = 0; nb < 4; nb++) {
                int n = wn * 64 + nb * 16 + ((lane >> 4) & 1) * 8;
                ldm4t(b[nb], baseB + (uint32_t)(krB * TLDB + n) * 2);
            }
#pragma unroll
            for (int mi = 0; mi < 4; mi++)
#pragma unroll
                for (int nb = 0; nb < 4; nb++) {
                    mma16816(acc[mi][nb * 2], a[mi], b[nb][0], b[nb][1]);
                    mma16816(acc[mi][nb * 2 + 1], a[mi], b[nb][2], b[nb][3]);
                }
        }
    };

    const int nk = Kdim / BK;
#pragma unroll 1
    for (int s = 0; s < 4; s++) { if (s < nk) load_stage(s, s * BK); CP_COMMIT(); }
#pragma unroll 1
    for (int p = 0; p < nk; p += 2) {
        asm volatile("cp.async.wait_group 2;\n" ::);
        __syncthreads();
        compute_stage(p % NSTAGE);
        if (p + 4 < nk) load_stage((p + 4) % NSTAGE, (p + 4) * BK);
        CP_COMMIT();
        compute_stage((p + 1) % NSTAGE);
        if (p + 5 < nk) load_stage((p + 5) % NSTAGE, (p + 5) * BK);
        CP_COMMIT();
    }
}

// ---------------------------------------------------------------------------
// proj kernel: M=131072, N=384, K=128.
// N-block 0: q path, fused 16-group softmax.
// N-block 1: k path, exp(logit+bias) -> Kexp fp16 + fused column sums -> g_ksum.
// N-block 2: v path, +bias -> Vh fp16.
// ---------------------------------------------------------------------------
__global__ __launch_bounds__(256, 1) void proj_kernel() {
    extern __shared__ __align__(16) hf smem[];
    const int tid = threadIdx.x, lane = tid & 31, warp = tid >> 5;
    const int wm = warp >> 1, wn = warp & 1;
    const int m0 = blockIdx.y * BM, n0 = blockIdx.x * BN;

    float acc[4][8][4];
#pragma unroll
    for (int i = 0; i < 4; i++)
#pragma unroll
        for (int j = 0; j < 8; j++)
#pragma unroll
            for (int q = 0; q < 4; q++) acc[i][j][q] = 0.f;

    gemm_nt(g_xh, g_Wallh, EE, EE, EE, m0, n0, smem, tid, lane, wm, wn, acc);

    const float* bias = g_ball;
    if (n0 == 0) {
        // ---- q path: fused 16-group softmax (+bias, *1/32) -> g_Qh fp16 ----
#pragma unroll
        for (int mi = 0; mi < 4; mi++) {
            int rc0 = m0 + wm * 64 + mi * 16 + (lane >> 2);
#pragma unroll
            for (int nb = 0; nb < 8; nb += 2) {
                int e0 = wn * 64 + nb * 8 + (lane & 3) * 2;
                float b0 = bias[e0], b1 = bias[e0 + 1];
                float b2 = bias[e0 + 8], b3 = bias[e0 + 9];
                float r0[4] = {acc[mi][nb][0] + b0, acc[mi][nb][1] + b1,
                               acc[mi][nb + 1][0] + b2, acc[mi][nb + 1][1] + b3};
                float r1[4] = {acc[mi][nb][2] + b0, acc[mi][nb][3] + b1,
                               acc[mi][nb + 1][2] + b2, acc[mi][nb + 1][3] + b3};
                float mx0 = fmaxf(fmaxf(r0[0], r0[1]), fmaxf(r0[2], r0[3]));
                float mx1 = fmaxf(fmaxf(r1[0], r1[1]), fmaxf(r1[2], r1[3]));
                mx0 = fmaxf(mx0, __shfl_xor_sync(0xffffffffu, mx0, 1));
                mx0 = fmaxf(mx0, __shfl_xor_sync(0xffffffffu, mx0, 2));
                mx1 = fmaxf(mx1, __shfl_xor_sync(0xffffffffu, mx1, 1));
                mx1 = fmaxf(mx1, __shfl_xor_sync(0xffffffffu, mx1, 2));
                float s0 = 0.f, s1 = 0.f;
#pragma unroll
                for (int q = 0; q < 4; q++) { r0[q] = __expf(r0[q] - mx0); s0 += r0[q]; }
#pragma unroll
                for (int q = 0; q < 4; q++) { r1[q] = __expf(r1[q] - mx1); s1 += r1[q]; }
                s0 += __shfl_xor_sync(0xffffffffu, s0, 1);
                s0 += __shfl_xor_sync(0xffffffffu, s0, 2);
                s1 += __shfl_xor_sync(0xffffffffu, s1, 1);
                s1 += __shfl_xor_sync(0xffffffffu, s1, 2);
                float sc0 = 0.03125f / s0, sc1 = 0.03125f / s1;

                int hh = e0 >> 4, jj = e0 & 15;
#pragma unroll
                for (int rr2 = 0; rr2 < 2; rr2++) {
                    int rc = rc0 + rr2 * 8;
                    int r = rc >> 11, c = rc & (CC - 1);
                    float* vv = rr2 ? r1 : r0;
                    float sc = rr2 ? sc1 : sc0;
                    hf* dst = g_Qh + ((size_t)hh * CC + c) * DD + (r << 4) + jj;
                    *(__half2*)dst = __floats2half2_rn(vv[0] * sc, vv[1] * sc);
                    *(__half2*)(dst + 8) = __floats2half2_rn(vv[2] * sc, vv[3] * sc);
                }
            }
        }
        return;
    }

    if (n0 == 128) {
        // ---- k path: exp(logit+bias) -> g_Kexp + fused column exp-sums ----
        int rB = m0 >> 11;            // cell-row index, constant across the tile
        float colsum[16];
#pragma unroll
        for (int j = 0; j < 16; j++) colsum[j] = 0.f;

#pragma unroll
        for (int mi = 0; mi < 4; mi++) {
#pragma unroll
            for (int ni = 0; ni < 8; ni++) {
                int grow = m0 + wm * 64 + mi * 16 + (lane >> 2);
                int gcol = n0 + wn * 64 + ni * 8 + (lane & 3) * 2;
                int e = gcol & 127;
                int hh = e >> 4, jj = e & 15;
                float b0 = bias[gcol], b1 = bias[gcol + 1];
#pragma unroll
                for (int rr2 = 0; rr2 < 2; rr2++) {
                    int rc = grow + rr2 * 8;
                    int c = rc & (CC - 1);
                    float e0 = __expf((rr2 ? acc[mi][ni][2] : acc[mi][ni][0]) + b0);
                    float e1 = __expf((rr2 ? acc[mi][ni][3] : acc[mi][ni][1]) + b1);
                    colsum[ni * 2] += e0;
                    colsum[ni * 2 + 1] += e1;
                    *(__half2*)&g_Kexp[((size_t)hh * CC + c) * DD + (rB << 4) + jj] =
                        __floats2half2_rn(e0, e1);
                }
            }
        }
        // reduce the 8 row-groups (lane>>2) per column, lanes 0-3 commit
#pragma unroll
        for (int j = 0; j < 16; j++) {
            float s = colsum[j];
            s += __shfl_xor_sync(0xffffffffu, s, 4);
            s += __shfl_xor_sync(0xffffffffu, s, 8);
            s += __shfl_xor_sync(0xffffffffu, s, 16);
            if ((lane >> 2) == 0) {
                int e = wn * 64 + (j >> 1) * 8 + (lane & 3) * 2 + (j & 1);
                int hh = e >> 4, jj = e & 15;
                atomicAdd(&g_ksum[hh * DD + (rB << 4) + jj], s);
            }
        }
        return;
    }

    // ---- v path: +bias -> g_Vh fp16 ----
#pragma unroll
    for (int mi = 0; mi < 4; mi++) {
#pragma unroll
        for (int ni = 0; ni < 8; ni++) {
            int grow = m0 + wm * 64 + mi * 16 + (lane >> 2);
            int gcol = n0 + wn * 64 + ni * 8 + (lane & 3) * 2;
            int e = gcol & 127;
            int hh = e >> 4, jj = e & 15;
            float b0 = bias[gcol], b1 = bias[gcol + 1];
#pragma unroll
            for (int rr2 = 0; rr2 < 2; rr2++) {
                int rc = grow + rr2 * 8;
                int r = rc >> 11, c = rc & (CC - 1);
                float a0 = (rr2 ? acc[mi][ni][2] : acc[mi][ni][0]) + b0;
                float a1 = (rr2 ? acc[mi][ni][3] : acc[mi][ni][1]) + b1;
                *(__half2*)&g_Vh[((size_t)hh * CC + c) * DD + (r << 4) + jj] =
                    __floats2half2_rn(a0, a1);
            }
        }
    }
}

// ---------------------------------------------------------------------------
// MEGA kernel: blockIdx.x in [0, 1792):
//   [0,256):     ctx (TN)  — per head 4x8 blocks; signals g_ctx_done
//   [256,1280):  attn (NT) — per head 8x16 blocks
//   [1280,1792): out (NT)  — per head 8x8 blocks; waits for ctx
// ---------------------------------------------------------------------------
__global__ __launch_bounds__(256, 1) void mega_kernel(float* __restrict__ attn_out,
                                                      float* __restrict__ out) {
    extern __shared__ __align__(16) hf smem[];
    const int tid = threadIdx.x, lane = tid & 31, warp = tid >> 5;
    const int wm = warp >> 1, wn = warp & 1;
    const int id = blockIdx.x;

    float acc[4][8][4];
#pragma unroll
    for (int i = 0; i < 4; i++)
#pragma unroll
        for (int j = 0; j < 8; j++)
#pragma unroll
            for (int q = 0; q < 4; q++) acc[i][j][q] = 0.f;

    if (id < 256) {
        // ---- ctx: z in [0,8), by in [0,4), bx in [0,8) ----
        int z = id >> 5, by = (id >> 3) & 3, bx = id & 7;
        int m0 = by * BM, n0 = bx * BN;
        gemm_tn(g_Vh + (size_t)z * CC * DD, g_Kh + (size_t)z * CC * DD,
                DD, DD, CC, m0, n0, smem, tid, lane, wm, wn, acc);
        hf* bh = g_CTh + (size_t)z * DD * DD;
#pragma unroll
        for (int mi = 0; mi < 4; mi++)
#pragma unroll
            for (int ni = 0; ni < 8; ni++) {
                int grow = m0 + wm * 64 + mi * 16 + (lane >> 2);
                int gcol = n0 + wn * 64 + ni * 8 + (lane & 3) * 2;
                *(__half2*)&bh[(size_t)grow * DD + gcol] =
                    __floats2half2_rn(acc[mi][ni][0], acc[mi][ni][1]);
                *(__half2*)&bh[(size_t)(grow + 8) * DD + gcol] =
                    __floats2half2_rn(acc[mi][ni][2], acc[mi][ni][3]);
            }
        __syncthreads();
        if (tid == 0) {
            __threadfence();
            atomicAdd(&g_ctx_done, 1);
        }
    } else if (id < 1280) {
        // ---- attn: z in [0,8), by in [0,8), bx in [0,16) ----
        int id2 = id - 256;
        int z = id2 >> 7, by = (id2 >> 4) & 7, bx = id2 & 15;
        int m0 = by * BM, n0 = bx * BN;
        gemm_nt(g_Qh + (size_t)z * CC * DD, g_Kh + (size_t)z * CC * DD,
                DD, DD, DD, m0, n0, smem, tid, lane, wm, wn, acc);
        float* base = attn_out + (size_t)z * CC * CC;
#pragma unroll
        for (int mi = 0; mi < 4; mi++)
#pragma unroll
            for (int ni = 0; ni < 8; ni++) {
                int grow = m0 + wm * 64 + mi * 16 + (lane >> 2);
                int gcol = n0 + wn * 64 + ni * 8 + (lane & 3) * 2;
                *(float2*)&base[(size_t)grow * CC + gcol] =
                    make_float2(acc[mi][ni][0], acc[mi][ni][1]);
                *(float2*)&base[(size_t)(grow + 8) * CC + gcol] =
                    make_float2(acc[mi][ni][2], acc[mi][ni][3]);
            }
    } else {
        // ---- out: z in [0,8), by in [0,8), bx in [0,8); waits for ctx ----
        if (tid == 0) {
            while (atomicAdd(&g_ctx_done, 0) < 256) { __nanosleep(128); }
        }
        __syncthreads();
        __threadfence();

        int id2 = id - 1280;                 // [0,512)
        int z = id2 >> 6, by = (id2 >> 3) & 7, bx = id2 & 7;
        int m0 = by * BM, n0 = bx * BN;
        gemm_nt(g_Qh + (size_t)z * CC * DD, g_CTh + (size_t)z * DD * DD,
                DD, DD, DD, m0, n0, smem, tid, lane, wm, wn, acc);
#pragma unroll
        for (int mi = 0; mi < 4; mi++)
#pragma unroll
            for (int ni = 0; ni < 8; ni++) {
                int grow = m0 + wm * 64 + mi * 16 + (lane >> 2);
                int gcol = n0 + wn * 64 + ni * 8 + (lane & 3) * 2;
                int r = gcol >> 4, j = gcol & 15;
#pragma unroll
                for (int rr2 = 0; rr2 < 2; rr2++) {
                    int c = grow + rr2 * 8;
                    float a0 = rr2 ? acc[mi][ni][2] : acc[mi][ni][0];
                    float a1 = rr2 ? acc[mi][ni][3] : acc[mi][ni][1];
                    *(float2*)&out[(((size_t)r * CC + c) << 7) + z * HDIM + j] =
                        make_float2(a0, a1);
                }
            }
    }
}

// ---------------------------------------------------------------------------
// prep: x->fp16 (16384), W->fp16 (48), bias+flag (2), zero ksum (32)
// ---------------------------------------------------------------------------
__global__ __launch_bounds__(256) void prep_kernel(
    const float* __restrict__ x, const float* __restrict__ Wq,
    const float* __restrict__ Wk, const float* __restrict__ Wv,
    const float* __restrict__ bq, const float* __restrict__ bk,
    const float* __restrict__ bv) {
    int b = blockIdx.x, tid = threadIdx.x;
    if (b < 16384) {
        int i = b * 256 + tid;
        float4 v = *(const float4*)(x + (size_t)i * 4);
        *(__half2*)(g_xh + (size_t)i * 4) = __floats2half2_rn(v.x, v.y);
        *(__half2*)(g_xh + (size_t)i * 4 + 2) = __floats2half2_rn(v.z, v.w);
    } else if (b < 16432) {
        int q = (b - 16384) * 256 + tid;
        int w = q >> 12, j = q & 4095;
        const float* W = (w == 0) ? Wq : (w == 1) ? Wk : Wv;
        float4 v = *(const float4*)(W + j * 4);
        hf* dst = g_Wallh + w * EE * EE + j * 4;
        *(__half2*)dst = __floats2half2_rn(v.x, v.y);
        *(__half2*)(dst + 2) = __floats2half2_rn(v.z, v.w);
    } else if (b < 16434) {
        int i = (b - 16432) * 256 + tid;
        if (i < 384)
            g_ball[i] = (i < 128) ? bq[i] : (i < 256) ? bk[i - 128] : bv[i - 256];
        if (b == 16432 && tid == 0) g_ctx_done = 0;
    } else {
        g_ksum[(b - 16434) * 256 + tid] = 0.f;
    }
}

// ---------------------------------------------------------------------------
// ksoft: Kh = Kexp * (1 / ksum[d])  — pure scale pass, 8 halfs per thread
// ---------------------------------------------------------------------------
__global__ __launch_bounds__(256) void ksoft_kernel() {
    size_t i8 = (size_t)blockIdx.x * 256 + threadIdx.x;
    size_t base = i8 * 8;
    int h = (int)(base >> 21);
    int d = (int)(base & (DD - 1));
    float4 raw = *(const float4*)(g_Kexp + base);
    const __half2* h2 = (const __half2*)&raw;
    const float* sums = g_ksum + h * DD + d;
    float4 sv0 = *(const float4*)sums;
    float4 sv1 = *(const float4*)(sums + 4);
    float iv[8] = {__fdividef(1.f, sv0.x), __fdividef(1.f, sv0.y),
                   __fdividef(1.f, sv0.z), __fdividef(1.f, sv0.w),
                   __fdividef(1.f, sv1.x), __fdividef(1.f, sv1.y),
                   __fdividef(1.f, sv1.z), __fdividef(1.f, sv1.w)};
    __half2 outv[4];
#pragma unroll
    for (int j = 0; j < 4; j++) {
        float2 f = __half22float2(h2[j]);
        outv[j] = __floats2half2_rn(f.x * iv[2 * j], f.y * iv[2 * j + 1]);
    }
    *(float4*)(g_Kh + base) = *(float4*)outv;
}

// ---------------------------------------------------------------------------
// launch
// ---------------------------------------------------------------------------
extern "C" void kernel_launch(void* const* d_in, const int* in_sizes, int n_in,
                              void* d_out, int out_size) {
    const float* x  = (const float*)d_in[0];
    const float* Wq = (const float*)d_in[1];
    const float* bq = (const float*)d_in[2];
    const float* Wk = (const float*)d_in[3];
    const float* bk = (const float*)d_in[4];
    const float* Wv = (const float*)d_in[5];
    const float* bv = (const float*)d_in[6];
    float* out = (float*)d_out;

    cudaFuncSetAttribute(proj_kernel, cudaFuncAttributeMaxDynamicSharedMemorySize, SMEM_BYTES);
    cudaFuncSetAttribute(mega_kernel, cudaFuncAttributeMaxDynamicSharedMemorySize, SMEM_BYTES);

    dim3 t256(256);

    // 1) prep (x/W fp16, bias, zero ksum + ctx flag)
    prep_kernel<<<16466, t256>>>(x, Wq, Wk, Wv, bq, bk, bv);

    // 2) fused projection (q softmax on N-block 0; k exp + column sums on N-block 1)
    proj_kernel<<<dim3(3, (RR * CC) / BM, 1), t256, SMEM_BYTES>>>();

    // 3) k softmax apply (pure scale)
    ksoft_kernel<<<HH * CC * DD / 8 / 256, t256>>>();

    // 4) mega: ctx (256) + attn (1024) + out (512, waits on ctx)
    mega_kernel<<<1792, t256, SMEM_BYTES>>>(out + (size_t)RR * CC * EE, out);
}

// round 12
// speedup vs baseline: 8.9047x; 1.0859x over previous
#include <cuda_runtime.h>
#include <cuda_fp16.h>
#include <cstdint>

// Gene Linear Attention — fp16 mma.sync pipeline v10.
// 2 CTAs/SM: CTA tile 128x128 (warp 64x32), 5-stage pipeline, 100KB smem, <=128 regs.
// ncu r11 showed tensor=59.6% at 1 CTA/SM — this round doubles scheduler-level concurrency.

#define RR   64
#define CC   2048
#define EE   128
#define HH   8
#define HDIM 16
#define DD   1024   // RR*HDIM

typedef __half hf;

// ---------------- device global scratch ----------------
__device__ float g_ksum[HH * DD];
__device__ float g_ball[3 * EE];
__device__ int   g_ctx_done;

__device__ hf g_xh[RR * CC * EE];
__device__ hf g_Wallh[3 * EE * EE];     // Wq|Wk|Wv stacked rows

__device__ hf g_Qh[HH * CC * DD];       // softmaxed+scaled q [h][c][d]
__device__ hf g_Kexp[HH * CC * DD];     // exp(k logits) fp16 [h][n][d]
__device__ hf g_Vh[HH * CC * DD];       // v fp16 [h][n][e]
__device__ hf g_Kh[HH * CC * DD];       // softmaxed k [h][n][d]
__device__ hf g_CTh[HH * DD * DD];      // ctxT [h][col=e][d]

// ---------------- PTX helpers ----------------
__device__ __forceinline__ uint32_t cvta(const void* p) {
    return (uint32_t)__cvta_generic_to_shared(p);
}
__device__ __forceinline__ void cp16(uint32_t dst, const void* src) {
    asm volatile("cp.async.cg.shared.global [%0], [%1], 16;\n" :: "r"(dst), "l"(src));
}
#define CP_COMMIT() asm volatile("cp.async.commit_group;\n" ::)

__device__ __forceinline__ void ldm4(uint32_t (&a)[4], uint32_t addr) {
    asm volatile("ldmatrix.sync.aligned.m8n8.x4.shared.b16 {%0,%1,%2,%3}, [%4];"
                 : "=r"(a[0]), "=r"(a[1]), "=r"(a[2]), "=r"(a[3]) : "r"(addr));
}
__device__ __forceinline__ void ldm4t(uint32_t (&a)[4], uint32_t addr) {
    asm volatile("ldmatrix.sync.aligned.m8n8.x4.trans.shared.b16 {%0,%1,%2,%3}, [%4];"
                 : "=r"(a[0]), "=r"(a[1]), "=r"(a[2]), "=r"(a[3]) : "r"(addr));
}
__device__ __forceinline__ void mma16816(float (&c)[4], const uint32_t (&a)[4],
                                         const uint32_t b0, const uint32_t b1) {
    asm volatile(
        "mma.sync.aligned.m16n8k16.row.col.f32.f16.f16.f32 "
        "{%0,%1,%2,%3}, {%4,%5,%6,%7}, {%8,%9}, {%0,%1,%2,%3};"
        : "+f"(c[0]), "+f"(c[1]), "+f"(c[2]), "+f"(c[3])
        : "r"(a[0]), "r"(a[1]), "r"(a[2]), "r"(a[3]), "r"(b0), "r"(b1));
}

// ---------------------------------------------------------------------------
// Tile config: CTA 128x128, warps 2x4 (64x32 each), BK=32, S=5 pair-chunk pipeline
// ---------------------------------------------------------------------------
#define BM 128
#define BN 128
#define BK 32
#define LDSS 40                       // NT half stride (32 + 8 pad)
#define OFF_BH (BM * LDSS)
#define GSTAGE ((BM + BN) * LDSS)     // 10240 halfs per stage
#define NSTAGE 5
#define SMEM_BYTES (NSTAGE * GSTAGE * 2)   // 102400

// TN layout inside a stage: A 32x128 (stride 136), B 32x128 (stride 136)
#define TLDA 136
#define TLDB 136
#define OFF_TB (32 * TLDA)

// ---------------- NT mainloop (A[m][k], B[n][k]) ----------------
__device__ __forceinline__ void gemm_nt(
    const hf* __restrict__ pA, const hf* __restrict__ pB,
    int ldA, int ldB, int Kdim, int m0, int n0,
    hf* smem, int tid, int lane, int wm, int wn,
    float (&acc)[4][4][4])
{
    auto load_stage = [&](int st, int k0) {
        hf* s = smem + st * GSTAGE;
#pragma unroll
        for (int t = 0; t < 2; t++) {
            int slot = tid + t * 256;     // 512 slots: 128 rows x 4 segs
            int r = slot >> 2, seg = slot & 3;
            cp16(cvta(s + r * LDSS + seg * 8), pA + (size_t)(m0 + r) * ldA + k0 + seg * 8);
        }
#pragma unroll
        for (int t = 0; t < 2; t++) {
            int slot = tid + t * 256;
            int r = slot >> 2, seg = slot & 3;
            cp16(cvta(s + OFF_BH + r * LDSS + seg * 8), pB + (size_t)(n0 + r) * ldB + k0 + seg * 8);
        }
    };
    auto compute_stage = [&](int st) {
        const hf* s = smem + st * GSTAGE;
        const uint32_t baseA = cvta(s);
        const uint32_t baseB = cvta(s + OFF_BH);
#pragma unroll
        for (int kk = 0; kk < 2; kk++) {
            uint32_t a[4][4], b[2][4];
#pragma unroll
            for (int mi = 0; mi < 4; mi++) {
                int m = wm * 64 + mi * 16 + (lane & 15);
                ldm4(a[mi], baseA + (uint32_t)(m * LDSS + kk * 16 + (lane >> 4) * 8) * 2);
            }
#pragma unroll
            for (int nb = 0; nb < 2; nb++) {
                int n = wn * 32 + nb * 16 + ((lane >> 4) << 3) + (lane & 7);
                ldm4(b[nb], baseB + (uint32_t)(n * LDSS + kk * 16 + ((lane >> 3) & 1) * 8) * 2);
            }
#pragma unroll
            for (int mi = 0; mi < 4; mi++)
#pragma unroll
                for (int nb = 0; nb < 2; nb++) {
                    mma16816(acc[mi][nb * 2], a[mi], b[nb][0], b[nb][1]);
                    mma16816(acc[mi][nb * 2 + 1], a[mi], b[nb][2], b[nb][3]);
                }
        }
    };

    const int nk = Kdim / BK;
#pragma unroll 1
    for (int s = 0; s < 3; s++) { if (s < nk) load_stage(s, s * BK); CP_COMMIT(); }
#pragma unroll 1
    for (int p = 0; p < nk; p += 2) {
        asm volatile("cp.async.wait_group 1;\n" ::);
        __syncthreads();
        compute_stage(p % NSTAGE);
        if (p + 3 < nk) load_stage((p + 3) % NSTAGE, (p + 3) * BK);
        CP_COMMIT();
        compute_stage((p + 1) % NSTAGE);
        if (p + 4 < nk) load_stage((p + 4) % NSTAGE, (p + 4) * BK);
        CP_COMMIT();
    }
}

// ---------------- TN mainloop (A[k][m], B[k][n]; ldmatrix.trans) ----------------
__device__ __forceinline__ void gemm_tn(
    const hf* __restrict__ pA, const hf* __restrict__ pB,
    int ldA, int ldB, int Kdim, int m0, int n0,
    hf* smem, int tid, int lane, int wm, int wn,
    float (&acc)[4][4][4])
{
    auto load_stage = [&](int st, int k0) {
        hf* s = smem + st * GSTAGE;
#pragma unroll
        for (int t = 0; t < 2; t++) {
            int slot = tid + t * 256;     // 512 slots: 32 rows x 16 segs
            int r = slot >> 4, seg = slot & 15;
            cp16(cvta(s + r * TLDA + seg * 8), pA + (size_t)(k0 + r) * ldA + m0 + seg * 8);
        }
#pragma unroll
        for (int t = 0; t < 2; t++) {
            int slot = tid + t * 256;
            int r = slot >> 4, seg = slot & 15;
            cp16(cvta(s + OFF_TB + r * TLDB + seg * 8), pB + (size_t)(k0 + r) * ldB + n0 + seg * 8);
        }
    };
    auto compute_stage = [&](int st) {
        const hf* s = smem + st * GSTAGE;
        const uint32_t baseA = cvta(s);
        const uint32_t baseB = cvta(s + OFF_TB);
#pragma unroll
        for (int kk = 0; kk < 2; kk++) {
            uint32_t a[4][4], b[2][4];
            int krA = kk * 16 + (lane & 7) + ((lane >> 4) & 1) * 8;
            int krB = kk * 16 + (lane & 7) + ((lane >> 3) & 1) * 8;
#pragma unroll
            for (int mi = 0; mi < 4; mi++) {
                int m = wm * 64 + mi * 16 + ((lane >> 3) & 1) * 8;
                ldm4t(a[mi], baseA + (uint32_t)(krA * TLDA + m) * 2);
            }
#pragma unroll
            for (int nb = 0; nb < 2; nb++) {
                int n = wn * 32 + nb * 16 + ((lane >> 4) & 1) * 8;
                ldm4t(b[nb], baseB + (uint32_t)(krB * TLDB + n) * 2);
            }
#pragma unroll
            for (int mi = 0; mi < 4; mi++)
#pragma unroll
                for (int nb = 0; nb < 2; nb++) {
                    mma16816(acc[mi][nb * 2], a[mi], b[nb][0], b[nb][1]);
                    mma16816(acc[mi][nb * 2 + 1], a[mi], b[nb][2], b[nb][3]);
                }
        }
    };

    const int nk = Kdim / BK;
#pragma unroll 1
    for (int s = 0; s < 3; s++) { if (s < nk) load_stage(s, s * BK); CP_COMMIT(); }
#pragma unroll 1
    for (int p = 0; p < nk; p += 2) {
        asm volatile("cp.async.wait_group 1;\n" ::);
        __syncthreads();
        compute_stage(p % NSTAGE);
        if (p + 3 < nk) load_stage((p + 3) % NSTAGE, (p + 3) * BK);
        CP_COMMIT();
        compute_stage((p + 1) % NSTAGE);
        if (p + 4 < nk) load_stage((p + 4) % NSTAGE, (p + 4) * BK);
        CP_COMMIT();
    }
}

// ---------------------------------------------------------------------------
// proj kernel: M=131072 (1024 blocks), N=384 (3 blocks), K=128.
// N-block 0: q + fused 16-group softmax; 1: k exp + colsums; 2: v.
// ---------------------------------------------------------------------------
__global__ __launch_bounds__(256, 2) void proj_kernel() {
    extern __shared__ __align__(16) hf smem[];
    const int tid = threadIdx.x, lane = tid & 31, warp = tid >> 5;
    const int wm = warp >> 2, wn = warp & 3;
    const int m0 = blockIdx.y * BM, n0 = blockIdx.x * BN;

    float acc[4][4][4];
#pragma unroll
    for (int i = 0; i < 4; i++)
#pragma unroll
        for (int j = 0; j < 4; j++)
#pragma unroll
            for (int q = 0; q < 4; q++) acc[i][j][q] = 0.f;

    gemm_nt(g_xh, g_Wallh, EE, EE, EE, m0, n0, smem, tid, lane, wm, wn, acc);

    const float* bias = g_ball;
    if (n0 == 0) {
        // ---- q path: fused 16-group softmax (+bias, *1/32) -> g_Qh fp16 ----
#pragma unroll
        for (int mi = 0; mi < 4; mi++) {
            int rc0 = m0 + wm * 64 + mi * 16 + (lane >> 2);
#pragma unroll
            for (int nb = 0; nb < 4; nb += 2) {
                int e0 = wn * 32 + nb * 8 + (lane & 3) * 2;
                float b0 = bias[e0], b1 = bias[e0 + 1];
                float b2 = bias[e0 + 8], b3 = bias[e0 + 9];
                float r0[4] = {acc[mi][nb][0] + b0, acc[mi][nb][1] + b1,
                               acc[mi][nb + 1][0] + b2, acc[mi][nb + 1][1] + b3};
                float r1[4] = {acc[mi][nb][2] + b0, acc[mi][nb][3] + b1,
                               acc[mi][nb + 1][2] + b2, acc[mi][nb + 1][3] + b3};
                float mx0 = fmaxf(fmaxf(r0[0], r0[1]), fmaxf(r0[2], r0[3]));
                float mx1 = fmaxf(fmaxf(r1[0], r1[1]), fmaxf(r1[2], r1[3]));
                mx0 = fmaxf(mx0, __shfl_xor_sync(0xffffffffu, mx0, 1));
                mx0 = fmaxf(mx0, __shfl_xor_sync(0xffffffffu, mx0, 2));
                mx1 = fmaxf(mx1, __shfl_xor_sync(0xffffffffu, mx1, 1));
                mx1 = fmaxf(mx1, __shfl_xor_sync(0xffffffffu, mx1, 2));
                float s0 = 0.f, s1 = 0.f;
#pragma unroll
                for (int q = 0; q < 4; q++) { r0[q] = __expf(r0[q] - mx0); s0 += r0[q]; }
#pragma unroll
                for (int q = 0; q < 4; q++) { r1[q] = __expf(r1[q] - mx1); s1 += r1[q]; }
                s0 += __shfl_xor_sync(0xffffffffu, s0, 1);
                s0 += __shfl_xor_sync(0xffffffffu, s0, 2);
                s1 += __shfl_xor_sync(0xffffffffu, s1, 1);
                s1 += __shfl_xor_sync(0xffffffffu, s1, 2);
                float sc0 = 0.03125f / s0, sc1 = 0.03125f / s1;

                int hh = e0 >> 4, jj = e0 & 15;
#pragma unroll
                for (int rr2 = 0; rr2 < 2; rr2++) {
                    int rc = rc0 + rr2 * 8;
                    int r = rc >> 11, c = rc & (CC - 1);
                    float* vv = rr2 ? r1 : r0;
                    float sc = rr2 ? sc1 : sc0;
                    hf* dst = g_Qh + ((size_t)hh * CC + c) * DD + (r << 4) + jj;
                    *(__half2*)dst = __floats2half2_rn(vv[0] * sc, vv[1] * sc);
                    *(__half2*)(dst + 8) = __floats2half2_rn(vv[2] * sc, vv[3] * sc);
                }
            }
        }
        return;
    }

    if (n0 == 128) {
        // ---- k path: exp(logit+bias) -> g_Kexp + fused column exp-sums ----
        int rB = m0 >> 11;
        float colsum[8];
#pragma unroll
        for (int j = 0; j < 8; j++) colsum[j] = 0.f;

#pragma unroll
        for (int mi = 0; mi < 4; mi++) {
#pragma unroll
            for (int ni = 0; ni < 4; ni++) {
                int grow = m0 + wm * 64 + mi * 16 + (lane >> 2);
                int gcol = n0 + wn * 32 + ni * 8 + (lane & 3) * 2;
                int e = gcol & 127;
                int hh = e >> 4, jj = e & 15;
                float b0 = bias[gcol], b1 = bias[gcol + 1];
#pragma unroll
                for (int rr2 = 0; rr2 < 2; rr2++) {
                    int rc = grow + rr2 * 8;
                    int c = rc & (CC - 1);
                    float e0 = __expf((rr2 ? acc[mi][ni][2] : acc[mi][ni][0]) + b0);
                    float e1 = __expf((rr2 ? acc[mi][ni][3] : acc[mi][ni][1]) + b1);
                    colsum[ni * 2] += e0;
                    colsum[ni * 2 + 1] += e1;
                    *(__half2*)&g_Kexp[((size_t)hh * CC + c) * DD + (rB << 4) + jj] =
                        __floats2half2_rn(e0, e1);
                }
            }
        }
#pragma unroll
        for (int j = 0; j < 8; j++) {
            float s = colsum[j];
            s += __shfl_xor_sync(0xffffffffu, s, 4);
            s += __shfl_xor_sync(0xffffffffu, s, 8);
            s += __shfl_xor_sync(0xffffffffu, s, 16);
            if ((lane >> 2) == 0) {
                int e = wn * 32 + (j >> 1) * 8 + (lane & 3) * 2 + (j & 1);
                int hh = e >> 4, jj = e & 15;
                atomicAdd(&g_ksum[hh * DD + (rB << 4) + jj], s);
            }
        }
        return;
    }

    // ---- v path: +bias -> g_Vh fp16 ----
#pragma unroll
    for (int mi = 0; mi < 4; mi++) {
#pragma unroll
        for (int ni = 0; ni < 4; ni++) {
            int grow = m0 + wm * 64 + mi * 16 + (lane >> 2);
            int gcol = n0 + wn * 32 + ni * 8 + (lane & 3) * 2;
            int e = gcol & 127;
            int hh = e >> 4, jj = e & 15;
            float b0 = bias[gcol], b1 = bias[gcol + 1];
#pragma unroll
            for (int rr2 = 0; rr2 < 2; rr2++) {
                int rc = grow + rr2 * 8;
                int r = rc >> 11, c = rc & (CC - 1);
                float a0 = (rr2 ? acc[mi][ni][2] : acc[mi][ni][0]) + b0;
                float a1 = (rr2 ? acc[mi][ni][3] : acc[mi][ni][1]) + b1;
                *(__half2*)&g_Vh[((size_t)hh * CC + c) * DD + (r << 4) + jj] =
                    __floats2half2_rn(a0, a1);
            }
        }
    }
}

// ---------------------------------------------------------------------------
// MEGA kernel: blockIdx.x in [0, 3584):
//   [0,512):     ctx (TN)  — per head 8x8 blocks; signals g_ctx_done
//   [512,2560):  attn (NT) — per head 16x16 blocks
//   [2560,3584): out (NT)  — per head 16x8 blocks; waits for ctx
// ---------------------------------------------------------------------------
__global__ __launch_bounds__(256, 2) void mega_kernel(float* __restrict__ attn_out,
                                                      float* __restrict__ out) {
    extern __shared__ __align__(16) hf smem[];
    const int tid = threadIdx.x, lane = tid & 31, warp = tid >> 5;
    const int wm = warp >> 2, wn = warp & 3;
    const int id = blockIdx.x;

    float acc[4][4][4];
#pragma unroll
    for (int i = 0; i < 4; i++)
#pragma unroll
        for (int j = 0; j < 4; j++)
#pragma unroll
            for (int q = 0; q < 4; q++) acc[i][j][q] = 0.f;

    if (id < 512) {
        // ---- ctx: z in [0,8), by in [0,8), bx in [0,8) ----
        int z = id >> 6, by = (id >> 3) & 7, bx = id & 7;
        int m0 = by * BM, n0 = bx * BN;
        gemm_tn(g_Vh + (size_t)z * CC * DD, g_Kh + (size_t)z * CC * DD,
                DD, DD, CC, m0, n0, smem, tid, lane, wm, wn, acc);
        hf* bh = g_CTh + (size_t)z * DD * DD;
#pragma unroll
        for (int mi = 0; mi < 4; mi++)
#pragma unroll
            for (int ni = 0; ni < 4; ni++) {
                int grow = m0 + wm * 64 + mi * 16 + (lane >> 2);
                int gcol = n0 + wn * 32 + ni * 8 + (lane & 3) * 2;
                *(__half2*)&bh[(size_t)grow * DD + gcol] =
                    __floats2half2_rn(acc[mi][ni][0], acc[mi][ni][1]);
                *(__half2*)&bh[(size_t)(grow + 8) * DD + gcol] =
                    __floats2half2_rn(acc[mi][ni][2], acc[mi][ni][3]);
            }
        __syncthreads();
        if (tid == 0) {
            __threadfence();
            atomicAdd(&g_ctx_done, 1);
        }
    } else if (id < 2560) {
        // ---- attn: z in [0,8), by in [0,16), bx in [0,16) ----
        int id2 = id - 512;
        int z = id2 >> 8, by = (id2 >> 4) & 15, bx = id2 & 15;
        int m0 = by * BM, n0 = bx * BN;
        gemm_nt(g_Qh + (size_t)z * CC * DD, g_Kh + (size_t)z * CC * DD,
                DD, DD, DD, m0, n0, smem, tid, lane, wm, wn, acc);
        float* base = attn_out + (size_t)z * CC * CC;
#pragma unroll
        for (int mi = 0; mi < 4; mi++)
#pragma unroll
            for (int ni = 0; ni < 4; ni++) {
                int grow = m0 + wm * 64 + mi * 16 + (lane >> 2);
                int gcol = n0 + wn * 32 + ni * 8 + (lane & 3) * 2;
                *(float2*)&base[(size_t)grow * CC + gcol] =
                    make_float2(acc[mi][ni][0], acc[mi][ni][1]);
                *(float2*)&base[(size_t)(grow + 8) * CC + gcol] =
                    make_float2(acc[mi][ni][2], acc[mi][ni][3]);
            }
    } else {
        // ---- out: z in [0,8), by in [0,16), bx in [0,8); waits for ctx ----
        if (tid == 0) {
            while (atomicAdd(&g_ctx_done, 0) < 512) { __nanosleep(128); }
        }
        __syncthreads();
        __threadfence();

        int id2 = id - 2560;                 // [0,1024)
        int z = id2 >> 7, by = (id2 >> 3) & 15, bx = id2 & 7;
        int m0 = by * BM, n0 = bx * BN;
        gemm_nt(g_Qh + (size_t)z * CC * DD, g_CTh + (size_t)z * DD * DD,
                DD, DD, DD, m0, n0, smem, tid, lane, wm, wn, acc);
#pragma unroll
        for (int mi = 0; mi < 4; mi++)
#pragma unroll
            for (int ni = 0; ni < 4; ni++) {
                int grow = m0 + wm * 64 + mi * 16 + (lane >> 2);
                int gcol = n0 + wn * 32 + ni * 8 + (lane & 3) * 2;
                int r = gcol >> 4, j = gcol & 15;
#pragma unroll
                for (int rr2 = 0; rr2 < 2; rr2++) {
                    int c = grow + rr2 * 8;
                    float a0 = rr2 ? acc[mi][ni][2] : acc[mi][ni][0];
                    float a1 = rr2 ? acc[mi][ni][3] : acc[mi][ni][1];
                    *(float2*)&out[(((size_t)r * CC + c) << 7) + z * HDIM + j] =
                        make_float2(a0, a1);
                }
            }
    }
}

// ---------------------------------------------------------------------------
// prep: x->fp16 (16384), W->fp16 (48), bias+flag (2), zero ksum (32)
// ---------------------------------------------------------------------------
__global__ __launch_bounds__(256) void prep_kernel(
    const float* __restrict__ x, const float* __restrict__ Wq,
    const float* __restrict__ Wk, const float* __restrict__ Wv,
    const float* __restrict__ bq, const float* __restrict__ bk,
    const float* __restrict__ bv) {
    int b = blockIdx.x, tid = threadIdx.x;
    if (b < 16384) {
        int i = b * 256 + tid;
        float4 v = *(const float4*)(x + (size_t)i * 4);
        *(__half2*)(g_xh + (size_t)i * 4) = __floats2half2_rn(v.x, v.y);
        *(__half2*)(g_xh + (size_t)i * 4 + 2) = __floats2half2_rn(v.z, v.w);
    } else if (b < 16432) {
        int q = (b - 16384) * 256 + tid;
        int w = q >> 12, j = q & 4095;
        const float* W = (w == 0) ? Wq : (w == 1) ? Wk : Wv;
        float4 v = *(const float4*)(W + j * 4);
        hf* dst = g_Wallh + w * EE * EE + j * 4;
        *(__half2*)dst = __floats2half2_rn(v.x, v.y);
        *(__half2*)(dst + 2) = __floats2half2_rn(v.z, v.w);
    } else if (b < 16434) {
        int i = (b - 16432) * 256 + tid;
        if (i < 384)
            g_ball[i] = (i < 128) ? bq[i] : (i < 256) ? bk[i - 128] : bv[i - 256];
        if (b == 16432 && tid == 0) g_ctx_done = 0;
    } else {
        g_ksum[(b - 16434) * 256 + tid] = 0.f;
    }
}

// ---------------------------------------------------------------------------
// ksoft: Kh = Kexp * (1 / ksum[d])  — pure scale pass, 8 halfs per thread
// ---------------------------------------------------------------------------
__global__ __launch_bounds__(256) void ksoft_kernel() {
    size_t i8 = (size_t)blockIdx.x * 256 + threadIdx.x;
    size_t base = i8 * 8;
    int h = (int)(base >> 21);
    int d = (int)(base & (DD - 1));
    float4 raw = *(const float4*)(g_Kexp + base);
    const __half2* h2 = (const __half2*)&raw;
    const float* sums = g_ksum + h * DD + d;
    float4 sv0 = *(const float4*)sums;
    float4 sv1 = *(const float4*)(sums + 4);
    float iv[8] = {__fdividef(1.f, sv0.x), __fdividef(1.f, sv0.y),
                   __fdividef(1.f, sv0.z), __fdividef(1.f, sv0.w),
                   __fdividef(1.f, sv1.x), __fdividef(1.f, sv1.y),
                   __fdividef(1.f, sv1.z), __fdividef(1.f, sv1.w)};
    __half2 outv[4];
#pragma unroll
    for (int j = 0; j < 4; j++) {
        float2 f = __half22float2(h2[j]);
        outv[j] = __floats2half2_rn(f.x * iv[2 * j], f.y * iv[2 * j + 1]);
    }
    *(float4*)(g_Kh + base) = *(float4*)outv;
}

// ---------------------------------------------------------------------------
// launch
// ---------------------------------------------------------------------------
extern "C" void kernel_launch(void* const* d_in, const int* in_sizes, int n_in,
                              void* d_out, int out_size) {
    const float* x  = (const float*)d_in[0];
    const float* Wq = (const float*)d_in[1];
    const float* bq = (const float*)d_in[2];
    const float* Wk = (const float*)d_in[3];
    const float* bk = (const float*)d_in[4];
    const float* Wv = (const float*)d_in[5];
    const float* bv = (const float*)d_in[6];
    float* out = (float*)d_out;

    cudaFuncSetAttribute(proj_kernel, cudaFuncAttributeMaxDynamicSharedMemorySize, SMEM_BYTES);
    cudaFuncSetAttribute(mega_kernel, cudaFuncAttributeMaxDynamicSharedMemorySize, SMEM_BYTES);

    dim3 t256(256);

    // 1) prep (x/W fp16, bias, zero ksum + ctx flag)
    prep_kernel<<<16466, t256>>>(x, Wq, Wk, Wv, bq, bk, bv);

    // 2) fused projection (q softmax on N-block 0; k exp + column sums on N-block 1)
    proj_kernel<<<dim3(3, (RR * CC) / BM, 1), t256, SMEM_BYTES>>>();

    // 3) k softmax apply (pure scale)
    ksoft_kernel<<<HH * CC * DD / 8 / 256, t256>>>();

    // 4) mega: ctx (512) + attn (2048) + out (1024, waits on ctx)
    mega_kernel<<<3584, t256, SMEM_BYTES>>>(out + (size_t)RR * CC * EE, out);
}